// round 9
// baseline (speedup 1.0000x reference)
#include <cuda_runtime.h>
#include <cuda_bf16.h>
#include <cstdint>

// ---------------------------------------------------------------------------
// Problem constants
// ---------------------------------------------------------------------------
#define B_SZ 2
#define S_SZ 2048
#define D_SZ 1024
#define H_SZ 16
#define DK_SZ 64
#define BH_SZ (B_SZ * H_SZ)                   // 32
#define M_SZ (B_SZ * S_SZ)                    // 4096
#define OUT_ELEMS (B_SZ * S_SZ * D_SZ)        // 4,194,304
#define ATTN_ELEMS (134217728)                // B*H*S*S

// ---------------------------------------------------------------------------
// Scratch
// ---------------------------------------------------------------------------
__device__ float g_v[M_SZ * D_SZ];            // v proj fp32 [bh,s,dv]
__device__ float g_ctx[M_SZ * D_SZ];          // [b,s,h*dv]
__device__ float g_o[M_SZ * D_SZ];
__device__ __nv_bfloat16 g_a1[M_SZ * D_SZ];   // GEMM activation splits
__device__ __nv_bfloat16 g_a2[M_SZ * D_SZ];
__device__ __nv_bfloat16 g_wt1[D_SZ * D_SZ];  // weight^T splits [n][k]
__device__ __nv_bfloat16 g_wt2[D_SZ * D_SZ];
__device__ __nv_bfloat16 g_q1[M_SZ * D_SZ];   // q/k proj bf16 hi/lo [bh,s,dk]
__device__ __nv_bfloat16 g_q2[M_SZ * D_SZ];
__device__ __nv_bfloat16 g_k1[M_SZ * D_SZ];
__device__ __nv_bfloat16 g_k2[M_SZ * D_SZ];
__device__ __nv_bfloat16 g_vt1[M_SZ * D_SZ];  // V transposed hi: [bh][d][s]
__device__ float g_sc[ATTN_ELEMS];            // raw masked scores
__device__ float2 g_part[BH_SZ * 16 * 128 * 16];  // per-(row,ktile) (m, l)
__device__ float2 g_stat[BH_SZ * S_SZ];           // per-row (m*, 1/L)

// ---------------------------------------------------------------------------
// Warp MMA helpers (sm_80+ features only)
// ---------------------------------------------------------------------------
__device__ __forceinline__ uint32_t smem_u32(const void* p) {
    uint32_t a;
    asm("{ .reg .u64 t; cvta.to.shared.u64 t, %1; cvt.u32.u64 %0, t; }"
        : "=r"(a) : "l"(p));
    return a;
}

__device__ __forceinline__ void mma_bf16(float* c, const uint32_t* a,
                                         const uint32_t* b) {
    asm volatile(
        "mma.sync.aligned.m16n8k16.row.col.f32.bf16.bf16.f32 "
        "{%0,%1,%2,%3}, {%4,%5,%6,%7}, {%8,%9}, {%0,%1,%2,%3};"
        : "+f"(c[0]), "+f"(c[1]), "+f"(c[2]), "+f"(c[3])
        : "r"(a[0]), "r"(a[1]), "r"(a[2]), "r"(a[3]),
          "r"(b[0]), "r"(b[1]));
}

__device__ __forceinline__ void ldsm_x4(uint32_t* r, uint32_t addr) {
    asm volatile("ldmatrix.sync.aligned.m8n8.x4.shared.b16 {%0,%1,%2,%3}, [%4];"
                 : "=r"(r[0]), "=r"(r[1]), "=r"(r[2]), "=r"(r[3]) : "r"(addr));
}
__device__ __forceinline__ void ldsm_x2(uint32_t* r, uint32_t addr) {
    asm volatile("ldmatrix.sync.aligned.m8n8.x2.shared.b16 {%0,%1}, [%2];"
                 : "=r"(r[0]), "=r"(r[1]) : "r"(addr));
}

__device__ __forceinline__ uint32_t bf2pack(__nv_bfloat16 a, __nv_bfloat16 b) {
    __nv_bfloat162 v = {a, b};
    return *reinterpret_cast<uint32_t*>(&v);
}

// Tile stride: 72 bf16 per row (144 B, conflict-staggered, 16B aligned)
#define TSTR 72

// ---------------------------------------------------------------------------
// fp32 -> bf16 hi/lo split (elementwise)
// ---------------------------------------------------------------------------
__global__ void __launch_bounds__(256) split_kernel(
    const float* __restrict__ in, __nv_bfloat16* __restrict__ hi,
    __nv_bfloat16* __restrict__ lo)
{
    const int i = blockIdx.x * 256 + threadIdx.x;
    const float4 v = reinterpret_cast<const float4*>(in)[i];
    __nv_bfloat16 h0 = __float2bfloat16(v.x);
    __nv_bfloat16 h1 = __float2bfloat16(v.y);
    __nv_bfloat16 h2 = __float2bfloat16(v.z);
    __nv_bfloat16 h3 = __float2bfloat16(v.w);
    __nv_bfloat162 H0 = {h0, h1}, H1 = {h2, h3};
    __nv_bfloat162 L0 = {__float2bfloat16(v.x - __bfloat162float(h0)),
                         __float2bfloat16(v.y - __bfloat162float(h1))};
    __nv_bfloat162 L1 = {__float2bfloat16(v.z - __bfloat162float(h2)),
                         __float2bfloat16(v.w - __bfloat162float(h3))};
    reinterpret_cast<__nv_bfloat162*>(hi)[i * 2]     = H0;
    reinterpret_cast<__nv_bfloat162*>(hi)[i * 2 + 1] = H1;
    reinterpret_cast<__nv_bfloat162*>(lo)[i * 2]     = L0;
    reinterpret_cast<__nv_bfloat162*>(lo)[i * 2 + 1] = L1;
}

// ---------------------------------------------------------------------------
// Weight transpose + split: W [k][n] fp32 -> Wt hi/lo [n][k] bf16
// ---------------------------------------------------------------------------
__global__ void __launch_bounds__(256) wt_kernel(
    const float* __restrict__ W, __nv_bfloat16* __restrict__ wt1,
    __nv_bfloat16* __restrict__ wt2)
{
    __shared__ float vs[64][65];
    const int k0 = blockIdx.y * 64;
    const int n0 = blockIdx.x * 64;
    const int t  = threadIdx.x;

    for (int i = t; i < 64 * 16; i += 256) {
        const int r = i >> 4, c = i & 15;
        const float4 v = *reinterpret_cast<const float4*>(
            W + (size_t)(k0 + r) * D_SZ + n0 + c * 4);
        vs[r][c * 4 + 0] = v.x; vs[r][c * 4 + 1] = v.y;
        vs[r][c * 4 + 2] = v.z; vs[r][c * 4 + 3] = v.w;
    }
    __syncthreads();

    for (int i = t; i < 64 * 64; i += 256) {
        const int n = i >> 6, k = i & 63;
        const float x = vs[k][n];
        const __nv_bfloat16 h = __float2bfloat16(x);
        const __nv_bfloat16 l = __float2bfloat16(x - __bfloat162float(h));
        const size_t o = (size_t)(n0 + n) * D_SZ + k0 + k;
        wt1[o] = h;
        wt2[o] = l;
    }
}

// ---------------------------------------------------------------------------
// bf16x3 warp-MMA GEMM (verified round 8)
// ---------------------------------------------------------------------------
#define GM_A1 0
#define GM_A2 (128 * TSTR)
#define GM_W1 (2 * 128 * TSTR)
#define GM_W2 (3 * 128 * TSTR)
#define GEMM_SMEM (4 * 128 * TSTR * 2)        // 73728 B

__global__ void __launch_bounds__(256) gemm_mma(
    const __nv_bfloat16* __restrict__ a1, const __nv_bfloat16* __restrict__ a2,
    const __nv_bfloat16* __restrict__ wt1, const __nv_bfloat16* __restrict__ wt2,
    const float* __restrict__ bias,
    float* __restrict__ outf, __nv_bfloat16* __restrict__ outh,
    __nv_bfloat16* __restrict__ outl, int mode)
{
    extern __shared__ __align__(16) __nv_bfloat16 sm[];
    const int t = threadIdx.x;
    const int lane = t & 31, wid = t >> 5;
    const int wq = wid & 3, wk = wid >> 2;
    const int n0 = blockIdx.x * 128;
    const int m0 = blockIdx.y * 128;
    const uint32_t sb = smem_u32(sm);

    float acc[2][8][4] = {};

    for (int ck = 0; ck < 16; ck++) {
        const int j0 = ck * 64;
        __syncthreads();
        for (int i = t; i < 1024; i += 256) {
            const int r = i >> 3, c = i & 7;
            const int off = r * TSTR + c * 8;
            const size_t ga = (size_t)(m0 + r) * D_SZ + j0 + c * 8;
            const size_t gw = (size_t)(n0 + r) * D_SZ + j0 + c * 8;
            *reinterpret_cast<uint4*>(
                reinterpret_cast<char*>(sm) + (size_t)(GM_A1 + off) * 2) =
                *reinterpret_cast<const uint4*>(a1 + ga);
            *reinterpret_cast<uint4*>(
                reinterpret_cast<char*>(sm) + (size_t)(GM_A2 + off) * 2) =
                *reinterpret_cast<const uint4*>(a2 + ga);
            *reinterpret_cast<uint4*>(
                reinterpret_cast<char*>(sm) + (size_t)(GM_W1 + off) * 2) =
                *reinterpret_cast<const uint4*>(wt1 + gw);
            *reinterpret_cast<uint4*>(
                reinterpret_cast<char*>(sm) + (size_t)(GM_W2 + off) * 2) =
                *reinterpret_cast<const uint4*>(wt2 + gw);
        }
        __syncthreads();

#pragma unroll
        for (int ks = 0; ks < 4; ks++) {
            const int kc = ks * 16;
            uint32_t ah[2][4], al[2][4];
#pragma unroll
            for (int mi = 0; mi < 2; mi++) {
                const int row = wq * 32 + mi * 16 + (lane & 15);
                const int col = kc + ((lane >> 4) << 3);
                ldsm_x4(ah[mi], sb + (uint32_t)(GM_A1 + row * TSTR + col) * 2);
                ldsm_x4(al[mi], sb + (uint32_t)(GM_A2 + row * TSTR + col) * 2);
            }
#pragma unroll
            for (int ni = 0; ni < 8; ni++) {
                uint32_t bh_[2], bl_[2];
                const int row = wk * 64 + ni * 8 + (lane & 7);
                const int col = kc + (((lane >> 3) & 1) << 3);
                ldsm_x2(bh_, sb + (uint32_t)(GM_W1 + row * TSTR + col) * 2);
                ldsm_x2(bl_, sb + (uint32_t)(GM_W2 + row * TSTR + col) * 2);
#pragma unroll
                for (int mi = 0; mi < 2; mi++) {
                    mma_bf16(acc[mi][ni], ah[mi], bh_);
                    mma_bf16(acc[mi][ni], ah[mi], bl_);
                    mma_bf16(acc[mi][ni], al[mi], bh_);
                }
            }
        }
    }

    const int g  = lane >> 2;
    const int tg = lane & 3;
#pragma unroll
    for (int mi = 0; mi < 2; mi++) {
#pragma unroll
        for (int ni = 0; ni < 8; ni++) {
            const int col = n0 + wk * 64 + ni * 8 + tg * 2;
            const float2 bb = *reinterpret_cast<const float2*>(bias + col);
            const int m = m0 + wq * 32 + mi * 16 + g;
            float2 r0 = make_float2(acc[mi][ni][0] + bb.x, acc[mi][ni][1] + bb.y);
            float2 r1 = make_float2(acc[mi][ni][2] + bb.x, acc[mi][ni][3] + bb.y);
            if (mode == 0) {
                *reinterpret_cast<float2*>(outf + (size_t)m * D_SZ + col) = r0;
                *reinterpret_cast<float2*>(outf + (size_t)(m + 8) * D_SZ + col) = r1;
            } else {
                const int h  = col >> 6;
                const int dk = col & 63;
                const int b0 = m >> 11, s0 = m & 2047;
                const int b1 = (m + 8) >> 11, s1 = (m + 8) & 2047;
                const size_t o0 = (((size_t)(b0 * H_SZ + h) * S_SZ + s0) * DK_SZ) + dk;
                const size_t o1 = (((size_t)(b1 * H_SZ + h) * S_SZ + s1) * DK_SZ) + dk;
                if (mode == 2) {
                    *reinterpret_cast<float2*>(outf + o0) = r0;
                    *reinterpret_cast<float2*>(outf + o1) = r1;
                } else {
                    const __nv_bfloat16 h00 = __float2bfloat16(r0.x);
                    const __nv_bfloat16 h01 = __float2bfloat16(r0.y);
                    const __nv_bfloat16 h10 = __float2bfloat16(r1.x);
                    const __nv_bfloat16 h11 = __float2bfloat16(r1.y);
                    *reinterpret_cast<uint32_t*>(outh + o0) = bf2pack(h00, h01);
                    *reinterpret_cast<uint32_t*>(outh + o1) = bf2pack(h10, h11);
                    *reinterpret_cast<uint32_t*>(outl + o0) = bf2pack(
                        __float2bfloat16(r0.x - __bfloat162float(h00)),
                        __float2bfloat16(r0.y - __bfloat162float(h01)));
                    *reinterpret_cast<uint32_t*>(outl + o1) = bf2pack(
                        __float2bfloat16(r1.x - __bfloat162float(h10)),
                        __float2bfloat16(r1.y - __bfloat162float(h11)));
                }
            }
        }
    }
}

// ---------------------------------------------------------------------------
// V transpose + split (hi only): g_v [bh][s][64] -> g_vt1 [bh][64][2048]
// ---------------------------------------------------------------------------
__global__ void __launch_bounds__(128) vt_kernel()
{
    __shared__ float vs[128][65];
    const int jt = blockIdx.x;
    const int bh = blockIdx.y;
    const int t  = threadIdx.x;
    const int j0 = jt * 128;

    const float4* src = reinterpret_cast<const float4*>(
        g_v + ((size_t)bh * S_SZ + j0) * DK_SZ);
    for (int i = t; i < 128 * 16; i += 128) {
        const int r = i >> 4, c = i & 15;
        const float4 v = src[i];
        vs[r][c * 4 + 0] = v.x; vs[r][c * 4 + 1] = v.y;
        vs[r][c * 4 + 2] = v.z; vs[r][c * 4 + 3] = v.w;
    }
    __syncthreads();

    for (int i = t; i < 64 * 128; i += 128) {
        const int j = i & 127;
        const int d = i >> 7;
        g_vt1[((size_t)bh * 64 + d) * S_SZ + j0 + j] = __float2bfloat16(vs[j][d]);
    }
}

// ---------------------------------------------------------------------------
// Score kernel: raw masked scaled scores -> g_sc, partial (m, sumexp) -> g_part
// ---------------------------------------------------------------------------
#define SQ_H 0
#define SQ_L (128 * TSTR)
#define SK_H (2 * 128 * TSTR)
#define SK_L (3 * 128 * TSTR)
#define SCORE_SMEM (4 * 128 * TSTR * 2)       // 73728 B

__global__ void __launch_bounds__(256) score_kernel(
    const int* __restrict__ mask, float* __restrict__ sbuf)
{
    extern __shared__ __align__(16) __nv_bfloat16 sm[];
    const int t = threadIdx.x;
    const int lane = t & 31, wid = t >> 5;
    const int wq = wid & 3, wk = wid >> 2;
    const int q0 = blockIdx.x * 128, k0 = blockIdx.y * 128;
    const int bh = blockIdx.z, b = bh >> 4;

    {
        const uint4* q1 = reinterpret_cast<const uint4*>(
            g_q1 + ((size_t)bh * S_SZ + q0) * DK_SZ);
        const uint4* q2 = reinterpret_cast<const uint4*>(
            g_q2 + ((size_t)bh * S_SZ + q0) * DK_SZ);
        const uint4* k1 = reinterpret_cast<const uint4*>(
            g_k1 + ((size_t)bh * S_SZ + k0) * DK_SZ);
        const uint4* k2 = reinterpret_cast<const uint4*>(
            g_k2 + ((size_t)bh * S_SZ + k0) * DK_SZ);
        for (int i = t; i < 1024; i += 256) {
            const int r = i >> 3, c = i & 7;
            const int off = r * TSTR + c * 8;
            *reinterpret_cast<uint4*>(
                reinterpret_cast<char*>(sm) + (size_t)(SQ_H + off) * 2) = q1[i];
            *reinterpret_cast<uint4*>(
                reinterpret_cast<char*>(sm) + (size_t)(SQ_L + off) * 2) = q2[i];
            *reinterpret_cast<uint4*>(
                reinterpret_cast<char*>(sm) + (size_t)(SK_H + off) * 2) = k1[i];
            *reinterpret_cast<uint4*>(
                reinterpret_cast<char*>(sm) + (size_t)(SK_L + off) * 2) = k2[i];
        }
    }
    __syncthreads();

    const uint32_t sb = smem_u32(sm);
    float acc[2][8][4] = {};

#pragma unroll
    for (int ks = 0; ks < 4; ks++) {
        const int kc = ks * 16;
        uint32_t ah[2][4], al[2][4];
#pragma unroll
        for (int mi = 0; mi < 2; mi++) {
            const int row = wq * 32 + mi * 16 + (lane & 15);
            const int col = kc + ((lane >> 4) << 3);
            ldsm_x4(ah[mi], sb + (uint32_t)(SQ_H + row * TSTR + col) * 2);
            ldsm_x4(al[mi], sb + (uint32_t)(SQ_L + row * TSTR + col) * 2);
        }
#pragma unroll
        for (int ni = 0; ni < 8; ni++) {
            uint32_t bh_[2], bl_[2];
            const int row = wk * 64 + ni * 8 + (lane & 7);
            const int col = kc + (((lane >> 3) & 1) << 3);
            ldsm_x2(bh_, sb + (uint32_t)(SK_H + row * TSTR + col) * 2);
            ldsm_x2(bl_, sb + (uint32_t)(SK_L + row * TSTR + col) * 2);
#pragma unroll
            for (int mi = 0; mi < 2; mi++) {
                mma_bf16(acc[mi][ni], ah[mi], bh_);
                mma_bf16(acc[mi][ni], ah[mi], bl_);
                mma_bf16(acc[mi][ni], al[mi], bh_);
            }
        }
    }
    __syncthreads();   // smem reads done; sm will be reused for stats

    float2* statsm = reinterpret_cast<float2*>(sm);   // [2 wk][128 rows]
    const int g  = lane >> 2;
    const int tg = lane & 3;
#pragma unroll
    for (int mi = 0; mi < 2; mi++) {
        float m0 = -3e38f, m1 = -3e38f;
        const int q = q0 + wq * 32 + mi * 16 + g;
#pragma unroll
        for (int ni = 0; ni < 8; ni++) {
            const int k = k0 + wk * 64 + ni * 8 + tg * 2;
            const int2 ma = *reinterpret_cast<const int2*>(
                mask + ((size_t)b * S_SZ + q) * S_SZ + k);
            const int2 mb = *reinterpret_cast<const int2*>(
                mask + ((size_t)b * S_SZ + q + 8) * S_SZ + k);
            float a0 = ma.x ? -1e9f : acc[mi][ni][0] * 0.125f;
            float a1 = ma.y ? -1e9f : acc[mi][ni][1] * 0.125f;
            float a2 = mb.x ? -1e9f : acc[mi][ni][2] * 0.125f;
            float a3 = mb.y ? -1e9f : acc[mi][ni][3] * 0.125f;
            acc[mi][ni][0] = a0; acc[mi][ni][1] = a1;
            acc[mi][ni][2] = a2; acc[mi][ni][3] = a3;
            *reinterpret_cast<float2*>(
                sbuf + ((size_t)bh * S_SZ + q) * S_SZ + k) = make_float2(a0, a1);
            *reinterpret_cast<float2*>(
                sbuf + ((size_t)bh * S_SZ + q + 8) * S_SZ + k) = make_float2(a2, a3);
            m0 = fmaxf(m0, fmaxf(a0, a1));
            m1 = fmaxf(m1, fmaxf(a2, a3));
        }
#pragma unroll
        for (int o = 1; o <= 2; o <<= 1) {
            m0 = fmaxf(m0, __shfl_xor_sync(0xffffffffu, m0, o));
            m1 = fmaxf(m1, __shfl_xor_sync(0xffffffffu, m1, o));
        }
        float l0 = 0.f, l1 = 0.f;
#pragma unroll
        for (int ni = 0; ni < 8; ni++) {
            l0 += __expf(acc[mi][ni][0] - m0) + __expf(acc[mi][ni][1] - m0);
            l1 += __expf(acc[mi][ni][2] - m1) + __expf(acc[mi][ni][3] - m1);
        }
#pragma unroll
        for (int o = 1; o <= 2; o <<= 1) {
            l0 += __shfl_xor_sync(0xffffffffu, l0, o);
            l1 += __shfl_xor_sync(0xffffffffu, l1, o);
        }
        if (tg == 0) {
            statsm[wk * 128 + wq * 32 + mi * 16 + g]     = make_float2(m0, l0);
            statsm[wk * 128 + wq * 32 + mi * 16 + g + 8] = make_float2(m1, l1);
        }
    }
    __syncthreads();

    if (t < 128) {
        const float2 s0 = statsm[t];
        const float2 s1 = statsm[128 + t];
        const float m = fmaxf(s0.x, s1.x);
        const float l = s0.y * __expf(s0.x - m) + s1.y * __expf(s1.x - m);
        g_part[(((size_t)bh * 16 + blockIdx.x) * 128 + t) * 16 + blockIdx.y] =
            make_float2(m, l);
    }
}

// ---------------------------------------------------------------------------
// Row-stat reduce: 16 (m,l) partials per row -> (m*, 1/L)
// ---------------------------------------------------------------------------
__global__ void __launch_bounds__(256) reduce_kernel()
{
    const int row = blockIdx.x * 8 + (threadIdx.x >> 5);
    const int lane = threadIdx.x & 31;
    float m = -3e38f, l = 0.f;
    if (lane < 16) {
        const float2 p = g_part[(size_t)row * 16 + lane];
        m = p.x; l = p.y;
    }
#pragma unroll
    for (int o = 8; o; o >>= 1) {
        const float m2 = __shfl_xor_sync(0xffffffffu, m, o);
        const float l2 = __shfl_xor_sync(0xffffffffu, l, o);
        const float mn = fmaxf(m, m2);
        l = l * __expf(m - mn) + l2 * __expf(m2 - mn);
        m = mn;
    }
    if (lane == 0) g_stat[row] = make_float2(m, 1.f / l);
}

// ---------------------------------------------------------------------------
// Context kernel: reads raw scores, applies softmax on the fly, writes probs
// to attn output, PV via 2-term (P hi/lo x V hi).
// ---------------------------------------------------------------------------
#define CP_H 0
#define CP_L (128 * TSTR)
#define CV_H (2 * 128 * TSTR)
#define CTX_SMEM ((2 * 128 * TSTR + 64 * TSTR) * 2)   // 46080 B

__global__ void __launch_bounds__(256) ctx_kernel(
    const float* __restrict__ scores, float* __restrict__ attn_out,
    int write_attn)
{
    extern __shared__ __align__(16) __nv_bfloat16 sm[];
    const int t = threadIdx.x;
    const int lane = t & 31, wid = t >> 5;
    const int q0 = blockIdx.x * 128;
    const int bh = blockIdx.y, b = bh >> 4, h = bh & 15;
    const uint32_t sb = smem_u32(sm);

    const float* srow = scores + ((size_t)bh * S_SZ + q0) * S_SZ;
    float* arow = attn_out + ((size_t)bh * S_SZ + q0) * S_SZ;
    const __nv_bfloat16* vt1 = g_vt1 + (size_t)bh * 64 * S_SZ;
    const float2* stat = g_stat + (size_t)bh * S_SZ + q0;

    float acc[8][4] = {};

    for (int ch = 0; ch < 32; ch++) {
        const int j0 = ch * 64;
        __syncthreads();
        for (int i = t; i < 2048; i += 256) {
            const int r = i >> 4, c = i & 15;
            const float2 st = stat[r];
            const float4 v = *reinterpret_cast<const float4*>(
                srow + (size_t)r * S_SZ + j0 + c * 4);
            float4 p;
            p.x = __expf(v.x - st.x) * st.y;
            p.y = __expf(v.y - st.x) * st.y;
            p.z = __expf(v.z - st.x) * st.y;
            p.w = __expf(v.w - st.x) * st.y;
            if (write_attn)
                *reinterpret_cast<float4*>(
                    arow + (size_t)r * S_SZ + j0 + c * 4) = p;
            const __nv_bfloat16 h0 = __float2bfloat16(p.x);
            const __nv_bfloat16 h1 = __float2bfloat16(p.y);
            const __nv_bfloat16 h2 = __float2bfloat16(p.z);
            const __nv_bfloat16 h3 = __float2bfloat16(p.w);
            const uint2 hp = make_uint2(bf2pack(h0, h1), bf2pack(h2, h3));
            const uint2 lp = make_uint2(
                bf2pack(__float2bfloat16(p.x - __bfloat162float(h0)),
                        __float2bfloat16(p.y - __bfloat162float(h1))),
                bf2pack(__float2bfloat16(p.z - __bfloat162float(h2)),
                        __float2bfloat16(p.w - __bfloat162float(h3))));
            const int off = r * TSTR + c * 4;
            *reinterpret_cast<uint2*>(
                reinterpret_cast<char*>(sm) + (size_t)(CP_H + off) * 2) = hp;
            *reinterpret_cast<uint2*>(
                reinterpret_cast<char*>(sm) + (size_t)(CP_L + off) * 2) = lp;
        }
        for (int i = t; i < 512; i += 256) {
            const int r = i >> 3, c = i & 7;
            const int off = r * TSTR + c * 8;
            *reinterpret_cast<uint4*>(
                reinterpret_cast<char*>(sm) + (size_t)(CV_H + off) * 2) =
                *reinterpret_cast<const uint4*>(vt1 + (size_t)r * S_SZ + j0 + c * 8);
        }
        __syncthreads();

#pragma unroll
        for (int ks = 0; ks < 4; ks++) {
            const int kc = ks * 16;
            uint32_t ah[4], al[4];
            {
                const int row = wid * 16 + (lane & 15);
                const int col = kc + ((lane >> 4) << 3);
                ldsm_x4(ah, sb + (uint32_t)(CP_H + row * TSTR + col) * 2);
                ldsm_x4(al, sb + (uint32_t)(CP_L + row * TSTR + col) * 2);
            }
#pragma unroll
            for (int ni = 0; ni < 8; ni++) {
                uint32_t bh_[2];
                const int row = ni * 8 + (lane & 7);
                const int col = kc + (((lane >> 3) & 1) << 3);
                ldsm_x2(bh_, sb + (uint32_t)(CV_H + row * TSTR + col) * 2);
                mma_bf16(acc[ni], ah, bh_);
                mma_bf16(acc[ni], al, bh_);
            }
        }
    }

    const int g  = lane >> 2;
    const int tg = lane & 3;
#pragma unroll
    for (int ni = 0; ni < 8; ni++) {
        const int q = q0 + wid * 16 + g;
        const int d = ni * 8 + tg * 2;
        *reinterpret_cast<float2*>(
            g_ctx + ((size_t)(b * S_SZ + q)) * D_SZ + h * DK_SZ + d) =
            make_float2(acc[ni][0], acc[ni][1]);
        *reinterpret_cast<float2*>(
            g_ctx + ((size_t)(b * S_SZ + q + 8)) * D_SZ + h * DK_SZ + d) =
            make_float2(acc[ni][2], acc[ni][3]);
    }
}

// ---------------------------------------------------------------------------
// Residual + LayerNorm
// ---------------------------------------------------------------------------
__global__ void __launch_bounds__(256) ln_kernel(
    const float* __restrict__ resid, const float* __restrict__ gamma,
    const float* __restrict__ beta, float* __restrict__ out)
{
    __shared__ float rs[8], rq[8];
    const int row = blockIdx.x;
    const int t = threadIdx.x;

    const float4 a = reinterpret_cast<const float4*>(g_o + (size_t)row * D_SZ)[t];
    const float4 r = reinterpret_cast<const float4*>(resid + (size_t)row * D_SZ)[t];
    const float4 v = make_float4(a.x + r.x, a.y + r.y, a.z + r.z, a.w + r.w);

    float s  = v.x + v.y + v.z + v.w;
    float sq = v.x * v.x + v.y * v.y + v.z * v.z + v.w * v.w;
#pragma unroll
    for (int o = 16; o; o >>= 1) {
        s  += __shfl_xor_sync(0xffffffffu, s, o);
        sq += __shfl_xor_sync(0xffffffffu, sq, o);
    }
    if ((t & 31) == 0) { rs[t >> 5] = s; rq[t >> 5] = sq; }
    __syncthreads();
    float S = 0.f, SQ = 0.f;
#pragma unroll
    for (int i = 0; i < 8; i++) { S += rs[i]; SQ += rq[i]; }
    const float mu  = S * (1.f / D_SZ);
    const float var = SQ * (1.f / D_SZ) - mu * mu;
    const float rstd = rsqrtf(var + 1e-5f);

    const float4 g  = reinterpret_cast<const float4*>(gamma)[t];
    const float4 be = reinterpret_cast<const float4*>(beta)[t];
    reinterpret_cast<float4*>(out + (size_t)row * D_SZ)[t] =
        make_float4((v.x - mu) * rstd * g.x + be.x,
                    (v.y - mu) * rstd * g.y + be.y,
                    (v.z - mu) * rstd * g.z + be.z,
                    (v.w - mu) * rstd * g.w + be.w);
}

// ---------------------------------------------------------------------------
// kernel_launch
// ---------------------------------------------------------------------------
extern "C" void kernel_launch(void* const* d_in, const int* in_sizes, int n_in,
                              void* d_out, int out_size)
{
    const float* Q  = (const float*)d_in[0];
    const float* K  = (const float*)d_in[1];
    const float* V  = (const float*)d_in[2];
    const int*   mask = (const int*)d_in[3];
    const float* Wq = (const float*)d_in[4];
    const float* bq = (const float*)d_in[5];
    const float* Wk = (const float*)d_in[6];
    const float* bk = (const float*)d_in[7];
    const float* Wv = (const float*)d_in[8];
    const float* bv = (const float*)d_in[9];
    const float* Wo = (const float*)d_in[10];
    const float* bo = (const float*)d_in[11];
    const float* gamma = (const float*)d_in[12];
    const float* beta  = (const float*)d_in[13];

    float *vp, *ctx, *op, *scp;
    __nv_bfloat16 *a1, *a2, *w1, *w2, *q1, *q2, *k1, *k2;
    cudaGetSymbolAddress((void**)&vp,  g_v);
    cudaGetSymbolAddress((void**)&ctx, g_ctx);
    cudaGetSymbolAddress((void**)&op,  g_o);
    cudaGetSymbolAddress((void**)&scp, g_sc);
    cudaGetSymbolAddress((void**)&a1,  g_a1);
    cudaGetSymbolAddress((void**)&a2,  g_a2);
    cudaGetSymbolAddress((void**)&w1,  g_wt1);
    cudaGetSymbolAddress((void**)&w2,  g_wt2);
    cudaGetSymbolAddress((void**)&q1,  g_q1);
    cudaGetSymbolAddress((void**)&q2,  g_q2);
    cudaGetSymbolAddress((void**)&k1,  g_k1);
    cudaGetSymbolAddress((void**)&k2,  g_k2);

    float* outp = (float*)d_out;
    int write_attn = 0;
    float* attn_ptr = outp;
    if ((long long)out_size >= (long long)OUT_ELEMS + (long long)ATTN_ELEMS) {
        write_attn = 1;
        attn_ptr = outp + OUT_ELEMS;
    }

    cudaFuncSetAttribute(score_kernel,
        cudaFuncAttributeMaxDynamicSharedMemorySize, SCORE_SMEM);
    cudaFuncSetAttribute(ctx_kernel,
        cudaFuncAttributeMaxDynamicSharedMemorySize, CTX_SMEM);
    cudaFuncSetAttribute(gemm_mma,
        cudaFuncAttributeMaxDynamicSharedMemorySize, GEMM_SMEM);

    const dim3 wt_grid(D_SZ / 64, D_SZ / 64);
    const dim3 gm_grid(D_SZ / 128, M_SZ / 128);
    const int  split_blocks = (M_SZ * D_SZ / 4) / 256;

    // q projection (bf16 hi/lo output, split fused)
    split_kernel<<<split_blocks, 256>>>(Q, a1, a2);
    wt_kernel<<<wt_grid, 256>>>(Wq, w1, w2);
    gemm_mma<<<gm_grid, 256, GEMM_SMEM>>>(a1, a2, w1, w2, bq, nullptr, q1, q2, 1);

    // k projection
    split_kernel<<<split_blocks, 256>>>(K, a1, a2);
    wt_kernel<<<wt_grid, 256>>>(Wk, w1, w2);
    gemm_mma<<<gm_grid, 256, GEMM_SMEM>>>(a1, a2, w1, w2, bk, nullptr, k1, k2, 1);

    // v projection -> fp32 [bh,s,64], then transpose (hi only)
    split_kernel<<<split_blocks, 256>>>(V, a1, a2);
    wt_kernel<<<wt_grid, 256>>>(Wv, w1, w2);
    gemm_mma<<<gm_grid, 256, GEMM_SMEM>>>(a1, a2, w1, w2, bv, vp, nullptr, nullptr, 2);
    vt_kernel<<<dim3(16, BH_SZ), 128>>>();

    // scores + partial softmax stats
    score_kernel<<<dim3(S_SZ / 128, S_SZ / 128, BH_SZ), 256, SCORE_SMEM>>>(mask, scp);
    reduce_kernel<<<(BH_SZ * S_SZ) / 8, 256>>>();

    // context (softmax applied on the fly; writes attn probs)
    ctx_kernel<<<dim3(S_SZ / 128, BH_SZ), 256, CTX_SMEM>>>(scp, attn_ptr, write_attn);

    // output projection + LN
    split_kernel<<<split_blocks, 256>>>(ctx, a1, a2);
    wt_kernel<<<wt_grid, 256>>>(Wo, w1, w2);
    gemm_mma<<<gm_grid, 256, GEMM_SMEM>>>(a1, a2, w1, w2, bo, op, nullptr, nullptr, 0);

    ln_kernel<<<M_SZ, 256>>>(Q, gamma, beta, outp);
}

// round 10
// speedup vs baseline: 1.0548x; 1.0548x over previous
#include <cuda_runtime.h>
#include <cuda_bf16.h>
#include <cstdint>

// ---------------------------------------------------------------------------
// Problem constants
// ---------------------------------------------------------------------------
#define B_SZ 2
#define S_SZ 2048
#define D_SZ 1024
#define H_SZ 16
#define DK_SZ 64
#define BH_SZ (B_SZ * H_SZ)                   // 32
#define M_SZ (B_SZ * S_SZ)                    // 4096
#define OUT_ELEMS (B_SZ * S_SZ * D_SZ)        // 4,194,304
#define ATTN_ELEMS (134217728)                // B*H*S*S

// ---------------------------------------------------------------------------
// Scratch
// ---------------------------------------------------------------------------
__device__ float g_v[M_SZ * D_SZ];            // v proj fp32 [bh,s,dv]
__device__ float g_ctx[M_SZ * D_SZ];          // [b,s,h*dv]
__device__ float g_o[M_SZ * D_SZ];
__device__ __nv_bfloat16 g_a1[M_SZ * D_SZ];   // GEMM activation splits
__device__ __nv_bfloat16 g_a2[M_SZ * D_SZ];
__device__ __nv_bfloat16 g_wt1[D_SZ * D_SZ];  // weight^T splits [n][k]
__device__ __nv_bfloat16 g_wt2[D_SZ * D_SZ];
__device__ __nv_bfloat16 g_q1[M_SZ * D_SZ];   // q/k proj bf16 hi/lo [bh,s,dk]
__device__ __nv_bfloat16 g_q2[M_SZ * D_SZ];
__device__ __nv_bfloat16 g_k1[M_SZ * D_SZ];
__device__ __nv_bfloat16 g_k2[M_SZ * D_SZ];
__device__ __nv_bfloat16 g_vt1[M_SZ * D_SZ];  // V transposed hi: [bh][d][s]
__device__ float g_sc[ATTN_ELEMS];            // score/prob scratch (if !write_attn)

// ---------------------------------------------------------------------------
// Warp MMA helpers (sm_80+ features only)
// ---------------------------------------------------------------------------
__device__ __forceinline__ uint32_t smem_u32(const void* p) {
    uint32_t a;
    asm("{ .reg .u64 t; cvta.to.shared.u64 t, %1; cvt.u32.u64 %0, t; }"
        : "=r"(a) : "l"(p));
    return a;
}

__device__ __forceinline__ void mma_bf16(float* c, const uint32_t* a,
                                         const uint32_t* b) {
    asm volatile(
        "mma.sync.aligned.m16n8k16.row.col.f32.bf16.bf16.f32 "
        "{%0,%1,%2,%3}, {%4,%5,%6,%7}, {%8,%9}, {%0,%1,%2,%3};"
        : "+f"(c[0]), "+f"(c[1]), "+f"(c[2]), "+f"(c[3])
        : "r"(a[0]), "r"(a[1]), "r"(a[2]), "r"(a[3]),
          "r"(b[0]), "r"(b[1]));
}

__device__ __forceinline__ void ldsm_x4(uint32_t* r, uint32_t addr) {
    asm volatile("ldmatrix.sync.aligned.m8n8.x4.shared.b16 {%0,%1,%2,%3}, [%4];"
                 : "=r"(r[0]), "=r"(r[1]), "=r"(r[2]), "=r"(r[3]) : "r"(addr));
}
__device__ __forceinline__ void ldsm_x2(uint32_t* r, uint32_t addr) {
    asm volatile("ldmatrix.sync.aligned.m8n8.x2.shared.b16 {%0,%1}, [%2];"
                 : "=r"(r[0]), "=r"(r[1]) : "r"(addr));
}

__device__ __forceinline__ void cp16(uint32_t dst, const void* src) {
    asm volatile("cp.async.cg.shared.global [%0], [%1], 16;"
                 :: "r"(dst), "l"(src) : "memory");
}
#define CP_COMMIT() asm volatile("cp.async.commit_group;" ::: "memory")
#define CP_WAIT0()  asm volatile("cp.async.wait_group 0;" ::: "memory")

__device__ __forceinline__ uint32_t bf2pack(__nv_bfloat16 a, __nv_bfloat16 b) {
    __nv_bfloat162 v = {a, b};
    return *reinterpret_cast<uint32_t*>(&v);
}

// Tile stride: 72 bf16 per row (144 B, conflict-staggered, 16B aligned)
#define TSTR 72

// ---------------------------------------------------------------------------
// fp32 -> bf16 hi/lo split (elementwise)
// ---------------------------------------------------------------------------
__global__ void __launch_bounds__(256) split_kernel(
    const float* __restrict__ in, __nv_bfloat16* __restrict__ hi,
    __nv_bfloat16* __restrict__ lo)
{
    const int i = blockIdx.x * 256 + threadIdx.x;
    const float4 v = reinterpret_cast<const float4*>(in)[i];
    __nv_bfloat16 h0 = __float2bfloat16(v.x);
    __nv_bfloat16 h1 = __float2bfloat16(v.y);
    __nv_bfloat16 h2 = __float2bfloat16(v.z);
    __nv_bfloat16 h3 = __float2bfloat16(v.w);
    __nv_bfloat162 H0 = {h0, h1}, H1 = {h2, h3};
    __nv_bfloat162 L0 = {__float2bfloat16(v.x - __bfloat162float(h0)),
                         __float2bfloat16(v.y - __bfloat162float(h1))};
    __nv_bfloat162 L1 = {__float2bfloat16(v.z - __bfloat162float(h2)),
                         __float2bfloat16(v.w - __bfloat162float(h3))};
    reinterpret_cast<__nv_bfloat162*>(hi)[i * 2]     = H0;
    reinterpret_cast<__nv_bfloat162*>(hi)[i * 2 + 1] = H1;
    reinterpret_cast<__nv_bfloat162*>(lo)[i * 2]     = L0;
    reinterpret_cast<__nv_bfloat162*>(lo)[i * 2 + 1] = L1;
}

// ---------------------------------------------------------------------------
// Weight transpose + split: W [k][n] fp32 -> Wt hi/lo [n][k] bf16
// ---------------------------------------------------------------------------
__global__ void __launch_bounds__(256) wt_kernel(
    const float* __restrict__ W, __nv_bfloat16* __restrict__ wt1,
    __nv_bfloat16* __restrict__ wt2)
{
    __shared__ float vs[64][65];
    const int k0 = blockIdx.y * 64;
    const int n0 = blockIdx.x * 64;
    const int t  = threadIdx.x;

    for (int i = t; i < 64 * 16; i += 256) {
        const int r = i >> 4, c = i & 15;
        const float4 v = *reinterpret_cast<const float4*>(
            W + (size_t)(k0 + r) * D_SZ + n0 + c * 4);
        vs[r][c * 4 + 0] = v.x; vs[r][c * 4 + 1] = v.y;
        vs[r][c * 4 + 2] = v.z; vs[r][c * 4 + 3] = v.w;
    }
    __syncthreads();

    for (int i = t; i < 64 * 64; i += 256) {
        const int n = i >> 6, k = i & 63;
        const float x = vs[k][n];
        const __nv_bfloat16 h = __float2bfloat16(x);
        const __nv_bfloat16 l = __float2bfloat16(x - __bfloat162float(h));
        const size_t o = (size_t)(n0 + n) * D_SZ + k0 + k;
        wt1[o] = h;
        wt2[o] = l;
    }
}

// ---------------------------------------------------------------------------
// bf16x3 warp-MMA GEMM with cp.async double buffering.
// Byte offsets within one buffer:
//   A1B=0, A2B=18432, W1B=36864, W2B=55296; buffer size GM_HALF=73728.
// ---------------------------------------------------------------------------
#define A1B 0
#define A2B (128 * TSTR * 2)
#define W1B (2 * 128 * TSTR * 2)
#define W2B (3 * 128 * TSTR * 2)
#define GM_HALF (4 * 128 * TSTR * 2)          // 73728
#define GEMM_SMEM (2 * GM_HALF)               // 147456

__global__ void __launch_bounds__(256) gemm_mma(
    const __nv_bfloat16* __restrict__ a1, const __nv_bfloat16* __restrict__ a2,
    const __nv_bfloat16* __restrict__ wt1, const __nv_bfloat16* __restrict__ wt2,
    const float* __restrict__ bias,
    float* __restrict__ outf, __nv_bfloat16* __restrict__ outh,
    __nv_bfloat16* __restrict__ outl, int mode)
{
    extern __shared__ __align__(16) char smc[];
    const int t = threadIdx.x;
    const int lane = t & 31, wid = t >> 5;
    const int wq = wid & 3, wk = wid >> 2;
    const int n0 = blockIdx.x * 128;
    const int m0 = blockIdx.y * 128;
    const uint32_t sb = smem_u32(smc);

    float acc[2][8][4] = {};

    // async stage of chunk ck into buffer buf
    auto stage = [&](int ck, int buf) {
        const int j0 = ck * 64;
        const uint32_t base = sb + buf * GM_HALF;
#pragma unroll
        for (int ii = 0; ii < 4; ii++) {
            const int i = t + ii * 256;
            const int r = i >> 3, c = i & 7;
            const uint32_t off = (uint32_t)(r * TSTR + c * 8) * 2;
            const size_t ga = (size_t)(m0 + r) * D_SZ + j0 + c * 8;
            const size_t gw = (size_t)(n0 + r) * D_SZ + j0 + c * 8;
            cp16(base + A1B + off, a1 + ga);
            cp16(base + A2B + off, a2 + ga);
            cp16(base + W1B + off, wt1 + gw);
            cp16(base + W2B + off, wt2 + gw);
        }
    };

    stage(0, 0);
    CP_COMMIT();

    for (int ck = 0; ck < 16; ck++) {
        CP_WAIT0();
        __syncthreads();
        if (ck < 15) { stage(ck + 1, (ck + 1) & 1); CP_COMMIT(); }
        const uint32_t bb = sb + (ck & 1) * GM_HALF;

#pragma unroll
        for (int ks = 0; ks < 4; ks++) {
            const int kc = ks * 16;
            uint32_t ah[2][4], al[2][4];
#pragma unroll
            for (int mi = 0; mi < 2; mi++) {
                const int row = wq * 32 + mi * 16 + (lane & 15);
                const int col = kc + ((lane >> 4) << 3);
                ldsm_x4(ah[mi], bb + A1B + (uint32_t)(row * TSTR + col) * 2);
                ldsm_x4(al[mi], bb + A2B + (uint32_t)(row * TSTR + col) * 2);
            }
#pragma unroll
            for (int ni = 0; ni < 8; ni++) {
                uint32_t bh_[2], bl_[2];
                const int row = wk * 64 + ni * 8 + (lane & 7);
                const int col = kc + (((lane >> 3) & 1) << 3);
                ldsm_x2(bh_, bb + W1B + (uint32_t)(row * TSTR + col) * 2);
                ldsm_x2(bl_, bb + W2B + (uint32_t)(row * TSTR + col) * 2);
#pragma unroll
                for (int mi = 0; mi < 2; mi++) {
                    mma_bf16(acc[mi][ni], ah[mi], bh_);
                    mma_bf16(acc[mi][ni], ah[mi], bl_);
                    mma_bf16(acc[mi][ni], al[mi], bh_);
                }
            }
        }
    }

    const int g  = lane >> 2;
    const int tg = lane & 3;
#pragma unroll
    for (int mi = 0; mi < 2; mi++) {
#pragma unroll
        for (int ni = 0; ni < 8; ni++) {
            const int col = n0 + wk * 64 + ni * 8 + tg * 2;
            const float2 bb2 = *reinterpret_cast<const float2*>(bias + col);
            const int m = m0 + wq * 32 + mi * 16 + g;
            float2 r0 = make_float2(acc[mi][ni][0] + bb2.x, acc[mi][ni][1] + bb2.y);
            float2 r1 = make_float2(acc[mi][ni][2] + bb2.x, acc[mi][ni][3] + bb2.y);
            if (mode == 0) {
                *reinterpret_cast<float2*>(outf + (size_t)m * D_SZ + col) = r0;
                *reinterpret_cast<float2*>(outf + (size_t)(m + 8) * D_SZ + col) = r1;
            } else {
                const int h  = col >> 6;
                const int dk = col & 63;
                const int b0 = m >> 11, s0 = m & 2047;
                const int b1 = (m + 8) >> 11, s1 = (m + 8) & 2047;
                const size_t o0 = (((size_t)(b0 * H_SZ + h) * S_SZ + s0) * DK_SZ) + dk;
                const size_t o1 = (((size_t)(b1 * H_SZ + h) * S_SZ + s1) * DK_SZ) + dk;
                if (mode == 2) {
                    *reinterpret_cast<float2*>(outf + o0) = r0;
                    *reinterpret_cast<float2*>(outf + o1) = r1;
                } else {
                    const __nv_bfloat16 h00 = __float2bfloat16(r0.x);
                    const __nv_bfloat16 h01 = __float2bfloat16(r0.y);
                    const __nv_bfloat16 h10 = __float2bfloat16(r1.x);
                    const __nv_bfloat16 h11 = __float2bfloat16(r1.y);
                    *reinterpret_cast<uint32_t*>(outh + o0) = bf2pack(h00, h01);
                    *reinterpret_cast<uint32_t*>(outh + o1) = bf2pack(h10, h11);
                    *reinterpret_cast<uint32_t*>(outl + o0) = bf2pack(
                        __float2bfloat16(r0.x - __bfloat162float(h00)),
                        __float2bfloat16(r0.y - __bfloat162float(h01)));
                    *reinterpret_cast<uint32_t*>(outl + o1) = bf2pack(
                        __float2bfloat16(r1.x - __bfloat162float(h10)),
                        __float2bfloat16(r1.y - __bfloat162float(h11)));
                }
            }
        }
    }
}

// ---------------------------------------------------------------------------
// V transpose (hi only): g_v [bh][s][64] -> g_vt1 [bh][64][2048]
// ---------------------------------------------------------------------------
__global__ void __launch_bounds__(128) vt_kernel()
{
    __shared__ float vs[128][65];
    const int jt = blockIdx.x;
    const int bh = blockIdx.y;
    const int t  = threadIdx.x;
    const int j0 = jt * 128;

    const float4* src = reinterpret_cast<const float4*>(
        g_v + ((size_t)bh * S_SZ + j0) * DK_SZ);
    for (int i = t; i < 128 * 16; i += 128) {
        const int r = i >> 4, c = i & 15;
        const float4 v = src[i];
        vs[r][c * 4 + 0] = v.x; vs[r][c * 4 + 1] = v.y;
        vs[r][c * 4 + 2] = v.z; vs[r][c * 4 + 3] = v.w;
    }
    __syncthreads();

    for (int i = t; i < 64 * 128; i += 128) {
        const int j = i & 127;
        const int d = i >> 7;
        g_vt1[((size_t)bh * 64 + d) * S_SZ + j0 + j] = __float2bfloat16(vs[j][d]);
    }
}

// ---------------------------------------------------------------------------
// Score kernel (round-8, verified): masked scaled scores -> sbuf
// ---------------------------------------------------------------------------
#define SQ_H 0
#define SQ_L (128 * TSTR)
#define SK_H (2 * 128 * TSTR)
#define SK_L (3 * 128 * TSTR)
#define SCORE_SMEM (4 * 128 * TSTR * 2)       // 73728 B

__global__ void __launch_bounds__(256) score_kernel(
    const int* __restrict__ mask, float* __restrict__ sbuf)
{
    extern __shared__ __align__(16) __nv_bfloat16 sm[];
    const int t = threadIdx.x;
    const int lane = t & 31, wid = t >> 5;
    const int wq = wid & 3, wk = wid >> 2;
    const int q0 = blockIdx.x * 128, k0 = blockIdx.y * 128;
    const int bh = blockIdx.z, b = bh >> 4;

    {
        const uint4* q1 = reinterpret_cast<const uint4*>(
            g_q1 + ((size_t)bh * S_SZ + q0) * DK_SZ);
        const uint4* q2 = reinterpret_cast<const uint4*>(
            g_q2 + ((size_t)bh * S_SZ + q0) * DK_SZ);
        const uint4* k1 = reinterpret_cast<const uint4*>(
            g_k1 + ((size_t)bh * S_SZ + k0) * DK_SZ);
        const uint4* k2 = reinterpret_cast<const uint4*>(
            g_k2 + ((size_t)bh * S_SZ + k0) * DK_SZ);
        for (int i = t; i < 1024; i += 256) {
            const int r = i >> 3, c = i & 7;
            const int off = r * TSTR + c * 8;
            *reinterpret_cast<uint4*>(
                reinterpret_cast<char*>(sm) + (size_t)(SQ_H + off) * 2) = q1[i];
            *reinterpret_cast<uint4*>(
                reinterpret_cast<char*>(sm) + (size_t)(SQ_L + off) * 2) = q2[i];
            *reinterpret_cast<uint4*>(
                reinterpret_cast<char*>(sm) + (size_t)(SK_H + off) * 2) = k1[i];
            *reinterpret_cast<uint4*>(
                reinterpret_cast<char*>(sm) + (size_t)(SK_L + off) * 2) = k2[i];
        }
    }
    __syncthreads();

    const uint32_t sb = smem_u32(sm);
    float acc[2][8][4] = {};

#pragma unroll
    for (int ks = 0; ks < 4; ks++) {
        const int kc = ks * 16;
        uint32_t ah[2][4], al[2][4];
#pragma unroll
        for (int mi = 0; mi < 2; mi++) {
            const int row = wq * 32 + mi * 16 + (lane & 15);
            const int col = kc + ((lane >> 4) << 3);
            ldsm_x4(ah[mi], sb + (uint32_t)(SQ_H + row * TSTR + col) * 2);
            ldsm_x4(al[mi], sb + (uint32_t)(SQ_L + row * TSTR + col) * 2);
        }
#pragma unroll
        for (int ni = 0; ni < 8; ni++) {
            uint32_t bh_[2], bl_[2];
            const int row = wk * 64 + ni * 8 + (lane & 7);
            const int col = kc + (((lane >> 3) & 1) << 3);
            ldsm_x2(bh_, sb + (uint32_t)(SK_H + row * TSTR + col) * 2);
            ldsm_x2(bl_, sb + (uint32_t)(SK_L + row * TSTR + col) * 2);
#pragma unroll
            for (int mi = 0; mi < 2; mi++) {
                mma_bf16(acc[mi][ni], ah[mi], bh_);
                mma_bf16(acc[mi][ni], ah[mi], bl_);
                mma_bf16(acc[mi][ni], al[mi], bh_);
            }
        }
    }

    const int g  = lane >> 2;
    const int tg = lane & 3;
#pragma unroll
    for (int mi = 0; mi < 2; mi++) {
#pragma unroll
        for (int ni = 0; ni < 8; ni++) {
            const int q = q0 + wq * 32 + mi * 16 + g;
            const int k = k0 + wk * 64 + ni * 8 + tg * 2;
            const int2 m0 = *reinterpret_cast<const int2*>(
                mask + ((size_t)b * S_SZ + q) * S_SZ + k);
            const int2 m1 = *reinterpret_cast<const int2*>(
                mask + ((size_t)b * S_SZ + q + 8) * S_SZ + k);
            float2 s0, s1;
            s0.x = m0.x ? -1e9f : acc[mi][ni][0] * 0.125f;
            s0.y = m0.y ? -1e9f : acc[mi][ni][1] * 0.125f;
            s1.x = m1.x ? -1e9f : acc[mi][ni][2] * 0.125f;
            s1.y = m1.y ? -1e9f : acc[mi][ni][3] * 0.125f;
            *reinterpret_cast<float2*>(
                sbuf + ((size_t)bh * S_SZ + q) * S_SZ + k) = s0;
            *reinterpret_cast<float2*>(
                sbuf + ((size_t)bh * S_SZ + q + 8) * S_SZ + k) = s1;
        }
    }
}

// ---------------------------------------------------------------------------
// Softmax (in place over rows of 2048)
// ---------------------------------------------------------------------------
__global__ void __launch_bounds__(256) softmax_kernel(float* __restrict__ buf)
{
    __shared__ float red[8];
    const size_t row = blockIdx.x;
    const int t = threadIdx.x;
    float4* p4 = reinterpret_cast<float4*>(buf + row * S_SZ);

    float4 v0 = p4[t], v1 = p4[t + 256];
    float mx = fmaxf(fmaxf(fmaxf(v0.x, v0.y), fmaxf(v0.z, v0.w)),
                     fmaxf(fmaxf(v1.x, v1.y), fmaxf(v1.z, v1.w)));
#pragma unroll
    for (int o = 16; o; o >>= 1) mx = fmaxf(mx, __shfl_xor_sync(0xffffffffu, mx, o));
    if ((t & 31) == 0) red[t >> 5] = mx;
    __syncthreads();
    mx = fmaxf(fmaxf(fmaxf(red[0], red[1]), fmaxf(red[2], red[3])),
               fmaxf(fmaxf(red[4], red[5]), fmaxf(red[6], red[7])));
    __syncthreads();

    v0.x = __expf(v0.x - mx); v0.y = __expf(v0.y - mx);
    v0.z = __expf(v0.z - mx); v0.w = __expf(v0.w - mx);
    v1.x = __expf(v1.x - mx); v1.y = __expf(v1.y - mx);
    v1.z = __expf(v1.z - mx); v1.w = __expf(v1.w - mx);
    float sum = v0.x + v0.y + v0.z + v0.w + v1.x + v1.y + v1.z + v1.w;
#pragma unroll
    for (int o = 16; o; o >>= 1) sum += __shfl_xor_sync(0xffffffffu, sum, o);
    if ((t & 31) == 0) red[t >> 5] = sum;
    __syncthreads();
    const float inv = 1.f / (red[0] + red[1] + red[2] + red[3] +
                             red[4] + red[5] + red[6] + red[7]);

    v0.x *= inv; v0.y *= inv; v0.z *= inv; v0.w *= inv;
    v1.x *= inv; v1.y *= inv; v1.z *= inv; v1.w *= inv;
    p4[t] = v0;
    p4[t + 256] = v1;
}

// ---------------------------------------------------------------------------
// Context kernel (round-8 structure, 2-term PV: P hi/lo x V hi)
// ---------------------------------------------------------------------------
#define CP_H 0
#define CP_L (128 * TSTR)
#define CV_H (2 * 128 * TSTR)
#define CTX_SMEM ((2 * 128 * TSTR + 64 * TSTR) * 2)   // 46080 B

__global__ void __launch_bounds__(256) ctx_kernel(const float* __restrict__ probs)
{
    extern __shared__ __align__(16) __nv_bfloat16 sm[];
    const int t = threadIdx.x;
    const int lane = t & 31, wid = t >> 5;
    const int q0 = blockIdx.x * 128;
    const int bh = blockIdx.y, b = bh >> 4, h = bh & 15;
    const uint32_t sb = smem_u32(sm);

    const float* prow = probs + ((size_t)bh * S_SZ + q0) * S_SZ;
    const __nv_bfloat16* vt1 = g_vt1 + (size_t)bh * 64 * S_SZ;

    float acc[8][4] = {};

    for (int ch = 0; ch < 32; ch++) {
        const int j0 = ch * 64;
        __syncthreads();
        for (int i = t; i < 2048; i += 256) {
            const int r = i >> 4, c = i & 15;
            const float4 v = *reinterpret_cast<const float4*>(
                prow + (size_t)r * S_SZ + j0 + c * 4);
            const __nv_bfloat16 h0 = __float2bfloat16(v.x);
            const __nv_bfloat16 h1 = __float2bfloat16(v.y);
            const __nv_bfloat16 h2 = __float2bfloat16(v.z);
            const __nv_bfloat16 h3 = __float2bfloat16(v.w);
            const uint2 hp = make_uint2(bf2pack(h0, h1), bf2pack(h2, h3));
            const uint2 lp = make_uint2(
                bf2pack(__float2bfloat16(v.x - __bfloat162float(h0)),
                        __float2bfloat16(v.y - __bfloat162float(h1))),
                bf2pack(__float2bfloat16(v.z - __bfloat162float(h2)),
                        __float2bfloat16(v.w - __bfloat162float(h3))));
            const int off = r * TSTR + c * 4;
            *reinterpret_cast<uint2*>(
                reinterpret_cast<char*>(sm) + (size_t)(CP_H + off) * 2) = hp;
            *reinterpret_cast<uint2*>(
                reinterpret_cast<char*>(sm) + (size_t)(CP_L + off) * 2) = lp;
        }
        for (int i = t; i < 512; i += 256) {
            const int r = i >> 3, c = i & 7;
            const int off = r * TSTR + c * 8;
            *reinterpret_cast<uint4*>(
                reinterpret_cast<char*>(sm) + (size_t)(CV_H + off) * 2) =
                *reinterpret_cast<const uint4*>(vt1 + (size_t)r * S_SZ + j0 + c * 8);
        }
        __syncthreads();

#pragma unroll
        for (int ks = 0; ks < 4; ks++) {
            const int kc = ks * 16;
            uint32_t ah[4], al[4];
            {
                const int row = wid * 16 + (lane & 15);
                const int col = kc + ((lane >> 4) << 3);
                ldsm_x4(ah, sb + (uint32_t)(CP_H + row * TSTR + col) * 2);
                ldsm_x4(al, sb + (uint32_t)(CP_L + row * TSTR + col) * 2);
            }
#pragma unroll
            for (int ni = 0; ni < 8; ni++) {
                uint32_t bh_[2];
                const int row = ni * 8 + (lane & 7);
                const int col = kc + (((lane >> 3) & 1) << 3);
                ldsm_x2(bh_, sb + (uint32_t)(CV_H + row * TSTR + col) * 2);
                mma_bf16(acc[ni], ah, bh_);
                mma_bf16(acc[ni], al, bh_);
            }
        }
    }

    const int g  = lane >> 2;
    const int tg = lane & 3;
#pragma unroll
    for (int ni = 0; ni < 8; ni++) {
        const int q = q0 + wid * 16 + g;
        const int d = ni * 8 + tg * 2;
        *reinterpret_cast<float2*>(
            g_ctx + ((size_t)(b * S_SZ + q)) * D_SZ + h * DK_SZ + d) =
            make_float2(acc[ni][0], acc[ni][1]);
        *reinterpret_cast<float2*>(
            g_ctx + ((size_t)(b * S_SZ + q + 8)) * D_SZ + h * DK_SZ + d) =
            make_float2(acc[ni][2], acc[ni][3]);
    }
}

// ---------------------------------------------------------------------------
// Residual + LayerNorm
// ---------------------------------------------------------------------------
__global__ void __launch_bounds__(256) ln_kernel(
    const float* __restrict__ resid, const float* __restrict__ gamma,
    const float* __restrict__ beta, float* __restrict__ out)
{
    __shared__ float rs[8], rq[8];
    const int row = blockIdx.x;
    const int t = threadIdx.x;

    const float4 a = reinterpret_cast<const float4*>(g_o + (size_t)row * D_SZ)[t];
    const float4 r = reinterpret_cast<const float4*>(resid + (size_t)row * D_SZ)[t];
    const float4 v = make_float4(a.x + r.x, a.y + r.y, a.z + r.z, a.w + r.w);

    float s  = v.x + v.y + v.z + v.w;
    float sq = v.x * v.x + v.y * v.y + v.z * v.z + v.w * v.w;
#pragma unroll
    for (int o = 16; o; o >>= 1) {
        s  += __shfl_xor_sync(0xffffffffu, s, o);
        sq += __shfl_xor_sync(0xffffffffu, sq, o);
    }
    if ((t & 31) == 0) { rs[t >> 5] = s; rq[t >> 5] = sq; }
    __syncthreads();
    float S = 0.f, SQ = 0.f;
#pragma unroll
    for (int i = 0; i < 8; i++) { S += rs[i]; SQ += rq[i]; }
    const float mu  = S * (1.f / D_SZ);
    const float var = SQ * (1.f / D_SZ) - mu * mu;
    const float rstd = rsqrtf(var + 1e-5f);

    const float4 g  = reinterpret_cast<const float4*>(gamma)[t];
    const float4 be = reinterpret_cast<const float4*>(beta)[t];
    reinterpret_cast<float4*>(out + (size_t)row * D_SZ)[t] =
        make_float4((v.x - mu) * rstd * g.x + be.x,
                    (v.y - mu) * rstd * g.y + be.y,
                    (v.z - mu) * rstd * g.z + be.z,
                    (v.w - mu) * rstd * g.w + be.w);
}

// ---------------------------------------------------------------------------
// kernel_launch
// ---------------------------------------------------------------------------
extern "C" void kernel_launch(void* const* d_in, const int* in_sizes, int n_in,
                              void* d_out, int out_size)
{
    const float* Q  = (const float*)d_in[0];
    const float* K  = (const float*)d_in[1];
    const float* V  = (const float*)d_in[2];
    const int*   mask = (const int*)d_in[3];
    const float* Wq = (const float*)d_in[4];
    const float* bq = (const float*)d_in[5];
    const float* Wk = (const float*)d_in[6];
    const float* bk = (const float*)d_in[7];
    const float* Wv = (const float*)d_in[8];
    const float* bv = (const float*)d_in[9];
    const float* Wo = (const float*)d_in[10];
    const float* bo = (const float*)d_in[11];
    const float* gamma = (const float*)d_in[12];
    const float* beta  = (const float*)d_in[13];

    float *vp, *ctx, *op, *scp;
    __nv_bfloat16 *a1, *a2, *w1, *w2, *q1, *q2, *k1, *k2;
    cudaGetSymbolAddress((void**)&vp,  g_v);
    cudaGetSymbolAddress((void**)&ctx, g_ctx);
    cudaGetSymbolAddress((void**)&op,  g_o);
    cudaGetSymbolAddress((void**)&scp, g_sc);
    cudaGetSymbolAddress((void**)&a1,  g_a1);
    cudaGetSymbolAddress((void**)&a2,  g_a2);
    cudaGetSymbolAddress((void**)&w1,  g_wt1);
    cudaGetSymbolAddress((void**)&w2,  g_wt2);
    cudaGetSymbolAddress((void**)&q1,  g_q1);
    cudaGetSymbolAddress((void**)&q2,  g_q2);
    cudaGetSymbolAddress((void**)&k1,  g_k1);
    cudaGetSymbolAddress((void**)&k2,  g_k2);

    float* outp = (float*)d_out;
    float* sbuf = scp;
    if ((long long)out_size >= (long long)OUT_ELEMS + (long long)ATTN_ELEMS)
        sbuf = outp + OUT_ELEMS;   // probs land directly in the attn output

    cudaFuncSetAttribute(score_kernel,
        cudaFuncAttributeMaxDynamicSharedMemorySize, SCORE_SMEM);
    cudaFuncSetAttribute(ctx_kernel,
        cudaFuncAttributeMaxDynamicSharedMemorySize, CTX_SMEM);
    cudaFuncSetAttribute(gemm_mma,
        cudaFuncAttributeMaxDynamicSharedMemorySize, GEMM_SMEM);

    const dim3 wt_grid(D_SZ / 64, D_SZ / 64);
    const dim3 gm_grid(D_SZ / 128, M_SZ / 128);
    const int  split_blocks = (M_SZ * D_SZ / 4) / 256;

    // q projection (bf16 hi/lo output, split fused)
    split_kernel<<<split_blocks, 256>>>(Q, a1, a2);
    wt_kernel<<<wt_grid, 256>>>(Wq, w1, w2);
    gemm_mma<<<gm_grid, 256, GEMM_SMEM>>>(a1, a2, w1, w2, bq, nullptr, q1, q2, 1);

    // k projection
    split_kernel<<<split_blocks, 256>>>(K, a1, a2);
    wt_kernel<<<wt_grid, 256>>>(Wk, w1, w2);
    gemm_mma<<<gm_grid, 256, GEMM_SMEM>>>(a1, a2, w1, w2, bk, nullptr, k1, k2, 1);

    // v projection -> fp32 [bh,s,64], then transpose (hi only)
    split_kernel<<<split_blocks, 256>>>(V, a1, a2);
    wt_kernel<<<wt_grid, 256>>>(Wv, w1, w2);
    gemm_mma<<<gm_grid, 256, GEMM_SMEM>>>(a1, a2, w1, w2, bv, vp, nullptr, nullptr, 2);
    vt_kernel<<<dim3(16, BH_SZ), 128>>>();

    // attention
    score_kernel<<<dim3(S_SZ / 128, S_SZ / 128, BH_SZ), 256, SCORE_SMEM>>>(mask, sbuf);
    softmax_kernel<<<BH_SZ * S_SZ, 256>>>(sbuf);
    ctx_kernel<<<dim3(S_SZ / 128, BH_SZ), 256, CTX_SMEM>>>(sbuf);

    // output projection + LN
    split_kernel<<<split_blocks, 256>>>(ctx, a1, a2);
    wt_kernel<<<wt_grid, 256>>>(Wo, w1, w2);
    gemm_mma<<<gm_grid, 256, GEMM_SMEM>>>(a1, a2, w1, w2, bo, op, nullptr, nullptr, 0);

    ln_kernel<<<M_SZ, 256>>>(Q, gamma, beta, outp);
}

// round 11
// speedup vs baseline: 1.0686x; 1.0131x over previous
#include <cuda_runtime.h>
#include <cuda_bf16.h>
#include <cstdint>

// ---------------------------------------------------------------------------
// Problem constants
// ---------------------------------------------------------------------------
#define B_SZ 2
#define S_SZ 2048
#define D_SZ 1024
#define H_SZ 16
#define DK_SZ 64
#define BH_SZ (B_SZ * H_SZ)                   // 32
#define M_SZ (B_SZ * S_SZ)                    // 4096
#define OUT_ELEMS (B_SZ * S_SZ * D_SZ)        // 4,194,304
#define ATTN_ELEMS (134217728)                // B*H*S*S
#define MD ((size_t)M_SZ * D_SZ)
#define DD ((size_t)D_SZ * D_SZ)

// ---------------------------------------------------------------------------
// Scratch
// ---------------------------------------------------------------------------
__device__ float g_v[M_SZ * D_SZ];            // v proj fp32 [bh,s,dv]
__device__ float g_ctx[M_SZ * D_SZ];          // [b,s,h*dv]
__device__ float g_o[M_SZ * D_SZ];
__device__ __nv_bfloat16 g_a1[3 * M_SZ * D_SZ];   // activation splits (3 slots)
__device__ __nv_bfloat16 g_a2[3 * M_SZ * D_SZ];
__device__ __nv_bfloat16 g_wt1[3 * D_SZ * D_SZ];  // weight^T splits (3 slots)
__device__ __nv_bfloat16 g_wt2[3 * D_SZ * D_SZ];
__device__ __nv_bfloat16 g_q1[M_SZ * D_SZ];   // q/k proj bf16 hi/lo [bh,s,dk]
__device__ __nv_bfloat16 g_q2[M_SZ * D_SZ];
__device__ __nv_bfloat16 g_k1[M_SZ * D_SZ];
__device__ __nv_bfloat16 g_k2[M_SZ * D_SZ];
__device__ __nv_bfloat16 g_vt1[M_SZ * D_SZ];  // V transposed hi: [bh][d][s]
__device__ float g_sc[ATTN_ELEMS];            // score/prob scratch (if !write_attn)

// ---------------------------------------------------------------------------
// Warp MMA helpers (sm_80+ features only)
// ---------------------------------------------------------------------------
__device__ __forceinline__ uint32_t smem_u32(const void* p) {
    uint32_t a;
    asm("{ .reg .u64 t; cvta.to.shared.u64 t, %1; cvt.u32.u64 %0, t; }"
        : "=r"(a) : "l"(p));
    return a;
}

__device__ __forceinline__ void mma_bf16(float* c, const uint32_t* a,
                                         const uint32_t* b) {
    asm volatile(
        "mma.sync.aligned.m16n8k16.row.col.f32.bf16.bf16.f32 "
        "{%0,%1,%2,%3}, {%4,%5,%6,%7}, {%8,%9}, {%0,%1,%2,%3};"
        : "+f"(c[0]), "+f"(c[1]), "+f"(c[2]), "+f"(c[3])
        : "r"(a[0]), "r"(a[1]), "r"(a[2]), "r"(a[3]),
          "r"(b[0]), "r"(b[1]));
}

__device__ __forceinline__ void ldsm_x4(uint32_t* r, uint32_t addr) {
    asm volatile("ldmatrix.sync.aligned.m8n8.x4.shared.b16 {%0,%1,%2,%3}, [%4];"
                 : "=r"(r[0]), "=r"(r[1]), "=r"(r[2]), "=r"(r[3]) : "r"(addr));
}

__device__ __forceinline__ void cp16(uint32_t dst, const void* src) {
    asm volatile("cp.async.cg.shared.global [%0], [%1], 16;"
                 :: "r"(dst), "l"(src) : "memory");
}
#define CP_COMMIT() asm volatile("cp.async.commit_group;" ::: "memory")
#define CP_WAIT0()  asm volatile("cp.async.wait_group 0;" ::: "memory")

__device__ __forceinline__ uint32_t bf2pack(__nv_bfloat16 a, __nv_bfloat16 b) {
    __nv_bfloat162 v = {a, b};
    return *reinterpret_cast<uint32_t*>(&v);
}

// Tile stride: 72 bf16 per row (144 B, conflict-staggered, 16B aligned)
#define TSTR 72

// ---------------------------------------------------------------------------
// Batched fp32 -> bf16 hi/lo split: z selects input, writes slot z
// ---------------------------------------------------------------------------
__global__ void __launch_bounds__(256) split3_kernel(
    const float* __restrict__ i0, const float* __restrict__ i1,
    const float* __restrict__ i2)
{
    const int z = blockIdx.y;
    const float* in = (z == 0) ? i0 : (z == 1) ? i1 : i2;
    __nv_bfloat16* hi = g_a1 + (size_t)z * MD;
    __nv_bfloat16* lo = g_a2 + (size_t)z * MD;

    const int i = blockIdx.x * 256 + threadIdx.x;
    const float4 v = reinterpret_cast<const float4*>(in)[i];
    __nv_bfloat16 h0 = __float2bfloat16(v.x);
    __nv_bfloat16 h1 = __float2bfloat16(v.y);
    __nv_bfloat16 h2 = __float2bfloat16(v.z);
    __nv_bfloat16 h3 = __float2bfloat16(v.w);
    __nv_bfloat162 H0 = {h0, h1}, H1 = {h2, h3};
    __nv_bfloat162 L0 = {__float2bfloat16(v.x - __bfloat162float(h0)),
                         __float2bfloat16(v.y - __bfloat162float(h1))};
    __nv_bfloat162 L1 = {__float2bfloat16(v.z - __bfloat162float(h2)),
                         __float2bfloat16(v.w - __bfloat162float(h3))};
    reinterpret_cast<__nv_bfloat162*>(hi)[i * 2]     = H0;
    reinterpret_cast<__nv_bfloat162*>(hi)[i * 2 + 1] = H1;
    reinterpret_cast<__nv_bfloat162*>(lo)[i * 2]     = L0;
    reinterpret_cast<__nv_bfloat162*>(lo)[i * 2 + 1] = L1;
}

// ---------------------------------------------------------------------------
// Batched weight transpose + split: z selects W, writes slot z
// ---------------------------------------------------------------------------
__global__ void __launch_bounds__(256) wt3_kernel(
    const float* __restrict__ W0, const float* __restrict__ W1,
    const float* __restrict__ W2)
{
    __shared__ float vs[64][65];
    const int z = blockIdx.z;
    const float* W = (z == 0) ? W0 : (z == 1) ? W1 : W2;
    __nv_bfloat16* wt1 = g_wt1 + (size_t)z * DD;
    __nv_bfloat16* wt2 = g_wt2 + (size_t)z * DD;
    const int k0 = blockIdx.y * 64;
    const int n0 = blockIdx.x * 64;
    const int t  = threadIdx.x;

    for (int i = t; i < 64 * 16; i += 256) {
        const int r = i >> 4, c = i & 15;
        const float4 v = *reinterpret_cast<const float4*>(
            W + (size_t)(k0 + r) * D_SZ + n0 + c * 4);
        vs[r][c * 4 + 0] = v.x; vs[r][c * 4 + 1] = v.y;
        vs[r][c * 4 + 2] = v.z; vs[r][c * 4 + 3] = v.w;
    }
    __syncthreads();

    for (int i = t; i < 64 * 64; i += 256) {
        const int n = i >> 6, k = i & 63;
        const float x = vs[k][n];
        const __nv_bfloat16 h = __float2bfloat16(x);
        const __nv_bfloat16 l = __float2bfloat16(x - __bfloat162float(h));
        const size_t o = (size_t)(n0 + n) * D_SZ + k0 + k;
        wt1[o] = h;
        wt2[o] = l;
    }
}

// ---------------------------------------------------------------------------
// GEMM core: bf16x3, cp.async double-buffered, x4 B-operand ldsm.
// ---------------------------------------------------------------------------
#define A1B 0
#define A2B (128 * TSTR * 2)
#define W1B (2 * 128 * TSTR * 2)
#define W2B (3 * 128 * TSTR * 2)
#define GM_HALF (4 * 128 * TSTR * 2)          // 73728
#define GEMM_SMEM (2 * GM_HALF)               // 147456

__device__ __forceinline__ void gemm_core(
    const __nv_bfloat16* a1, const __nv_bfloat16* a2,
    const __nv_bfloat16* wt1, const __nv_bfloat16* wt2,
    const float* bias, float* outf, __nv_bfloat16* outh,
    __nv_bfloat16* outl, int mode, int m0, int n0, char* smc)
{
    const int t = threadIdx.x;
    const int lane = t & 31, wid = t >> 5;
    const int wq = wid & 3, wk = wid >> 2;
    const uint32_t sb = smem_u32(smc);

    float acc[2][8][4] = {};

    auto stage = [&](int ck, int buf) {
        const int j0 = ck * 64;
        const uint32_t base = sb + buf * GM_HALF;
#pragma unroll
        for (int ii = 0; ii < 4; ii++) {
            const int i = t + ii * 256;
            const int r = i >> 3, c = i & 7;
            const uint32_t off = (uint32_t)(r * TSTR + c * 8) * 2;
            const size_t ga = (size_t)(m0 + r) * D_SZ + j0 + c * 8;
            const size_t gw = (size_t)(n0 + r) * D_SZ + j0 + c * 8;
            cp16(base + A1B + off, a1 + ga);
            cp16(base + A2B + off, a2 + ga);
            cp16(base + W1B + off, wt1 + gw);
            cp16(base + W2B + off, wt2 + gw);
        }
    };

    stage(0, 0);
    CP_COMMIT();

    for (int ck = 0; ck < 16; ck++) {
        CP_WAIT0();
        __syncthreads();
        if (ck < 15) { stage(ck + 1, (ck + 1) & 1); CP_COMMIT(); }
        const uint32_t bb = sb + (ck & 1) * GM_HALF;

#pragma unroll
        for (int ks = 0; ks < 4; ks++) {
            const int kc = ks * 16;
            uint32_t ah[2][4], al[2][4];
#pragma unroll
            for (int mi = 0; mi < 2; mi++) {
                const int row = wq * 32 + mi * 16 + (lane & 15);
                const int col = kc + ((lane >> 4) << 3);
                ldsm_x4(ah[mi], bb + A1B + (uint32_t)(row * TSTR + col) * 2);
                ldsm_x4(al[mi], bb + A2B + (uint32_t)(row * TSTR + col) * 2);
            }
#pragma unroll
            for (int np = 0; np < 4; np++) {
                uint32_t bh4[4], bl4[4];
                const int row = wk * 64 + np * 16 + (lane & 7) + ((lane >> 4) & 1) * 8;
                const int col = kc + ((lane >> 3) & 1) * 8;
                ldsm_x4(bh4, bb + W1B + (uint32_t)(row * TSTR + col) * 2);
                ldsm_x4(bl4, bb + W2B + (uint32_t)(row * TSTR + col) * 2);
#pragma unroll
                for (int mi = 0; mi < 2; mi++) {
                    mma_bf16(acc[mi][np * 2],     ah[mi], bh4);
                    mma_bf16(acc[mi][np * 2],     ah[mi], bl4);
                    mma_bf16(acc[mi][np * 2],     al[mi], bh4);
                    mma_bf16(acc[mi][np * 2 + 1], ah[mi], bh4 + 2);
                    mma_bf16(acc[mi][np * 2 + 1], ah[mi], bl4 + 2);
                    mma_bf16(acc[mi][np * 2 + 1], al[mi], bh4 + 2);
                }
            }
        }
    }

    const int g  = lane >> 2;
    const int tg = lane & 3;
#pragma unroll
    for (int mi = 0; mi < 2; mi++) {
#pragma unroll
        for (int ni = 0; ni < 8; ni++) {
            const int col = n0 + wk * 64 + ni * 8 + tg * 2;
            const float2 bb2 = *reinterpret_cast<const float2*>(bias + col);
            const int m = m0 + wq * 32 + mi * 16 + g;
            float2 r0 = make_float2(acc[mi][ni][0] + bb2.x, acc[mi][ni][1] + bb2.y);
            float2 r1 = make_float2(acc[mi][ni][2] + bb2.x, acc[mi][ni][3] + bb2.y);
            if (mode == 0) {
                *reinterpret_cast<float2*>(outf + (size_t)m * D_SZ + col) = r0;
                *reinterpret_cast<float2*>(outf + (size_t)(m + 8) * D_SZ + col) = r1;
            } else {
                const int h  = col >> 6;
                const int dk = col & 63;
                const int b0 = m >> 11, s0 = m & 2047;
                const int b1 = (m + 8) >> 11, s1 = (m + 8) & 2047;
                const size_t o0 = (((size_t)(b0 * H_SZ + h) * S_SZ + s0) * DK_SZ) + dk;
                const size_t o1 = (((size_t)(b1 * H_SZ + h) * S_SZ + s1) * DK_SZ) + dk;
                if (mode == 2) {
                    *reinterpret_cast<float2*>(outf + o0) = r0;
                    *reinterpret_cast<float2*>(outf + o1) = r1;
                } else {
                    const __nv_bfloat16 h00 = __float2bfloat16(r0.x);
                    const __nv_bfloat16 h01 = __float2bfloat16(r0.y);
                    const __nv_bfloat16 h10 = __float2bfloat16(r1.x);
                    const __nv_bfloat16 h11 = __float2bfloat16(r1.y);
                    *reinterpret_cast<uint32_t*>(outh + o0) = bf2pack(h00, h01);
                    *reinterpret_cast<uint32_t*>(outh + o1) = bf2pack(h10, h11);
                    *reinterpret_cast<uint32_t*>(outl + o0) = bf2pack(
                        __float2bfloat16(r0.x - __bfloat162float(h00)),
                        __float2bfloat16(r0.y - __bfloat162float(h01)));
                    *reinterpret_cast<uint32_t*>(outl + o1) = bf2pack(
                        __float2bfloat16(r1.x - __bfloat162float(h10)),
                        __float2bfloat16(r1.y - __bfloat162float(h11)));
                }
            }
        }
    }
}

// Batched QKV projections: z=0 -> q1/q2 (mode 1), z=1 -> k1/k2, z=2 -> g_v (mode 2)
__global__ void __launch_bounds__(256) gemm_proj(
    const float* __restrict__ bq, const float* __restrict__ bk,
    const float* __restrict__ bv)
{
    extern __shared__ __align__(16) char smc[];
    const int z = blockIdx.z;
    const __nv_bfloat16* a1 = g_a1 + (size_t)z * MD;
    const __nv_bfloat16* a2 = g_a2 + (size_t)z * MD;
    const __nv_bfloat16* w1 = g_wt1 + (size_t)z * DD;
    const __nv_bfloat16* w2 = g_wt2 + (size_t)z * DD;
    const float* bias = (z == 0) ? bq : (z == 1) ? bk : bv;
    float* outf = (z == 2) ? g_v : nullptr;
    __nv_bfloat16* outh = (z == 0) ? g_q1 : g_k1;
    __nv_bfloat16* outl = (z == 0) ? g_q2 : g_k2;
    const int mode = (z == 2) ? 2 : 1;
    gemm_core(a1, a2, w1, w2, bias, outf, outh, outl, mode,
              blockIdx.y * 128, blockIdx.x * 128, smc);
}

// Output projection: slot 0 buffers, fp32 row-major out
__global__ void __launch_bounds__(256) gemm_out(
    const float* __restrict__ bo, float* __restrict__ outf)
{
    extern __shared__ __align__(16) char smc[];
    gemm_core(g_a1, g_a2, g_wt1, g_wt2, bo, outf, nullptr, nullptr, 0,
              blockIdx.y * 128, blockIdx.x * 128, smc);
}

// ---------------------------------------------------------------------------
// V transpose (hi only): g_v [bh][s][64] -> g_vt1 [bh][64][2048]
// ---------------------------------------------------------------------------
__global__ void __launch_bounds__(128) vt_kernel()
{
    __shared__ float vs[128][65];
    const int jt = blockIdx.x;
    const int bh = blockIdx.y;
    const int t  = threadIdx.x;
    const int j0 = jt * 128;

    const float4* src = reinterpret_cast<const float4*>(
        g_v + ((size_t)bh * S_SZ + j0) * DK_SZ);
    for (int i = t; i < 128 * 16; i += 128) {
        const int r = i >> 4, c = i & 15;
        const float4 v = src[i];
        vs[r][c * 4 + 0] = v.x; vs[r][c * 4 + 1] = v.y;
        vs[r][c * 4 + 2] = v.z; vs[r][c * 4 + 3] = v.w;
    }
    __syncthreads();

    for (int i = t; i < 64 * 128; i += 128) {
        const int j = i & 127;
        const int d = i >> 7;
        g_vt1[((size_t)bh * 64 + d) * S_SZ + j0 + j] = __float2bfloat16(vs[j][d]);
    }
}

// ---------------------------------------------------------------------------
// Score kernel: masked scaled scores -> sbuf (x4 K-operand ldsm)
// ---------------------------------------------------------------------------
#define SQ_H 0
#define SQ_L (128 * TSTR)
#define SK_H (2 * 128 * TSTR)
#define SK_L (3 * 128 * TSTR)
#define SCORE_SMEM (4 * 128 * TSTR * 2)       // 73728 B

__global__ void __launch_bounds__(256) score_kernel(
    const int* __restrict__ mask, float* __restrict__ sbuf)
{
    extern __shared__ __align__(16) __nv_bfloat16 sm[];
    const int t = threadIdx.x;
    const int lane = t & 31, wid = t >> 5;
    const int wq = wid & 3, wk = wid >> 2;
    const int q0 = blockIdx.x * 128, k0 = blockIdx.y * 128;
    const int bh = blockIdx.z, b = bh >> 4;

    {
        const uint4* q1 = reinterpret_cast<const uint4*>(
            g_q1 + ((size_t)bh * S_SZ + q0) * DK_SZ);
        const uint4* q2 = reinterpret_cast<const uint4*>(
            g_q2 + ((size_t)bh * S_SZ + q0) * DK_SZ);
        const uint4* k1 = reinterpret_cast<const uint4*>(
            g_k1 + ((size_t)bh * S_SZ + k0) * DK_SZ);
        const uint4* k2 = reinterpret_cast<const uint4*>(
            g_k2 + ((size_t)bh * S_SZ + k0) * DK_SZ);
        for (int i = t; i < 1024; i += 256) {
            const int r = i >> 3, c = i & 7;
            const int off = r * TSTR + c * 8;
            *reinterpret_cast<uint4*>(
                reinterpret_cast<char*>(sm) + (size_t)(SQ_H + off) * 2) = q1[i];
            *reinterpret_cast<uint4*>(
                reinterpret_cast<char*>(sm) + (size_t)(SQ_L + off) * 2) = q2[i];
            *reinterpret_cast<uint4*>(
                reinterpret_cast<char*>(sm) + (size_t)(SK_H + off) * 2) = k1[i];
            *reinterpret_cast<uint4*>(
                reinterpret_cast<char*>(sm) + (size_t)(SK_L + off) * 2) = k2[i];
        }
    }
    __syncthreads();

    const uint32_t sb = smem_u32(sm);
    float acc[2][8][4] = {};

#pragma unroll
    for (int ks = 0; ks < 4; ks++) {
        const int kc = ks * 16;
        uint32_t ah[2][4], al[2][4];
#pragma unroll
        for (int mi = 0; mi < 2; mi++) {
            const int row = wq * 32 + mi * 16 + (lane & 15);
            const int col = kc + ((lane >> 4) << 3);
            ldsm_x4(ah[mi], sb + (uint32_t)(SQ_H + row * TSTR + col) * 2);
            ldsm_x4(al[mi], sb + (uint32_t)(SQ_L + row * TSTR + col) * 2);
        }
#pragma unroll
        for (int np = 0; np < 4; np++) {
            uint32_t bh4[4], bl4[4];
            const int row = wk * 64 + np * 16 + (lane & 7) + ((lane >> 4) & 1) * 8;
            const int col = kc + ((lane >> 3) & 1) * 8;
            ldsm_x4(bh4, sb + (uint32_t)(SK_H + row * TSTR + col) * 2);
            ldsm_x4(bl4, sb + (uint32_t)(SK_L + row * TSTR + col) * 2);
#pragma unroll
            for (int mi = 0; mi < 2; mi++) {
                mma_bf16(acc[mi][np * 2],     ah[mi], bh4);
                mma_bf16(acc[mi][np * 2],     ah[mi], bl4);
                mma_bf16(acc[mi][np * 2],     al[mi], bh4);
                mma_bf16(acc[mi][np * 2 + 1], ah[mi], bh4 + 2);
                mma_bf16(acc[mi][np * 2 + 1], ah[mi], bl4 + 2);
                mma_bf16(acc[mi][np * 2 + 1], al[mi], bh4 + 2);
            }
        }
    }

    const int g  = lane >> 2;
    const int tg = lane & 3;
#pragma unroll
    for (int mi = 0; mi < 2; mi++) {
#pragma unroll
        for (int ni = 0; ni < 8; ni++) {
            const int q = q0 + wq * 32 + mi * 16 + g;
            const int k = k0 + wk * 64 + ni * 8 + tg * 2;
            const int2 m0 = *reinterpret_cast<const int2*>(
                mask + ((size_t)b * S_SZ + q) * S_SZ + k);
            const int2 m1 = *reinterpret_cast<const int2*>(
                mask + ((size_t)b * S_SZ + q + 8) * S_SZ + k);
            float2 s0, s1;
            s0.x = m0.x ? -1e9f : acc[mi][ni][0] * 0.125f;
            s0.y = m0.y ? -1e9f : acc[mi][ni][1] * 0.125f;
            s1.x = m1.x ? -1e9f : acc[mi][ni][2] * 0.125f;
            s1.y = m1.y ? -1e9f : acc[mi][ni][3] * 0.125f;
            *reinterpret_cast<float2*>(
                sbuf + ((size_t)bh * S_SZ + q) * S_SZ + k) = s0;
            *reinterpret_cast<float2*>(
                sbuf + ((size_t)bh * S_SZ + q + 8) * S_SZ + k) = s1;
        }
    }
}

// ---------------------------------------------------------------------------
// Softmax (in place over rows of 2048)
// ---------------------------------------------------------------------------
__global__ void __launch_bounds__(256) softmax_kernel(float* __restrict__ buf)
{
    __shared__ float red[8];
    const size_t row = blockIdx.x;
    const int t = threadIdx.x;
    float4* p4 = reinterpret_cast<float4*>(buf + row * S_SZ);

    float4 v0 = p4[t], v1 = p4[t + 256];
    float mx = fmaxf(fmaxf(fmaxf(v0.x, v0.y), fmaxf(v0.z, v0.w)),
                     fmaxf(fmaxf(v1.x, v1.y), fmaxf(v1.z, v1.w)));
#pragma unroll
    for (int o = 16; o; o >>= 1) mx = fmaxf(mx, __shfl_xor_sync(0xffffffffu, mx, o));
    if ((t & 31) == 0) red[t >> 5] = mx;
    __syncthreads();
    mx = fmaxf(fmaxf(fmaxf(red[0], red[1]), fmaxf(red[2], red[3])),
               fmaxf(fmaxf(red[4], red[5]), fmaxf(red[6], red[7])));
    __syncthreads();

    v0.x = __expf(v0.x - mx); v0.y = __expf(v0.y - mx);
    v0.z = __expf(v0.z - mx); v0.w = __expf(v0.w - mx);
    v1.x = __expf(v1.x - mx); v1.y = __expf(v1.y - mx);
    v1.z = __expf(v1.z - mx); v1.w = __expf(v1.w - mx);
    float sum = v0.x + v0.y + v0.z + v0.w + v1.x + v1.y + v1.z + v1.w;
#pragma unroll
    for (int o = 16; o; o >>= 1) sum += __shfl_xor_sync(0xffffffffu, sum, o);
    if ((t & 31) == 0) red[t >> 5] = sum;
    __syncthreads();
    const float inv = 1.f / (red[0] + red[1] + red[2] + red[3] +
                             red[4] + red[5] + red[6] + red[7]);

    v0.x *= inv; v0.y *= inv; v0.z *= inv; v0.w *= inv;
    v1.x *= inv; v1.y *= inv; v1.z *= inv; v1.w *= inv;
    p4[t] = v0;
    p4[t + 256] = v1;
}

// ---------------------------------------------------------------------------
// Context kernel: 2-term PV (P hi/lo x V hi), x4 V-operand ldsm
// ---------------------------------------------------------------------------
#define CP_H 0
#define CP_L (128 * TSTR)
#define CV_H (2 * 128 * TSTR)
#define CTX_SMEM ((2 * 128 * TSTR + 64 * TSTR) * 2)   // 46080 B

__global__ void __launch_bounds__(256) ctx_kernel(const float* __restrict__ probs)
{
    extern __shared__ __align__(16) __nv_bfloat16 sm[];
    const int t = threadIdx.x;
    const int lane = t & 31, wid = t >> 5;
    const int q0 = blockIdx.x * 128;
    const int bh = blockIdx.y, b = bh >> 4, h = bh & 15;
    const uint32_t sb = smem_u32(sm);

    const float* prow = probs + ((size_t)bh * S_SZ + q0) * S_SZ;
    const __nv_bfloat16* vt1 = g_vt1 + (size_t)bh * 64 * S_SZ;

    float acc[8][4] = {};

    for (int ch = 0; ch < 32; ch++) {
        const int j0 = ch * 64;
        __syncthreads();
        for (int i = t; i < 2048; i += 256) {
            const int r = i >> 4, c = i & 15;
            const float4 v = *reinterpret_cast<const float4*>(
                prow + (size_t)r * S_SZ + j0 + c * 4);
            const __nv_bfloat16 h0 = __float2bfloat16(v.x);
            const __nv_bfloat16 h1 = __float2bfloat16(v.y);
            const __nv_bfloat16 h2 = __float2bfloat16(v.z);
            const __nv_bfloat16 h3 = __float2bfloat16(v.w);
            const uint2 hp = make_uint2(bf2pack(h0, h1), bf2pack(h2, h3));
            const uint2 lp = make_uint2(
                bf2pack(__float2bfloat16(v.x - __bfloat162float(h0)),
                        __float2bfloat16(v.y - __bfloat162float(h1))),
                bf2pack(__float2bfloat16(v.z - __bfloat162float(h2)),
                        __float2bfloat16(v.w - __bfloat162float(h3))));
            const int off = r * TSTR + c * 4;
            *reinterpret_cast<uint2*>(
                reinterpret_cast<char*>(sm) + (size_t)(CP_H + off) * 2) = hp;
            *reinterpret_cast<uint2*>(
                reinterpret_cast<char*>(sm) + (size_t)(CP_L + off) * 2) = lp;
        }
        for (int i = t; i < 512; i += 256) {
            const int r = i >> 3, c = i & 7;
            const int off = r * TSTR + c * 8;
            *reinterpret_cast<uint4*>(
                reinterpret_cast<char*>(sm) + (size_t)(CV_H + off) * 2) =
                *reinterpret_cast<const uint4*>(vt1 + (size_t)r * S_SZ + j0 + c * 8);
        }
        __syncthreads();

#pragma unroll
        for (int ks = 0; ks < 4; ks++) {
            const int kc = ks * 16;
            uint32_t ah[4], al[4];
            {
                const int row = wid * 16 + (lane & 15);
                const int col = kc + ((lane >> 4) << 3);
                ldsm_x4(ah, sb + (uint32_t)(CP_H + row * TSTR + col) * 2);
                ldsm_x4(al, sb + (uint32_t)(CP_L + row * TSTR + col) * 2);
            }
#pragma unroll
            for (int np = 0; np < 4; np++) {
                uint32_t bh4[4];
                const int row = np * 16 + (lane & 7) + ((lane >> 4) & 1) * 8;
                const int col = kc + ((lane >> 3) & 1) * 8;
                ldsm_x4(bh4, sb + (uint32_t)(CV_H + row * TSTR + col) * 2);
                mma_bf16(acc[np * 2],     ah, bh4);
                mma_bf16(acc[np * 2],     al, bh4);
                mma_bf16(acc[np * 2 + 1], ah, bh4 + 2);
                mma_bf16(acc[np * 2 + 1], al, bh4 + 2);
            }
        }
    }

    const int g  = lane >> 2;
    const int tg = lane & 3;
#pragma unroll
    for (int ni = 0; ni < 8; ni++) {
        const int q = q0 + wid * 16 + g;
        const int d = ni * 8 + tg * 2;
        *reinterpret_cast<float2*>(
            g_ctx + ((size_t)(b * S_SZ + q)) * D_SZ + h * DK_SZ + d) =
            make_float2(acc[ni][0], acc[ni][1]);
        *reinterpret_cast<float2*>(
            g_ctx + ((size_t)(b * S_SZ + q + 8)) * D_SZ + h * DK_SZ + d) =
            make_float2(acc[ni][2], acc[ni][3]);
    }
}

// ---------------------------------------------------------------------------
// Residual + LayerNorm
// ---------------------------------------------------------------------------
__global__ void __launch_bounds__(256) ln_kernel(
    const float* __restrict__ resid, const float* __restrict__ gamma,
    const float* __restrict__ beta, float* __restrict__ out)
{
    __shared__ float rs[8], rq[8];
    const int row = blockIdx.x;
    const int t = threadIdx.x;

    const float4 a = reinterpret_cast<const float4*>(g_o + (size_t)row * D_SZ)[t];
    const float4 r = reinterpret_cast<const float4*>(resid + (size_t)row * D_SZ)[t];
    const float4 v = make_float4(a.x + r.x, a.y + r.y, a.z + r.z, a.w + r.w);

    float s  = v.x + v.y + v.z + v.w;
    float sq = v.x * v.x + v.y * v.y + v.z * v.z + v.w * v.w;
#pragma unroll
    for (int o = 16; o; o >>= 1) {
        s  += __shfl_xor_sync(0xffffffffu, s, o);
        sq += __shfl_xor_sync(0xffffffffu, sq, o);
    }
    if ((t & 31) == 0) { rs[t >> 5] = s; rq[t >> 5] = sq; }
    __syncthreads();
    float S = 0.f, SQ = 0.f;
#pragma unroll
    for (int i = 0; i < 8; i++) { S += rs[i]; SQ += rq[i]; }
    const float mu  = S * (1.f / D_SZ);
    const float var = SQ * (1.f / D_SZ) - mu * mu;
    const float rstd = rsqrtf(var + 1e-5f);

    const float4 g  = reinterpret_cast<const float4*>(gamma)[t];
    const float4 be = reinterpret_cast<const float4*>(beta)[t];
    reinterpret_cast<float4*>(out + (size_t)row * D_SZ)[t] =
        make_float4((v.x - mu) * rstd * g.x + be.x,
                    (v.y - mu) * rstd * g.y + be.y,
                    (v.z - mu) * rstd * g.z + be.z,
                    (v.w - mu) * rstd * g.w + be.w);
}

// ---------------------------------------------------------------------------
// kernel_launch
// ---------------------------------------------------------------------------
extern "C" void kernel_launch(void* const* d_in, const int* in_sizes, int n_in,
                              void* d_out, int out_size)
{
    const float* Q  = (const float*)d_in[0];
    const float* K  = (const float*)d_in[1];
    const float* V  = (const float*)d_in[2];
    const int*   mask = (const int*)d_in[3];
    const float* Wq = (const float*)d_in[4];
    const float* bq = (const float*)d_in[5];
    const float* Wk = (const float*)d_in[6];
    const float* bk = (const float*)d_in[7];
    const float* Wv = (const float*)d_in[8];
    const float* bv = (const float*)d_in[9];
    const float* Wo = (const float*)d_in[10];
    const float* bo = (const float*)d_in[11];
    const float* gamma = (const float*)d_in[12];
    const float* beta  = (const float*)d_in[13];

    float *ctx, *op, *scp;
    cudaGetSymbolAddress((void**)&ctx, g_ctx);
    cudaGetSymbolAddress((void**)&op,  g_o);
    cudaGetSymbolAddress((void**)&scp, g_sc);

    float* outp = (float*)d_out;
    float* sbuf = scp;
    if ((long long)out_size >= (long long)OUT_ELEMS + (long long)ATTN_ELEMS)
        sbuf = outp + OUT_ELEMS;   // probs land directly in the attn output

    cudaFuncSetAttribute(score_kernel,
        cudaFuncAttributeMaxDynamicSharedMemorySize, SCORE_SMEM);
    cudaFuncSetAttribute(ctx_kernel,
        cudaFuncAttributeMaxDynamicSharedMemorySize, CTX_SMEM);
    cudaFuncSetAttribute(gemm_proj,
        cudaFuncAttributeMaxDynamicSharedMemorySize, GEMM_SMEM);
    cudaFuncSetAttribute(gemm_out,
        cudaFuncAttributeMaxDynamicSharedMemorySize, GEMM_SMEM);

    // QKV projections, batched across z
    split3_kernel<<<dim3(M_SZ * D_SZ / 1024, 3), 256>>>(Q, K, V);
    wt3_kernel<<<dim3(16, 16, 3), 256>>>(Wq, Wk, Wv);
    gemm_proj<<<dim3(8, 32, 3), 256, GEMM_SMEM>>>(bq, bk, bv);
    vt_kernel<<<dim3(16, BH_SZ), 128>>>();

    // attention
    score_kernel<<<dim3(16, 16, BH_SZ), 256, SCORE_SMEM>>>(mask, sbuf);
    softmax_kernel<<<BH_SZ * S_SZ, 256>>>(sbuf);
    ctx_kernel<<<dim3(16, BH_SZ), 256, CTX_SMEM>>>(sbuf);

    // output projection (slot 0) + LN
    split3_kernel<<<dim3(M_SZ * D_SZ / 1024, 1), 256>>>(ctx, ctx, ctx);
    wt3_kernel<<<dim3(16, 16, 1), 256>>>(Wo, Wo, Wo);
    gemm_out<<<dim3(8, 32), 256, GEMM_SMEM>>>(bo, op);

    ln_kernel<<<M_SZ, 256>>>(Q, gamma, beta, outp);
}

// round 12
// speedup vs baseline: 1.2888x; 1.2060x over previous
#include <cuda_runtime.h>
#include <cuda_bf16.h>
#include <cstdint>

// ---------------------------------------------------------------------------
// Problem constants
// ---------------------------------------------------------------------------
#define B_SZ 2
#define S_SZ 2048
#define D_SZ 1024
#define H_SZ 16
#define DK_SZ 64
#define BH_SZ (B_SZ * H_SZ)                   // 32
#define M_SZ (B_SZ * S_SZ)                    // 4096
#define OUT_ELEMS (B_SZ * S_SZ * D_SZ)        // 4,194,304
#define ATTN_ELEMS (134217728)                // B*H*S*S
#define MD ((size_t)M_SZ * D_SZ)
#define DD ((size_t)D_SZ * D_SZ)

// ---------------------------------------------------------------------------
// Scratch
// ---------------------------------------------------------------------------
__device__ float g_v[M_SZ * D_SZ];            // v proj fp32 [bh,s,dv]
__device__ float g_ctx[M_SZ * D_SZ];          // [b,s,h*dv]
__device__ float g_o[M_SZ * D_SZ];
__device__ __nv_bfloat16 g_a1[3 * M_SZ * D_SZ];   // activation splits (3 slots)
__device__ __nv_bfloat16 g_a2[3 * M_SZ * D_SZ];
__device__ __nv_bfloat16 g_wt1[3 * D_SZ * D_SZ];  // weight^T splits (3 slots)
__device__ __nv_bfloat16 g_wt2[3 * D_SZ * D_SZ];
__device__ __nv_bfloat16 g_q1[M_SZ * D_SZ];   // q/k proj bf16 hi/lo [bh,s,dk]
__device__ __nv_bfloat16 g_q2[M_SZ * D_SZ];
__device__ __nv_bfloat16 g_k1[M_SZ * D_SZ];
__device__ __nv_bfloat16 g_k2[M_SZ * D_SZ];
__device__ __nv_bfloat16 g_vt1[M_SZ * D_SZ];  // V transposed hi: [bh][d][s]
__device__ float g_sc[ATTN_ELEMS];            // score/prob scratch (if !write_attn)

// ---------------------------------------------------------------------------
// Warp MMA helpers (sm_80+ features only)
// ---------------------------------------------------------------------------
__device__ __forceinline__ uint32_t smem_u32(const void* p) {
    uint32_t a;
    asm("{ .reg .u64 t; cvta.to.shared.u64 t, %1; cvt.u32.u64 %0, t; }"
        : "=r"(a) : "l"(p));
    return a;
}

__device__ __forceinline__ void mma_bf16(float* c, const uint32_t* a,
                                         const uint32_t* b) {
    asm volatile(
        "mma.sync.aligned.m16n8k16.row.col.f32.bf16.bf16.f32 "
        "{%0,%1,%2,%3}, {%4,%5,%6,%7}, {%8,%9}, {%0,%1,%2,%3};"
        : "+f"(c[0]), "+f"(c[1]), "+f"(c[2]), "+f"(c[3])
        : "r"(a[0]), "r"(a[1]), "r"(a[2]), "r"(a[3]),
          "r"(b[0]), "r"(b[1]));
}

__device__ __forceinline__ void ldsm_x4(uint32_t* r, uint32_t addr) {
    asm volatile("ldmatrix.sync.aligned.m8n8.x4.shared.b16 {%0,%1,%2,%3}, [%4];"
                 : "=r"(r[0]), "=r"(r[1]), "=r"(r[2]), "=r"(r[3]) : "r"(addr));
}

__device__ __forceinline__ void cp16(uint32_t dst, const void* src) {
    asm volatile("cp.async.cg.shared.global [%0], [%1], 16;"
                 :: "r"(dst), "l"(src) : "memory");
}
#define CP_COMMIT() asm volatile("cp.async.commit_group;" ::: "memory")
#define CP_WAIT0()  asm volatile("cp.async.wait_group 0;" ::: "memory")

__device__ __forceinline__ uint32_t bf2pack(__nv_bfloat16 a, __nv_bfloat16 b) {
    __nv_bfloat162 v = {a, b};
    return *reinterpret_cast<uint32_t*>(&v);
}

// Tile stride: 72 bf16 per row (144 B, conflict-staggered, 16B aligned)
#define TSTR 72

// ---------------------------------------------------------------------------
// Batched fp32 -> bf16 hi/lo split: z selects input, writes slot z
// ---------------------------------------------------------------------------
__global__ void __launch_bounds__(256) split3_kernel(
    const float* __restrict__ i0, const float* __restrict__ i1,
    const float* __restrict__ i2)
{
    const int z = blockIdx.y;
    const float* in = (z == 0) ? i0 : (z == 1) ? i1 : i2;
    __nv_bfloat16* hi = g_a1 + (size_t)z * MD;
    __nv_bfloat16* lo = g_a2 + (size_t)z * MD;

    const int i = blockIdx.x * 256 + threadIdx.x;
    const float4 v = reinterpret_cast<const float4*>(in)[i];
    __nv_bfloat16 h0 = __float2bfloat16(v.x);
    __nv_bfloat16 h1 = __float2bfloat16(v.y);
    __nv_bfloat16 h2 = __float2bfloat16(v.z);
    __nv_bfloat16 h3 = __float2bfloat16(v.w);
    __nv_bfloat162 H0 = {h0, h1}, H1 = {h2, h3};
    __nv_bfloat162 L0 = {__float2bfloat16(v.x - __bfloat162float(h0)),
                         __float2bfloat16(v.y - __bfloat162float(h1))};
    __nv_bfloat162 L1 = {__float2bfloat16(v.z - __bfloat162float(h2)),
                         __float2bfloat16(v.w - __bfloat162float(h3))};
    reinterpret_cast<__nv_bfloat162*>(hi)[i * 2]     = H0;
    reinterpret_cast<__nv_bfloat162*>(hi)[i * 2 + 1] = H1;
    reinterpret_cast<__nv_bfloat162*>(lo)[i * 2]     = L0;
    reinterpret_cast<__nv_bfloat162*>(lo)[i * 2 + 1] = L1;
}

// ---------------------------------------------------------------------------
// Batched weight transpose + split: z selects W, writes slot z
// ---------------------------------------------------------------------------
__global__ void __launch_bounds__(256) wt3_kernel(
    const float* __restrict__ W0, const float* __restrict__ W1,
    const float* __restrict__ W2)
{
    __shared__ float vs[64][65];
    const int z = blockIdx.z;
    const float* W = (z == 0) ? W0 : (z == 1) ? W1 : W2;
    __nv_bfloat16* wt1 = g_wt1 + (size_t)z * DD;
    __nv_bfloat16* wt2 = g_wt2 + (size_t)z * DD;
    const int k0 = blockIdx.y * 64;
    const int n0 = blockIdx.x * 64;
    const int t  = threadIdx.x;

    for (int i = t; i < 64 * 16; i += 256) {
        const int r = i >> 4, c = i & 15;
        const float4 v = *reinterpret_cast<const float4*>(
            W + (size_t)(k0 + r) * D_SZ + n0 + c * 4);
        vs[r][c * 4 + 0] = v.x; vs[r][c * 4 + 1] = v.y;
        vs[r][c * 4 + 2] = v.z; vs[r][c * 4 + 3] = v.w;
    }
    __syncthreads();

    for (int i = t; i < 64 * 64; i += 256) {
        const int n = i >> 6, k = i & 63;
        const float x = vs[k][n];
        const __nv_bfloat16 h = __float2bfloat16(x);
        const __nv_bfloat16 l = __float2bfloat16(x - __bfloat162float(h));
        const size_t o = (size_t)(n0 + n) * D_SZ + k0 + k;
        wt1[o] = h;
        wt2[o] = l;
    }
}

// ---------------------------------------------------------------------------
// GEMM core: bf16x3, single-buffer cp.async, 2 CTAs/SM (cross-CTA overlap).
// ---------------------------------------------------------------------------
#define A1B 0
#define A2B (128 * TSTR * 2)
#define W1B (2 * 128 * TSTR * 2)
#define W2B (3 * 128 * TSTR * 2)
#define GEMM_SMEM (4 * 128 * TSTR * 2)        // 73728

__device__ __forceinline__ void gemm_core(
    const __nv_bfloat16* a1, const __nv_bfloat16* a2,
    const __nv_bfloat16* wt1, const __nv_bfloat16* wt2,
    const float* bias, float* outf, __nv_bfloat16* outh,
    __nv_bfloat16* outl, int mode, int m0, int n0, char* smc)
{
    const int t = threadIdx.x;
    const int lane = t & 31, wid = t >> 5;
    const int wq = wid & 3, wk = wid >> 2;
    const uint32_t sb = smem_u32(smc);

    float acc[2][8][4] = {};

    for (int ck = 0; ck < 16; ck++) {
        const int j0 = ck * 64;
#pragma unroll
        for (int ii = 0; ii < 4; ii++) {
            const int i = t + ii * 256;
            const int r = i >> 3, c = i & 7;
            const uint32_t off = (uint32_t)(r * TSTR + c * 8) * 2;
            const size_t ga = (size_t)(m0 + r) * D_SZ + j0 + c * 8;
            const size_t gw = (size_t)(n0 + r) * D_SZ + j0 + c * 8;
            cp16(sb + A1B + off, a1 + ga);
            cp16(sb + A2B + off, a2 + ga);
            cp16(sb + W1B + off, wt1 + gw);
            cp16(sb + W2B + off, wt2 + gw);
        }
        CP_COMMIT();
        CP_WAIT0();
        __syncthreads();

#pragma unroll
        for (int ks = 0; ks < 4; ks++) {
            const int kc = ks * 16;
            uint32_t ah[2][4], al[2][4];
#pragma unroll
            for (int mi = 0; mi < 2; mi++) {
                const int row = wq * 32 + mi * 16 + (lane & 15);
                const int col = kc + ((lane >> 4) << 3);
                ldsm_x4(ah[mi], sb + A1B + (uint32_t)(row * TSTR + col) * 2);
                ldsm_x4(al[mi], sb + A2B + (uint32_t)(row * TSTR + col) * 2);
            }
#pragma unroll
            for (int np = 0; np < 4; np++) {
                uint32_t bh4[4], bl4[4];
                const int row = wk * 64 + np * 16 + (lane & 7) + ((lane >> 4) & 1) * 8;
                const int col = kc + ((lane >> 3) & 1) * 8;
                ldsm_x4(bh4, sb + W1B + (uint32_t)(row * TSTR + col) * 2);
                ldsm_x4(bl4, sb + W2B + (uint32_t)(row * TSTR + col) * 2);
#pragma unroll
                for (int mi = 0; mi < 2; mi++) {
                    mma_bf16(acc[mi][np * 2],     ah[mi], bh4);
                    mma_bf16(acc[mi][np * 2],     ah[mi], bl4);
                    mma_bf16(acc[mi][np * 2],     al[mi], bh4);
                    mma_bf16(acc[mi][np * 2 + 1], ah[mi], bh4 + 2);
                    mma_bf16(acc[mi][np * 2 + 1], ah[mi], bl4 + 2);
                    mma_bf16(acc[mi][np * 2 + 1], al[mi], bh4 + 2);
                }
            }
        }
        __syncthreads();
    }

    const int g  = lane >> 2;
    const int tg = lane & 3;
#pragma unroll
    for (int mi = 0; mi < 2; mi++) {
#pragma unroll
        for (int ni = 0; ni < 8; ni++) {
            const int col = n0 + wk * 64 + ni * 8 + tg * 2;
            const float2 bb2 = *reinterpret_cast<const float2*>(bias + col);
            const int m = m0 + wq * 32 + mi * 16 + g;
            float2 r0 = make_float2(acc[mi][ni][0] + bb2.x, acc[mi][ni][1] + bb2.y);
            float2 r1 = make_float2(acc[mi][ni][2] + bb2.x, acc[mi][ni][3] + bb2.y);
            if (mode == 0) {
                *reinterpret_cast<float2*>(outf + (size_t)m * D_SZ + col) = r0;
                *reinterpret_cast<float2*>(outf + (size_t)(m + 8) * D_SZ + col) = r1;
            } else {
                const int h  = col >> 6;
                const int dk = col & 63;
                const int b0 = m >> 11, s0 = m & 2047;
                const int b1 = (m + 8) >> 11, s1 = (m + 8) & 2047;
                const size_t o0 = (((size_t)(b0 * H_SZ + h) * S_SZ + s0) * DK_SZ) + dk;
                const size_t o1 = (((size_t)(b1 * H_SZ + h) * S_SZ + s1) * DK_SZ) + dk;
                if (mode == 2) {
                    *reinterpret_cast<float2*>(outf + o0) = r0;
                    *reinterpret_cast<float2*>(outf + o1) = r1;
                } else {
                    const __nv_bfloat16 h00 = __float2bfloat16(r0.x);
                    const __nv_bfloat16 h01 = __float2bfloat16(r0.y);
                    const __nv_bfloat16 h10 = __float2bfloat16(r1.x);
                    const __nv_bfloat16 h11 = __float2bfloat16(r1.y);
                    *reinterpret_cast<uint32_t*>(outh + o0) = bf2pack(h00, h01);
                    *reinterpret_cast<uint32_t*>(outh + o1) = bf2pack(h10, h11);
                    *reinterpret_cast<uint32_t*>(outl + o0) = bf2pack(
                        __float2bfloat16(r0.x - __bfloat162float(h00)),
                        __float2bfloat16(r0.y - __bfloat162float(h01)));
                    *reinterpret_cast<uint32_t*>(outl + o1) = bf2pack(
                        __float2bfloat16(r1.x - __bfloat162float(h10)),
                        __float2bfloat16(r1.y - __bfloat162float(h11)));
                }
            }
        }
    }
}

// Batched QKV projections: z=0 -> q1/q2 (mode 1), z=1 -> k1/k2, z=2 -> g_v (mode 2)
__global__ void __launch_bounds__(256, 2) gemm_proj(
    const float* __restrict__ bq, const float* __restrict__ bk,
    const float* __restrict__ bv)
{
    extern __shared__ __align__(16) char smc[];
    const int z = blockIdx.z;
    const __nv_bfloat16* a1 = g_a1 + (size_t)z * MD;
    const __nv_bfloat16* a2 = g_a2 + (size_t)z * MD;
    const __nv_bfloat16* w1 = g_wt1 + (size_t)z * DD;
    const __nv_bfloat16* w2 = g_wt2 + (size_t)z * DD;
    const float* bias = (z == 0) ? bq : (z == 1) ? bk : bv;
    float* outf = (z == 2) ? g_v : nullptr;
    __nv_bfloat16* outh = (z == 0) ? g_q1 : g_k1;
    __nv_bfloat16* outl = (z == 0) ? g_q2 : g_k2;
    const int mode = (z == 2) ? 2 : 1;
    gemm_core(a1, a2, w1, w2, bias, outf, outh, outl, mode,
              blockIdx.y * 128, blockIdx.x * 128, smc);
}

// Output projection: slot 0 buffers, fp32 row-major out
__global__ void __launch_bounds__(256, 2) gemm_out(
    const float* __restrict__ bo, float* __restrict__ outf)
{
    extern __shared__ __align__(16) char smc[];
    gemm_core(g_a1, g_a2, g_wt1, g_wt2, bo, outf, nullptr, nullptr, 0,
              blockIdx.y * 128, blockIdx.x * 128, smc);
}

// ---------------------------------------------------------------------------
// V transpose (hi only): g_v [bh][s][64] -> g_vt1 [bh][64][2048]
// ---------------------------------------------------------------------------
__global__ void __launch_bounds__(128) vt_kernel()
{
    __shared__ float vs[128][65];
    const int jt = blockIdx.x;
    const int bh = blockIdx.y;
    const int t  = threadIdx.x;
    const int j0 = jt * 128;

    const float4* src = reinterpret_cast<const float4*>(
        g_v + ((size_t)bh * S_SZ + j0) * DK_SZ);
    for (int i = t; i < 128 * 16; i += 128) {
        const int r = i >> 4, c = i & 15;
        const float4 v = src[i];
        vs[r][c * 4 + 0] = v.x; vs[r][c * 4 + 1] = v.y;
        vs[r][c * 4 + 2] = v.z; vs[r][c * 4 + 3] = v.w;
    }
    __syncthreads();

    for (int i = t; i < 64 * 128; i += 128) {
        const int j = i & 127;
        const int d = i >> 7;
        g_vt1[((size_t)bh * 64 + d) * S_SZ + j0 + j] = __float2bfloat16(vs[j][d]);
    }
}

// ---------------------------------------------------------------------------
// Score kernel: masked scaled scores -> sbuf (x4 K-operand ldsm, 2 CTA/SM)
// ---------------------------------------------------------------------------
#define SQ_H 0
#define SQ_L (128 * TSTR)
#define SK_H (2 * 128 * TSTR)
#define SK_L (3 * 128 * TSTR)
#define SCORE_SMEM (4 * 128 * TSTR * 2)       // 73728 B

__global__ void __launch_bounds__(256, 2) score_kernel(
    const int* __restrict__ mask, float* __restrict__ sbuf)
{
    extern __shared__ __align__(16) __nv_bfloat16 sm[];
    const int t = threadIdx.x;
    const int lane = t & 31, wid = t >> 5;
    const int wq = wid & 3, wk = wid >> 2;
    const int q0 = blockIdx.x * 128, k0 = blockIdx.y * 128;
    const int bh = blockIdx.z, b = bh >> 4;

    {
        const uint4* q1 = reinterpret_cast<const uint4*>(
            g_q1 + ((size_t)bh * S_SZ + q0) * DK_SZ);
        const uint4* q2 = reinterpret_cast<const uint4*>(
            g_q2 + ((size_t)bh * S_SZ + q0) * DK_SZ);
        const uint4* k1 = reinterpret_cast<const uint4*>(
            g_k1 + ((size_t)bh * S_SZ + k0) * DK_SZ);
        const uint4* k2 = reinterpret_cast<const uint4*>(
            g_k2 + ((size_t)bh * S_SZ + k0) * DK_SZ);
        for (int i = t; i < 1024; i += 256) {
            const int r = i >> 3, c = i & 7;
            const int off = r * TSTR + c * 8;
            *reinterpret_cast<uint4*>(
                reinterpret_cast<char*>(sm) + (size_t)(SQ_H + off) * 2) = q1[i];
            *reinterpret_cast<uint4*>(
                reinterpret_cast<char*>(sm) + (size_t)(SQ_L + off) * 2) = q2[i];
            *reinterpret_cast<uint4*>(
                reinterpret_cast<char*>(sm) + (size_t)(SK_H + off) * 2) = k1[i];
            *reinterpret_cast<uint4*>(
                reinterpret_cast<char*>(sm) + (size_t)(SK_L + off) * 2) = k2[i];
        }
    }
    __syncthreads();

    const uint32_t sb = smem_u32(sm);
    float acc[2][8][4] = {};

#pragma unroll
    for (int ks = 0; ks < 4; ks++) {
        const int kc = ks * 16;
        uint32_t ah[2][4], al[2][4];
#pragma unroll
        for (int mi = 0; mi < 2; mi++) {
            const int row = wq * 32 + mi * 16 + (lane & 15);
            const int col = kc + ((lane >> 4) << 3);
            ldsm_x4(ah[mi], sb + (uint32_t)(SQ_H + row * TSTR + col) * 2);
            ldsm_x4(al[mi], sb + (uint32_t)(SQ_L + row * TSTR + col) * 2);
        }
#pragma unroll
        for (int np = 0; np < 4; np++) {
            uint32_t bh4[4], bl4[4];
            const int row = wk * 64 + np * 16 + (lane & 7) + ((lane >> 4) & 1) * 8;
            const int col = kc + ((lane >> 3) & 1) * 8;
            ldsm_x4(bh4, sb + (uint32_t)(SK_H + row * TSTR + col) * 2);
            ldsm_x4(bl4, sb + (uint32_t)(SK_L + row * TSTR + col) * 2);
#pragma unroll
            for (int mi = 0; mi < 2; mi++) {
                mma_bf16(acc[mi][np * 2],     ah[mi], bh4);
                mma_bf16(acc[mi][np * 2],     ah[mi], bl4);
                mma_bf16(acc[mi][np * 2],     al[mi], bh4);
                mma_bf16(acc[mi][np * 2 + 1], ah[mi], bh4 + 2);
                mma_bf16(acc[mi][np * 2 + 1], ah[mi], bl4 + 2);
                mma_bf16(acc[mi][np * 2 + 1], al[mi], bh4 + 2);
            }
        }
    }

    const int g  = lane >> 2;
    const int tg = lane & 3;
#pragma unroll
    for (int mi = 0; mi < 2; mi++) {
#pragma unroll
        for (int ni = 0; ni < 8; ni++) {
            const int q = q0 + wq * 32 + mi * 16 + g;
            const int k = k0 + wk * 64 + ni * 8 + tg * 2;
            const int2 m0 = *reinterpret_cast<const int2*>(
                mask + ((size_t)b * S_SZ + q) * S_SZ + k);
            const int2 m1 = *reinterpret_cast<const int2*>(
                mask + ((size_t)b * S_SZ + q + 8) * S_SZ + k);
            float2 s0, s1;
            s0.x = m0.x ? -1e9f : acc[mi][ni][0] * 0.125f;
            s0.y = m0.y ? -1e9f : acc[mi][ni][1] * 0.125f;
            s1.x = m1.x ? -1e9f : acc[mi][ni][2] * 0.125f;
            s1.y = m1.y ? -1e9f : acc[mi][ni][3] * 0.125f;
            *reinterpret_cast<float2*>(
                sbuf + ((size_t)bh * S_SZ + q) * S_SZ + k) = s0;
            *reinterpret_cast<float2*>(
                sbuf + ((size_t)bh * S_SZ + q + 8) * S_SZ + k) = s1;
        }
    }
}

// ---------------------------------------------------------------------------
// Softmax (in place over rows of 2048)
// ---------------------------------------------------------------------------
__global__ void __launch_bounds__(256) softmax_kernel(float* __restrict__ buf)
{
    __shared__ float red[8];
    const size_t row = blockIdx.x;
    const int t = threadIdx.x;
    float4* p4 = reinterpret_cast<float4*>(buf + row * S_SZ);

    float4 v0 = p4[t], v1 = p4[t + 256];
    float mx = fmaxf(fmaxf(fmaxf(v0.x, v0.y), fmaxf(v0.z, v0.w)),
                     fmaxf(fmaxf(v1.x, v1.y), fmaxf(v1.z, v1.w)));
#pragma unroll
    for (int o = 16; o; o >>= 1) mx = fmaxf(mx, __shfl_xor_sync(0xffffffffu, mx, o));
    if ((t & 31) == 0) red[t >> 5] = mx;
    __syncthreads();
    mx = fmaxf(fmaxf(fmaxf(red[0], red[1]), fmaxf(red[2], red[3])),
               fmaxf(fmaxf(red[4], red[5]), fmaxf(red[6], red[7])));
    __syncthreads();

    v0.x = __expf(v0.x - mx); v0.y = __expf(v0.y - mx);
    v0.z = __expf(v0.z - mx); v0.w = __expf(v0.w - mx);
    v1.x = __expf(v1.x - mx); v1.y = __expf(v1.y - mx);
    v1.z = __expf(v1.z - mx); v1.w = __expf(v1.w - mx);
    float sum = v0.x + v0.y + v0.z + v0.w + v1.x + v1.y + v1.z + v1.w;
#pragma unroll
    for (int o = 16; o; o >>= 1) sum += __shfl_xor_sync(0xffffffffu, sum, o);
    if ((t & 31) == 0) red[t >> 5] = sum;
    __syncthreads();
    const float inv = 1.f / (red[0] + red[1] + red[2] + red[3] +
                             red[4] + red[5] + red[6] + red[7]);

    v0.x *= inv; v0.y *= inv; v0.z *= inv; v0.w *= inv;
    v1.x *= inv; v1.y *= inv; v1.z *= inv; v1.w *= inv;
    p4[t] = v0;
    p4[t + 256] = v1;
}

// ---------------------------------------------------------------------------
// Context kernel: 2-term PV (P hi/lo x V hi), x4 V-operand ldsm, 2 CTA/SM
// ---------------------------------------------------------------------------
#define CP_H 0
#define CP_L (128 * TSTR)
#define CV_H (2 * 128 * TSTR)
#define CTX_SMEM ((2 * 128 * TSTR + 64 * TSTR) * 2)   // 46080 B

__global__ void __launch_bounds__(256, 2) ctx_kernel(const float* __restrict__ probs)
{
    extern __shared__ __align__(16) __nv_bfloat16 sm[];
    const int t = threadIdx.x;
    const int lane = t & 31, wid = t >> 5;
    const int q0 = blockIdx.x * 128;
    const int bh = blockIdx.y, b = bh >> 4, h = bh & 15;
    const uint32_t sb = smem_u32(sm);

    const float* prow = probs + ((size_t)bh * S_SZ + q0) * S_SZ;
    const __nv_bfloat16* vt1 = g_vt1 + (size_t)bh * 64 * S_SZ;

    float acc[8][4] = {};

    for (int ch = 0; ch < 32; ch++) {
        const int j0 = ch * 64;
        __syncthreads();
        for (int i = t; i < 2048; i += 256) {
            const int r = i >> 4, c = i & 15;
            const float4 v = *reinterpret_cast<const float4*>(
                prow + (size_t)r * S_SZ + j0 + c * 4);
            const __nv_bfloat16 h0 = __float2bfloat16(v.x);
            const __nv_bfloat16 h1 = __float2bfloat16(v.y);
            const __nv_bfloat16 h2 = __float2bfloat16(v.z);
            const __nv_bfloat16 h3 = __float2bfloat16(v.w);
            const uint2 hp = make_uint2(bf2pack(h0, h1), bf2pack(h2, h3));
            const uint2 lp = make_uint2(
                bf2pack(__float2bfloat16(v.x - __bfloat162float(h0)),
                        __float2bfloat16(v.y - __bfloat162float(h1))),
                bf2pack(__float2bfloat16(v.z - __bfloat162float(h2)),
                        __float2bfloat16(v.w - __bfloat162float(h3))));
            const int off = r * TSTR + c * 4;
            *reinterpret_cast<uint2*>(
                reinterpret_cast<char*>(sm) + (size_t)(CP_H + off) * 2) = hp;
            *reinterpret_cast<uint2*>(
                reinterpret_cast<char*>(sm) + (size_t)(CP_L + off) * 2) = lp;
        }
        for (int i = t; i < 512; i += 256) {
            const int r = i >> 3, c = i & 7;
            const int off = r * TSTR + c * 8;
            *reinterpret_cast<uint4*>(
                reinterpret_cast<char*>(sm) + (size_t)(CV_H + off) * 2) =
                *reinterpret_cast<const uint4*>(vt1 + (size_t)r * S_SZ + j0 + c * 8);
        }
        __syncthreads();

#pragma unroll
        for (int ks = 0; ks < 4; ks++) {
            const int kc = ks * 16;
            uint32_t ah[4], al[4];
            {
                const int row = wid * 16 + (lane & 15);
                const int col = kc + ((lane >> 4) << 3);
                ldsm_x4(ah, sb + (uint32_t)(CP_H + row * TSTR + col) * 2);
                ldsm_x4(al, sb + (uint32_t)(CP_L + row * TSTR + col) * 2);
            }
#pragma unroll
            for (int np = 0; np < 4; np++) {
                uint32_t bh4[4];
                const int row = np * 16 + (lane & 7) + ((lane >> 4) & 1) * 8;
                const int col = kc + ((lane >> 3) & 1) * 8;
                ldsm_x4(bh4, sb + (uint32_t)(CV_H + row * TSTR + col) * 2);
                mma_bf16(acc[np * 2],     ah, bh4);
                mma_bf16(acc[np * 2],     al, bh4);
                mma_bf16(acc[np * 2 + 1], ah, bh4 + 2);
                mma_bf16(acc[np * 2 + 1], al, bh4 + 2);
            }
        }
    }

    const int g  = lane >> 2;
    const int tg = lane & 3;
#pragma unroll
    for (int ni = 0; ni < 8; ni++) {
        const int q = q0 + wid * 16 + g;
        const int d = ni * 8 + tg * 2;
        *reinterpret_cast<float2*>(
            g_ctx + ((size_t)(b * S_SZ + q)) * D_SZ + h * DK_SZ + d) =
            make_float2(acc[ni][0], acc[ni][1]);
        *reinterpret_cast<float2*>(
            g_ctx + ((size_t)(b * S_SZ + q + 8)) * D_SZ + h * DK_SZ + d) =
            make_float2(acc[ni][2], acc[ni][3]);
    }
}

// ---------------------------------------------------------------------------
// Residual + LayerNorm
// ---------------------------------------------------------------------------
__global__ void __launch_bounds__(256) ln_kernel(
    const float* __restrict__ resid, const float* __restrict__ gamma,
    const float* __restrict__ beta, float* __restrict__ out)
{
    __shared__ float rs[8], rq[8];
    const int row = blockIdx.x;
    const int t = threadIdx.x;

    const float4 a = reinterpret_cast<const float4*>(g_o + (size_t)row * D_SZ)[t];
    const float4 r = reinterpret_cast<const float4*>(resid + (size_t)row * D_SZ)[t];
    const float4 v = make_float4(a.x + r.x, a.y + r.y, a.z + r.z, a.w + r.w);

    float s  = v.x + v.y + v.z + v.w;
    float sq = v.x * v.x + v.y * v.y + v.z * v.z + v.w * v.w;
#pragma unroll
    for (int o = 16; o; o >>= 1) {
        s  += __shfl_xor_sync(0xffffffffu, s, o);
        sq += __shfl_xor_sync(0xffffffffu, sq, o);
    }
    if ((t & 31) == 0) { rs[t >> 5] = s; rq[t >> 5] = sq; }
    __syncthreads();
    float S = 0.f, SQ = 0.f;
#pragma unroll
    for (int i = 0; i < 8; i++) { S += rs[i]; SQ += rq[i]; }
    const float mu  = S * (1.f / D_SZ);
    const float var = SQ * (1.f / D_SZ) - mu * mu;
    const float rstd = rsqrtf(var + 1e-5f);

    const float4 g  = reinterpret_cast<const float4*>(gamma)[t];
    const float4 be = reinterpret_cast<const float4*>(beta)[t];
    reinterpret_cast<float4*>(out + (size_t)row * D_SZ)[t] =
        make_float4((v.x - mu) * rstd * g.x + be.x,
                    (v.y - mu) * rstd * g.y + be.y,
                    (v.z - mu) * rstd * g.z + be.z,
                    (v.w - mu) * rstd * g.w + be.w);
}

// ---------------------------------------------------------------------------
// kernel_launch
// ---------------------------------------------------------------------------
extern "C" void kernel_launch(void* const* d_in, const int* in_sizes, int n_in,
                              void* d_out, int out_size)
{
    const float* Q  = (const float*)d_in[0];
    const float* K  = (const float*)d_in[1];
    const float* V  = (const float*)d_in[2];
    const int*   mask = (const int*)d_in[3];
    const float* Wq = (const float*)d_in[4];
    const float* bq = (const float*)d_in[5];
    const float* Wk = (const float*)d_in[6];
    const float* bk = (const float*)d_in[7];
    const float* Wv = (const float*)d_in[8];
    const float* bv = (const float*)d_in[9];
    const float* Wo = (const float*)d_in[10];
    const float* bo = (const float*)d_in[11];
    const float* gamma = (const float*)d_in[12];
    const float* beta  = (const float*)d_in[13];

    float *ctx, *op, *scp;
    cudaGetSymbolAddress((void**)&ctx, g_ctx);
    cudaGetSymbolAddress((void**)&op,  g_o);
    cudaGetSymbolAddress((void**)&scp, g_sc);

    float* outp = (float*)d_out;
    float* sbuf = scp;
    if ((long long)out_size >= (long long)OUT_ELEMS + (long long)ATTN_ELEMS)
        sbuf = outp + OUT_ELEMS;   // probs land directly in the attn output

    cudaFuncSetAttribute(score_kernel,
        cudaFuncAttributeMaxDynamicSharedMemorySize, SCORE_SMEM);
    cudaFuncSetAttribute(ctx_kernel,
        cudaFuncAttributeMaxDynamicSharedMemorySize, CTX_SMEM);
    cudaFuncSetAttribute(gemm_proj,
        cudaFuncAttributeMaxDynamicSharedMemorySize, GEMM_SMEM);
    cudaFuncSetAttribute(gemm_out,
        cudaFuncAttributeMaxDynamicSharedMemorySize, GEMM_SMEM);

    // QKV projections, batched across z
    split3_kernel<<<dim3(M_SZ * D_SZ / 1024, 3), 256>>>(Q, K, V);
    wt3_kernel<<<dim3(16, 16, 3), 256>>>(Wq, Wk, Wv);
    gemm_proj<<<dim3(8, 32, 3), 256, GEMM_SMEM>>>(bq, bk, bv);
    vt_kernel<<<dim3(16, BH_SZ), 128>>>();

    // attention
    score_kernel<<<dim3(16, 16, BH_SZ), 256, SCORE_SMEM>>>(mask, sbuf);
    softmax_kernel<<<BH_SZ * S_SZ, 256>>>(sbuf);
    ctx_kernel<<<dim3(16, BH_SZ), 256, CTX_SMEM>>>(sbuf);

    // output projection (slot 0) + LN
    split3_kernel<<<dim3(M_SZ * D_SZ / 1024, 1), 256>>>(ctx, ctx, ctx);
    wt3_kernel<<<dim3(16, 16, 1), 256>>>(Wo, Wo, Wo);
    gemm_out<<<dim3(8, 32), 256, GEMM_SMEM>>>(bo, op);

    ln_kernel<<<M_SZ, 256>>>(Q, gamma, beta, outp);
}

// round 13
// speedup vs baseline: 1.2990x; 1.0079x over previous
#include <cuda_runtime.h>
#include <cuda_bf16.h>
#include <cstdint>

// ---------------------------------------------------------------------------
// Problem constants
// ---------------------------------------------------------------------------
#define B_SZ 2
#define S_SZ 2048
#define D_SZ 1024
#define H_SZ 16
#define DK_SZ 64
#define BH_SZ (B_SZ * H_SZ)                   // 32
#define M_SZ (B_SZ * S_SZ)                    // 4096
#define OUT_ELEMS (B_SZ * S_SZ * D_SZ)        // 4,194,304
#define ATTN_ELEMS (134217728)                // B*H*S*S
#define MD ((size_t)M_SZ * D_SZ)
#define DD ((size_t)D_SZ * D_SZ)

// ---------------------------------------------------------------------------
// Scratch
// ---------------------------------------------------------------------------
__device__ float g_v[M_SZ * D_SZ];            // v proj fp32 [bh,s,dv]
__device__ float g_o[M_SZ * D_SZ];
__device__ __nv_bfloat16 g_a1[3 * M_SZ * D_SZ];   // activation splits (3 slots)
__device__ __nv_bfloat16 g_a2[3 * M_SZ * D_SZ];
__device__ __nv_bfloat16 g_wt1[4 * D_SZ * D_SZ];  // weight^T splits (4 slots)
__device__ __nv_bfloat16 g_wt2[4 * D_SZ * D_SZ];
__device__ __nv_bfloat16 g_q1[M_SZ * D_SZ];   // q/k proj bf16 hi/lo [bh,s,dk]
__device__ __nv_bfloat16 g_q2[M_SZ * D_SZ];
__device__ __nv_bfloat16 g_k1[M_SZ * D_SZ];
__device__ __nv_bfloat16 g_k2[M_SZ * D_SZ];
__device__ __nv_bfloat16 g_vt1[M_SZ * D_SZ];  // V transposed hi: [bh][d][s]
__device__ float g_sc[ATTN_ELEMS];            // score/prob scratch (if !write_attn)

// ---------------------------------------------------------------------------
// Warp MMA helpers (sm_80+ features only)
// ---------------------------------------------------------------------------
__device__ __forceinline__ uint32_t smem_u32(const void* p) {
    uint32_t a;
    asm("{ .reg .u64 t; cvta.to.shared.u64 t, %1; cvt.u32.u64 %0, t; }"
        : "=r"(a) : "l"(p));
    return a;
}

__device__ __forceinline__ void mma_bf16(float* c, const uint32_t* a,
                                         const uint32_t* b) {
    asm volatile(
        "mma.sync.aligned.m16n8k16.row.col.f32.bf16.bf16.f32 "
        "{%0,%1,%2,%3}, {%4,%5,%6,%7}, {%8,%9}, {%0,%1,%2,%3};"
        : "+f"(c[0]), "+f"(c[1]), "+f"(c[2]), "+f"(c[3])
        : "r"(a[0]), "r"(a[1]), "r"(a[2]), "r"(a[3]),
          "r"(b[0]), "r"(b[1]));
}

__device__ __forceinline__ void ldsm_x4(uint32_t* r, uint32_t addr) {
    asm volatile("ldmatrix.sync.aligned.m8n8.x4.shared.b16 {%0,%1,%2,%3}, [%4];"
                 : "=r"(r[0]), "=r"(r[1]), "=r"(r[2]), "=r"(r[3]) : "r"(addr));
}

__device__ __forceinline__ void cp16(uint32_t dst, const void* src) {
    asm volatile("cp.async.cg.shared.global [%0], [%1], 16;"
                 :: "r"(dst), "l"(src) : "memory");
}
#define CP_COMMIT() asm volatile("cp.async.commit_group;" ::: "memory")
#define CP_WAIT0()  asm volatile("cp.async.wait_group 0;" ::: "memory")

__device__ __forceinline__ uint32_t bf2pack(__nv_bfloat16 a, __nv_bfloat16 b) {
    __nv_bfloat162 v = {a, b};
    return *reinterpret_cast<uint32_t*>(&v);
}

// Tile stride: 72 bf16 per row (144 B, conflict-staggered, 16B aligned)
#define TSTR 72

// ---------------------------------------------------------------------------
// Batched fp32 -> bf16 hi/lo split: z selects input, writes slot z
// ---------------------------------------------------------------------------
__global__ void __launch_bounds__(256) split3_kernel(
    const float* __restrict__ i0, const float* __restrict__ i1,
    const float* __restrict__ i2)
{
    const int z = blockIdx.y;
    const float* in = (z == 0) ? i0 : (z == 1) ? i1 : i2;
    __nv_bfloat16* hi = g_a1 + (size_t)z * MD;
    __nv_bfloat16* lo = g_a2 + (size_t)z * MD;

    const int i = blockIdx.x * 256 + threadIdx.x;
    const float4 v = reinterpret_cast<const float4*>(in)[i];
    __nv_bfloat16 h0 = __float2bfloat16(v.x);
    __nv_bfloat16 h1 = __float2bfloat16(v.y);
    __nv_bfloat16 h2 = __float2bfloat16(v.z);
    __nv_bfloat16 h3 = __float2bfloat16(v.w);
    __nv_bfloat162 H0 = {h0, h1}, H1 = {h2, h3};
    __nv_bfloat162 L0 = {__float2bfloat16(v.x - __bfloat162float(h0)),
                         __float2bfloat16(v.y - __bfloat162float(h1))};
    __nv_bfloat162 L1 = {__float2bfloat16(v.z - __bfloat162float(h2)),
                         __float2bfloat16(v.w - __bfloat162float(h3))};
    reinterpret_cast<__nv_bfloat162*>(hi)[i * 2]     = H0;
    reinterpret_cast<__nv_bfloat162*>(hi)[i * 2 + 1] = H1;
    reinterpret_cast<__nv_bfloat162*>(lo)[i * 2]     = L0;
    reinterpret_cast<__nv_bfloat162*>(lo)[i * 2 + 1] = L1;
}

// ---------------------------------------------------------------------------
// Batched weight transpose + split (all 4 weights): z selects W, writes slot z
// ---------------------------------------------------------------------------
__global__ void __launch_bounds__(256) wt4_kernel(
    const float* __restrict__ W0, const float* __restrict__ W1,
    const float* __restrict__ W2, const float* __restrict__ W3)
{
    __shared__ float vs[64][65];
    const int z = blockIdx.z;
    const float* W = (z == 0) ? W0 : (z == 1) ? W1 : (z == 2) ? W2 : W3;
    __nv_bfloat16* wt1 = g_wt1 + (size_t)z * DD;
    __nv_bfloat16* wt2 = g_wt2 + (size_t)z * DD;
    const int k0 = blockIdx.y * 64;
    const int n0 = blockIdx.x * 64;
    const int t  = threadIdx.x;

    for (int i = t; i < 64 * 16; i += 256) {
        const int r = i >> 4, c = i & 15;
        const float4 v = *reinterpret_cast<const float4*>(
            W + (size_t)(k0 + r) * D_SZ + n0 + c * 4);
        vs[r][c * 4 + 0] = v.x; vs[r][c * 4 + 1] = v.y;
        vs[r][c * 4 + 2] = v.z; vs[r][c * 4 + 3] = v.w;
    }
    __syncthreads();

    for (int i = t; i < 64 * 64; i += 256) {
        const int n = i >> 6, k = i & 63;
        const float x = vs[k][n];
        const __nv_bfloat16 h = __float2bfloat16(x);
        const __nv_bfloat16 l = __float2bfloat16(x - __bfloat162float(h));
        const size_t o = (size_t)(n0 + n) * D_SZ + k0 + k;
        wt1[o] = h;
        wt2[o] = l;
    }
}

// ---------------------------------------------------------------------------
// GEMM core: bf16x3, single-buffer cp.async, 2 CTAs/SM (cross-CTA overlap).
// ---------------------------------------------------------------------------
#define A1B 0
#define A2B (128 * TSTR * 2)
#define W1B (2 * 128 * TSTR * 2)
#define W2B (3 * 128 * TSTR * 2)
#define GEMM_SMEM (4 * 128 * TSTR * 2)        // 73728

__device__ __forceinline__ void gemm_core(
    const __nv_bfloat16* a1, const __nv_bfloat16* a2,
    const __nv_bfloat16* wt1, const __nv_bfloat16* wt2,
    const float* bias, float* outf, __nv_bfloat16* outh,
    __nv_bfloat16* outl, int mode, int m0, int n0, char* smc)
{
    const int t = threadIdx.x;
    const int lane = t & 31, wid = t >> 5;
    const int wq = wid & 3, wk = wid >> 2;
    const uint32_t sb = smem_u32(smc);

    float acc[2][8][4] = {};

    for (int ck = 0; ck < 16; ck++) {
        const int j0 = ck * 64;
#pragma unroll
        for (int ii = 0; ii < 4; ii++) {
            const int i = t + ii * 256;
            const int r = i >> 3, c = i & 7;
            const uint32_t off = (uint32_t)(r * TSTR + c * 8) * 2;
            const size_t ga = (size_t)(m0 + r) * D_SZ + j0 + c * 8;
            const size_t gw = (size_t)(n0 + r) * D_SZ + j0 + c * 8;
            cp16(sb + A1B + off, a1 + ga);
            cp16(sb + A2B + off, a2 + ga);
            cp16(sb + W1B + off, wt1 + gw);
            cp16(sb + W2B + off, wt2 + gw);
        }
        CP_COMMIT();
        CP_WAIT0();
        __syncthreads();

#pragma unroll
        for (int ks = 0; ks < 4; ks++) {
            const int kc = ks * 16;
            uint32_t ah[2][4], al[2][4];
#pragma unroll
            for (int mi = 0; mi < 2; mi++) {
                const int row = wq * 32 + mi * 16 + (lane & 15);
                const int col = kc + ((lane >> 4) << 3);
                ldsm_x4(ah[mi], sb + A1B + (uint32_t)(row * TSTR + col) * 2);
                ldsm_x4(al[mi], sb + A2B + (uint32_t)(row * TSTR + col) * 2);
            }
#pragma unroll
            for (int np = 0; np < 4; np++) {
                uint32_t bh4[4], bl4[4];
                const int row = wk * 64 + np * 16 + (lane & 7) + ((lane >> 4) & 1) * 8;
                const int col = kc + ((lane >> 3) & 1) * 8;
                ldsm_x4(bh4, sb + W1B + (uint32_t)(row * TSTR + col) * 2);
                ldsm_x4(bl4, sb + W2B + (uint32_t)(row * TSTR + col) * 2);
#pragma unroll
                for (int mi = 0; mi < 2; mi++) {
                    mma_bf16(acc[mi][np * 2],     ah[mi], bh4);
                    mma_bf16(acc[mi][np * 2],     ah[mi], bl4);
                    mma_bf16(acc[mi][np * 2],     al[mi], bh4);
                    mma_bf16(acc[mi][np * 2 + 1], ah[mi], bh4 + 2);
                    mma_bf16(acc[mi][np * 2 + 1], ah[mi], bl4 + 2);
                    mma_bf16(acc[mi][np * 2 + 1], al[mi], bh4 + 2);
                }
            }
        }
        __syncthreads();
    }

    const int g  = lane >> 2;
    const int tg = lane & 3;
#pragma unroll
    for (int mi = 0; mi < 2; mi++) {
#pragma unroll
        for (int ni = 0; ni < 8; ni++) {
            const int col = n0 + wk * 64 + ni * 8 + tg * 2;
            const float2 bb2 = *reinterpret_cast<const float2*>(bias + col);
            const int m = m0 + wq * 32 + mi * 16 + g;
            float2 r0 = make_float2(acc[mi][ni][0] + bb2.x, acc[mi][ni][1] + bb2.y);
            float2 r1 = make_float2(acc[mi][ni][2] + bb2.x, acc[mi][ni][3] + bb2.y);
            if (mode == 0) {
                *reinterpret_cast<float2*>(outf + (size_t)m * D_SZ + col) = r0;
                *reinterpret_cast<float2*>(outf + (size_t)(m + 8) * D_SZ + col) = r1;
            } else {
                const int h  = col >> 6;
                const int dk = col & 63;
                const int b0 = m >> 11, s0 = m & 2047;
                const int b1 = (m + 8) >> 11, s1 = (m + 8) & 2047;
                const size_t o0 = (((size_t)(b0 * H_SZ + h) * S_SZ + s0) * DK_SZ) + dk;
                const size_t o1 = (((size_t)(b1 * H_SZ + h) * S_SZ + s1) * DK_SZ) + dk;
                if (mode == 2) {
                    *reinterpret_cast<float2*>(outf + o0) = r0;
                    *reinterpret_cast<float2*>(outf + o1) = r1;
                } else {
                    const __nv_bfloat16 h00 = __float2bfloat16(r0.x);
                    const __nv_bfloat16 h01 = __float2bfloat16(r0.y);
                    const __nv_bfloat16 h10 = __float2bfloat16(r1.x);
                    const __nv_bfloat16 h11 = __float2bfloat16(r1.y);
                    *reinterpret_cast<uint32_t*>(outh + o0) = bf2pack(h00, h01);
                    *reinterpret_cast<uint32_t*>(outh + o1) = bf2pack(h10, h11);
                    *reinterpret_cast<uint32_t*>(outl + o0) = bf2pack(
                        __float2bfloat16(r0.x - __bfloat162float(h00)),
                        __float2bfloat16(r0.y - __bfloat162float(h01)));
                    *reinterpret_cast<uint32_t*>(outl + o1) = bf2pack(
                        __float2bfloat16(r1.x - __bfloat162float(h10)),
                        __float2bfloat16(r1.y - __bfloat162float(h11)));
                }
            }
        }
    }
}

// Batched QKV projections: z=0 -> q1/q2 (mode 1), z=1 -> k1/k2, z=2 -> g_v (mode 2)
__global__ void __launch_bounds__(256, 2) gemm_proj(
    const float* __restrict__ bq, const float* __restrict__ bk,
    const float* __restrict__ bv)
{
    extern __shared__ __align__(16) char smc[];
    const int z = blockIdx.z;
    const __nv_bfloat16* a1 = g_a1 + (size_t)z * MD;
    const __nv_bfloat16* a2 = g_a2 + (size_t)z * MD;
    const __nv_bfloat16* w1 = g_wt1 + (size_t)z * DD;
    const __nv_bfloat16* w2 = g_wt2 + (size_t)z * DD;
    const float* bias = (z == 0) ? bq : (z == 1) ? bk : bv;
    float* outf = (z == 2) ? g_v : nullptr;
    __nv_bfloat16* outh = (z == 0) ? g_q1 : g_k1;
    __nv_bfloat16* outl = (z == 0) ? g_q2 : g_k2;
    const int mode = (z == 2) ? 2 : 1;
    gemm_core(a1, a2, w1, w2, bias, outf, outh, outl, mode,
              blockIdx.y * 128, blockIdx.x * 128, smc);
}

// Output projection: activations in slot 0 (written by ctx), Wo in slot 3
__global__ void __launch_bounds__(256, 2) gemm_out(
    const float* __restrict__ bo, float* __restrict__ outf)
{
    extern __shared__ __align__(16) char smc[];
    gemm_core(g_a1, g_a2, g_wt1 + 3 * DD, g_wt2 + 3 * DD, bo, outf,
              nullptr, nullptr, 0, blockIdx.y * 128, blockIdx.x * 128, smc);
}

// ---------------------------------------------------------------------------
// V transpose (hi only): g_v [bh][s][64] -> g_vt1 [bh][64][2048]
// ---------------------------------------------------------------------------
__global__ void __launch_bounds__(128) vt_kernel()
{
    __shared__ float vs[128][65];
    const int jt = blockIdx.x;
    const int bh = blockIdx.y;
    const int t  = threadIdx.x;
    const int j0 = jt * 128;

    const float4* src = reinterpret_cast<const float4*>(
        g_v + ((size_t)bh * S_SZ + j0) * DK_SZ);
    for (int i = t; i < 128 * 16; i += 128) {
        const int r = i >> 4, c = i & 15;
        const float4 v = src[i];
        vs[r][c * 4 + 0] = v.x; vs[r][c * 4 + 1] = v.y;
        vs[r][c * 4 + 2] = v.z; vs[r][c * 4 + 3] = v.w;
    }
    __syncthreads();

    for (int i = t; i < 64 * 128; i += 128) {
        const int j = i & 127;
        const int d = i >> 7;
        g_vt1[((size_t)bh * 64 + d) * S_SZ + j0 + j] = __float2bfloat16(vs[j][d]);
    }
}

// ---------------------------------------------------------------------------
// Score kernel: masked scaled scores -> sbuf (x4 K-operand ldsm, 2 CTA/SM)
// ---------------------------------------------------------------------------
#define SQ_H 0
#define SQ_L (128 * TSTR)
#define SK_H (2 * 128 * TSTR)
#define SK_L (3 * 128 * TSTR)
#define SCORE_SMEM (4 * 128 * TSTR * 2)       // 73728 B

__global__ void __launch_bounds__(256, 2) score_kernel(
    const int* __restrict__ mask, float* __restrict__ sbuf)
{
    extern __shared__ __align__(16) __nv_bfloat16 sm[];
    const int t = threadIdx.x;
    const int lane = t & 31, wid = t >> 5;
    const int wq = wid & 3, wk = wid >> 2;
    const int q0 = blockIdx.x * 128, k0 = blockIdx.y * 128;
    const int bh = blockIdx.z, b = bh >> 4;

    {
        const uint4* q1 = reinterpret_cast<const uint4*>(
            g_q1 + ((size_t)bh * S_SZ + q0) * DK_SZ);
        const uint4* q2 = reinterpret_cast<const uint4*>(
            g_q2 + ((size_t)bh * S_SZ + q0) * DK_SZ);
        const uint4* k1 = reinterpret_cast<const uint4*>(
            g_k1 + ((size_t)bh * S_SZ + k0) * DK_SZ);
        const uint4* k2 = reinterpret_cast<const uint4*>(
            g_k2 + ((size_t)bh * S_SZ + k0) * DK_SZ);
        for (int i = t; i < 1024; i += 256) {
            const int r = i >> 3, c = i & 7;
            const int off = r * TSTR + c * 8;
            *reinterpret_cast<uint4*>(
                reinterpret_cast<char*>(sm) + (size_t)(SQ_H + off) * 2) = q1[i];
            *reinterpret_cast<uint4*>(
                reinterpret_cast<char*>(sm) + (size_t)(SQ_L + off) * 2) = q2[i];
            *reinterpret_cast<uint4*>(
                reinterpret_cast<char*>(sm) + (size_t)(SK_H + off) * 2) = k1[i];
            *reinterpret_cast<uint4*>(
                reinterpret_cast<char*>(sm) + (size_t)(SK_L + off) * 2) = k2[i];
        }
    }
    __syncthreads();

    const uint32_t sb = smem_u32(sm);
    float acc[2][8][4] = {};

#pragma unroll
    for (int ks = 0; ks < 4; ks++) {
        const int kc = ks * 16;
        uint32_t ah[2][4], al[2][4];
#pragma unroll
        for (int mi = 0; mi < 2; mi++) {
            const int row = wq * 32 + mi * 16 + (lane & 15);
            const int col = kc + ((lane >> 4) << 3);
            ldsm_x4(ah[mi], sb + (uint32_t)(SQ_H + row * TSTR + col) * 2);
            ldsm_x4(al[mi], sb + (uint32_t)(SQ_L + row * TSTR + col) * 2);
        }
#pragma unroll
        for (int np = 0; np < 4; np++) {
            uint32_t bh4[4], bl4[4];
            const int row = wk * 64 + np * 16 + (lane & 7) + ((lane >> 4) & 1) * 8;
            const int col = kc + ((lane >> 3) & 1) * 8;
            ldsm_x4(bh4, sb + (uint32_t)(SK_H + row * TSTR + col) * 2);
            ldsm_x4(bl4, sb + (uint32_t)(SK_L + row * TSTR + col) * 2);
#pragma unroll
            for (int mi = 0; mi < 2; mi++) {
                mma_bf16(acc[mi][np * 2],     ah[mi], bh4);
                mma_bf16(acc[mi][np * 2],     ah[mi], bl4);
                mma_bf16(acc[mi][np * 2],     al[mi], bh4);
                mma_bf16(acc[mi][np * 2 + 1], ah[mi], bh4 + 2);
                mma_bf16(acc[mi][np * 2 + 1], ah[mi], bl4 + 2);
                mma_bf16(acc[mi][np * 2 + 1], al[mi], bh4 + 2);
            }
        }
    }

    const int g  = lane >> 2;
    const int tg = lane & 3;
#pragma unroll
    for (int mi = 0; mi < 2; mi++) {
#pragma unroll
        for (int ni = 0; ni < 8; ni++) {
            const int q = q0 + wq * 32 + mi * 16 + g;
            const int k = k0 + wk * 64 + ni * 8 + tg * 2;
            const int2 m0 = *reinterpret_cast<const int2*>(
                mask + ((size_t)b * S_SZ + q) * S_SZ + k);
            const int2 m1 = *reinterpret_cast<const int2*>(
                mask + ((size_t)b * S_SZ + q + 8) * S_SZ + k);
            float2 s0, s1;
            s0.x = m0.x ? -1e9f : acc[mi][ni][0] * 0.125f;
            s0.y = m0.y ? -1e9f : acc[mi][ni][1] * 0.125f;
            s1.x = m1.x ? -1e9f : acc[mi][ni][2] * 0.125f;
            s1.y = m1.y ? -1e9f : acc[mi][ni][3] * 0.125f;
            *reinterpret_cast<float2*>(
                sbuf + ((size_t)bh * S_SZ + q) * S_SZ + k) = s0;
            *reinterpret_cast<float2*>(
                sbuf + ((size_t)bh * S_SZ + q + 8) * S_SZ + k) = s1;
        }
    }
}

// ---------------------------------------------------------------------------
// Softmax (in place over rows of 2048)
// ---------------------------------------------------------------------------
__global__ void __launch_bounds__(256) softmax_kernel(float* __restrict__ buf)
{
    __shared__ float red[8];
    const size_t row = blockIdx.x;
    const int t = threadIdx.x;
    float4* p4 = reinterpret_cast<float4*>(buf + row * S_SZ);

    float4 v0 = p4[t], v1 = p4[t + 256];
    float mx = fmaxf(fmaxf(fmaxf(v0.x, v0.y), fmaxf(v0.z, v0.w)),
                     fmaxf(fmaxf(v1.x, v1.y), fmaxf(v1.z, v1.w)));
#pragma unroll
    for (int o = 16; o; o >>= 1) mx = fmaxf(mx, __shfl_xor_sync(0xffffffffu, mx, o));
    if ((t & 31) == 0) red[t >> 5] = mx;
    __syncthreads();
    mx = fmaxf(fmaxf(fmaxf(red[0], red[1]), fmaxf(red[2], red[3])),
               fmaxf(fmaxf(red[4], red[5]), fmaxf(red[6], red[7])));
    __syncthreads();

    v0.x = __expf(v0.x - mx); v0.y = __expf(v0.y - mx);
    v0.z = __expf(v0.z - mx); v0.w = __expf(v0.w - mx);
    v1.x = __expf(v1.x - mx); v1.y = __expf(v1.y - mx);
    v1.z = __expf(v1.z - mx); v1.w = __expf(v1.w - mx);
    float sum = v0.x + v0.y + v0.z + v0.w + v1.x + v1.y + v1.z + v1.w;
#pragma unroll
    for (int o = 16; o; o >>= 1) sum += __shfl_xor_sync(0xffffffffu, sum, o);
    if ((t & 31) == 0) red[t >> 5] = sum;
    __syncthreads();
    const float inv = 1.f / (red[0] + red[1] + red[2] + red[3] +
                             red[4] + red[5] + red[6] + red[7]);

    v0.x *= inv; v0.y *= inv; v0.z *= inv; v0.w *= inv;
    v1.x *= inv; v1.y *= inv; v1.z *= inv; v1.w *= inv;
    p4[t] = v0;
    p4[t + 256] = v1;
}

// ---------------------------------------------------------------------------
// Context kernel: 2-term PV; epilogue writes bf16 hi/lo straight into the
// out-projection activation slot (g_a1/g_a2 slot 0, [m][1024] layout).
// ---------------------------------------------------------------------------
#define CP_H 0
#define CP_L (128 * TSTR)
#define CV_H (2 * 128 * TSTR)
#define CTX_SMEM ((2 * 128 * TSTR + 64 * TSTR) * 2)   // 46080 B

__global__ void __launch_bounds__(256, 2) ctx_kernel(const float* __restrict__ probs)
{
    extern __shared__ __align__(16) __nv_bfloat16 sm[];
    const int t = threadIdx.x;
    const int lane = t & 31, wid = t >> 5;
    const int q0 = blockIdx.x * 128;
    const int bh = blockIdx.y, b = bh >> 4, h = bh & 15;
    const uint32_t sb = smem_u32(sm);

    const float* prow = probs + ((size_t)bh * S_SZ + q0) * S_SZ;
    const __nv_bfloat16* vt1 = g_vt1 + (size_t)bh * 64 * S_SZ;

    float acc[8][4] = {};

    for (int ch = 0; ch < 32; ch++) {
        const int j0 = ch * 64;
        __syncthreads();
        for (int i = t; i < 2048; i += 256) {
            const int r = i >> 4, c = i & 15;
            const float4 v = *reinterpret_cast<const float4*>(
                prow + (size_t)r * S_SZ + j0 + c * 4);
            const __nv_bfloat16 h0 = __float2bfloat16(v.x);
            const __nv_bfloat16 h1 = __float2bfloat16(v.y);
            const __nv_bfloat16 h2 = __float2bfloat16(v.z);
            const __nv_bfloat16 h3 = __float2bfloat16(v.w);
            const uint2 hp = make_uint2(bf2pack(h0, h1), bf2pack(h2, h3));
            const uint2 lp = make_uint2(
                bf2pack(__float2bfloat16(v.x - __bfloat162float(h0)),
                        __float2bfloat16(v.y - __bfloat162float(h1))),
                bf2pack(__float2bfloat16(v.z - __bfloat162float(h2)),
                        __float2bfloat16(v.w - __bfloat162float(h3))));
            const int off = r * TSTR + c * 4;
            *reinterpret_cast<uint2*>(
                reinterpret_cast<char*>(sm) + (size_t)(CP_H + off) * 2) = hp;
            *reinterpret_cast<uint2*>(
                reinterpret_cast<char*>(sm) + (size_t)(CP_L + off) * 2) = lp;
        }
        for (int i = t; i < 512; i += 256) {
            const int r = i >> 3, c = i & 7;
            const int off = r * TSTR + c * 8;
            *reinterpret_cast<uint4*>(
                reinterpret_cast<char*>(sm) + (size_t)(CV_H + off) * 2) =
                *reinterpret_cast<const uint4*>(vt1 + (size_t)r * S_SZ + j0 + c * 8);
        }
        __syncthreads();

#pragma unroll
        for (int ks = 0; ks < 4; ks++) {
            const int kc = ks * 16;
            uint32_t ah[4], al[4];
            {
                const int row = wid * 16 + (lane & 15);
                const int col = kc + ((lane >> 4) << 3);
                ldsm_x4(ah, sb + (uint32_t)(CP_H + row * TSTR + col) * 2);
                ldsm_x4(al, sb + (uint32_t)(CP_L + row * TSTR + col) * 2);
            }
#pragma unroll
            for (int np = 0; np < 4; np++) {
                uint32_t bh4[4];
                const int row = np * 16 + (lane & 7) + ((lane >> 4) & 1) * 8;
                const int col = kc + ((lane >> 3) & 1) * 8;
                ldsm_x4(bh4, sb + (uint32_t)(CV_H + row * TSTR + col) * 2);
                mma_bf16(acc[np * 2],     ah, bh4);
                mma_bf16(acc[np * 2],     al, bh4);
                mma_bf16(acc[np * 2 + 1], ah, bh4 + 2);
                mma_bf16(acc[np * 2 + 1], al, bh4 + 2);
            }
        }
    }

    // epilogue: split ctx to bf16 hi/lo directly in GEMM-A layout
    const int g  = lane >> 2;
    const int tg = lane & 3;
#pragma unroll
    for (int ni = 0; ni < 8; ni++) {
        const int q = q0 + wid * 16 + g;
        const int d = ni * 8 + tg * 2;
        const size_t m0o = ((size_t)(b * S_SZ + q)) * D_SZ + h * DK_SZ + d;
        const size_t m1o = ((size_t)(b * S_SZ + q + 8)) * D_SZ + h * DK_SZ + d;
        const float2 r0 = make_float2(acc[ni][0], acc[ni][1]);
        const float2 r1 = make_float2(acc[ni][2], acc[ni][3]);
        const __nv_bfloat16 h00 = __float2bfloat16(r0.x);
        const __nv_bfloat16 h01 = __float2bfloat16(r0.y);
        const __nv_bfloat16 h10 = __float2bfloat16(r1.x);
        const __nv_bfloat16 h11 = __float2bfloat16(r1.y);
        *reinterpret_cast<uint32_t*>(g_a1 + m0o) = bf2pack(h00, h01);
        *reinterpret_cast<uint32_t*>(g_a1 + m1o) = bf2pack(h10, h11);
        *reinterpret_cast<uint32_t*>(g_a2 + m0o) = bf2pack(
            __float2bfloat16(r0.x - __bfloat162float(h00)),
            __float2bfloat16(r0.y - __bfloat162float(h01)));
        *reinterpret_cast<uint32_t*>(g_a2 + m1o) = bf2pack(
            __float2bfloat16(r1.x - __bfloat162float(h10)),
            __float2bfloat16(r1.y - __bfloat162float(h11)));
    }
}

// ---------------------------------------------------------------------------
// Residual + LayerNorm
// ---------------------------------------------------------------------------
__global__ void __launch_bounds__(256) ln_kernel(
    const float* __restrict__ resid, const float* __restrict__ gamma,
    const float* __restrict__ beta, float* __restrict__ out)
{
    __shared__ float rs[8], rq[8];
    const int row = blockIdx.x;
    const int t = threadIdx.x;

    const float4 a = reinterpret_cast<const float4*>(g_o + (size_t)row * D_SZ)[t];
    const float4 r = reinterpret_cast<const float4*>(resid + (size_t)row * D_SZ)[t];
    const float4 v = make_float4(a.x + r.x, a.y + r.y, a.z + r.z, a.w + r.w);

    float s  = v.x + v.y + v.z + v.w;
    float sq = v.x * v.x + v.y * v.y + v.z * v.z + v.w * v.w;
#pragma unroll
    for (int o = 16; o; o >>= 1) {
        s  += __shfl_xor_sync(0xffffffffu, s, o);
        sq += __shfl_xor_sync(0xffffffffu, sq, o);
    }
    if ((t & 31) == 0) { rs[t >> 5] = s; rq[t >> 5] = sq; }
    __syncthreads();
    float S = 0.f, SQ = 0.f;
#pragma unroll
    for (int i = 0; i < 8; i++) { S += rs[i]; SQ += rq[i]; }
    const float mu  = S * (1.f / D_SZ);
    const float var = SQ * (1.f / D_SZ) - mu * mu;
    const float rstd = rsqrtf(var + 1e-5f);

    const float4 g  = reinterpret_cast<const float4*>(gamma)[t];
    const float4 be = reinterpret_cast<const float4*>(beta)[t];
    reinterpret_cast<float4*>(out + (size_t)row * D_SZ)[t] =
        make_float4((v.x - mu) * rstd * g.x + be.x,
                    (v.y - mu) * rstd * g.y + be.y,
                    (v.z - mu) * rstd * g.z + be.z,
                    (v.w - mu) * rstd * g.w + be.w);
}

// ---------------------------------------------------------------------------
// kernel_launch
// ---------------------------------------------------------------------------
extern "C" void kernel_launch(void* const* d_in, const int* in_sizes, int n_in,
                              void* d_out, int out_size)
{
    const float* Q  = (const float*)d_in[0];
    const float* K  = (const float*)d_in[1];
    const float* V  = (const float*)d_in[2];
    const int*   mask = (const int*)d_in[3];
    const float* Wq = (const float*)d_in[4];
    const float* bq = (const float*)d_in[5];
    const float* Wk = (const float*)d_in[6];
    const float* bk = (const float*)d_in[7];
    const float* Wv = (const float*)d_in[8];
    const float* bv = (const float*)d_in[9];
    const float* Wo = (const float*)d_in[10];
    const float* bo = (const float*)d_in[11];
    const float* gamma = (const float*)d_in[12];
    const float* beta  = (const float*)d_in[13];

    float *op, *scp;
    cudaGetSymbolAddress((void**)&op,  g_o);
    cudaGetSymbolAddress((void**)&scp, g_sc);

    float* outp = (float*)d_out;
    float* sbuf = scp;
    if ((long long)out_size >= (long long)OUT_ELEMS + (long long)ATTN_ELEMS)
        sbuf = outp + OUT_ELEMS;   // probs land directly in the attn output

    cudaFuncSetAttribute(score_kernel,
        cudaFuncAttributeMaxDynamicSharedMemorySize, SCORE_SMEM);
    cudaFuncSetAttribute(ctx_kernel,
        cudaFuncAttributeMaxDynamicSharedMemorySize, CTX_SMEM);
    cudaFuncSetAttribute(gemm_proj,
        cudaFuncAttributeMaxDynamicSharedMemorySize, GEMM_SMEM);
    cudaFuncSetAttribute(gemm_out,
        cudaFuncAttributeMaxDynamicSharedMemorySize, GEMM_SMEM);

    // input splits + ALL four weight transposes (Wo off critical path)
    split3_kernel<<<dim3(M_SZ * D_SZ / 1024, 3), 256>>>(Q, K, V);
    wt4_kernel<<<dim3(16, 16, 4), 256>>>(Wq, Wk, Wv, Wo);

    // QKV projections (batched)
    gemm_proj<<<dim3(8, 32, 3), 256, GEMM_SMEM>>>(bq, bk, bv);
    vt_kernel<<<dim3(16, BH_SZ), 128>>>();

    // attention
    score_kernel<<<dim3(16, 16, BH_SZ), 256, SCORE_SMEM>>>(mask, sbuf);
    softmax_kernel<<<BH_SZ * S_SZ, 256>>>(sbuf);
    ctx_kernel<<<dim3(16, BH_SZ), 256, CTX_SMEM>>>(sbuf);   // writes a1/a2 slot 0

    // output projection + LN
    gemm_out<<<dim3(8, 32), 256, GEMM_SMEM>>>(bo, op);
    ln_kernel<<<M_SZ, 256>>>(Q, gamma, beta, outp);
}

// round 14
// speedup vs baseline: 1.3862x; 1.0671x over previous
#include <cuda_runtime.h>
#include <cuda_bf16.h>
#include <cstdint>

// ---------------------------------------------------------------------------
// Problem constants
// ---------------------------------------------------------------------------
#define B_SZ 2
#define S_SZ 2048
#define D_SZ 1024
#define H_SZ 16
#define DK_SZ 64
#define BH_SZ (B_SZ * H_SZ)                   // 32
#define M_SZ (B_SZ * S_SZ)                    // 4096
#define OUT_ELEMS (B_SZ * S_SZ * D_SZ)        // 4,194,304
#define ATTN_ELEMS (134217728)                // B*H*S*S
#define MD ((size_t)M_SZ * D_SZ)
#define DD ((size_t)D_SZ * D_SZ)

// ---------------------------------------------------------------------------
// Scratch
// ---------------------------------------------------------------------------
__device__ float g_v[M_SZ * D_SZ];            // v proj fp32 [bh,s,dv]
__device__ float g_o[M_SZ * D_SZ];
__device__ __nv_bfloat16 g_a1[3 * M_SZ * D_SZ];   // activation splits (3 slots)
__device__ __nv_bfloat16 g_a2[3 * M_SZ * D_SZ];
__device__ __nv_bfloat16 g_wt1[4 * D_SZ * D_SZ];  // weight^T splits (4 slots)
__device__ __nv_bfloat16 g_wt2[4 * D_SZ * D_SZ];
__device__ __nv_bfloat16 g_q1[M_SZ * D_SZ];   // q/k proj bf16 hi/lo [bh,s,dk]
__device__ __nv_bfloat16 g_q2[M_SZ * D_SZ];
__device__ __nv_bfloat16 g_k1[M_SZ * D_SZ];
__device__ __nv_bfloat16 g_k2[M_SZ * D_SZ];
__device__ __nv_bfloat16 g_vt1[M_SZ * D_SZ];  // V transposed hi: [bh][d][s]
__device__ float g_sc[ATTN_ELEMS];            // score/prob scratch (if !write_attn)

// ---------------------------------------------------------------------------
// Warp MMA helpers (sm_80+ features only)
// ---------------------------------------------------------------------------
__device__ __forceinline__ uint32_t smem_u32(const void* p) {
    uint32_t a;
    asm("{ .reg .u64 t; cvta.to.shared.u64 t, %1; cvt.u32.u64 %0, t; }"
        : "=r"(a) : "l"(p));
    return a;
}

__device__ __forceinline__ void mma_bf16(float* c, const uint32_t* a,
                                         const uint32_t* b) {
    asm volatile(
        "mma.sync.aligned.m16n8k16.row.col.f32.bf16.bf16.f32 "
        "{%0,%1,%2,%3}, {%4,%5,%6,%7}, {%8,%9}, {%0,%1,%2,%3};"
        : "+f"(c[0]), "+f"(c[1]), "+f"(c[2]), "+f"(c[3])
        : "r"(a[0]), "r"(a[1]), "r"(a[2]), "r"(a[3]),
          "r"(b[0]), "r"(b[1]));
}

__device__ __forceinline__ void ldsm_x4(uint32_t* r, uint32_t addr) {
    asm volatile("ldmatrix.sync.aligned.m8n8.x4.shared.b16 {%0,%1,%2,%3}, [%4];"
                 : "=r"(r[0]), "=r"(r[1]), "=r"(r[2]), "=r"(r[3]) : "r"(addr));
}

__device__ __forceinline__ void cp16(uint32_t dst, const void* src) {
    asm volatile("cp.async.cg.shared.global [%0], [%1], 16;"
                 :: "r"(dst), "l"(src) : "memory");
}
#define CP_COMMIT() asm volatile("cp.async.commit_group;" ::: "memory")
#define CP_WAIT0()  asm volatile("cp.async.wait_group 0;" ::: "memory")

__device__ __forceinline__ uint32_t bf2pack(__nv_bfloat16 a, __nv_bfloat16 b) {
    __nv_bfloat162 v = {a, b};
    return *reinterpret_cast<uint32_t*>(&v);
}

// Tile stride: 72 bf16 per row (144 B, conflict-staggered, 16B aligned)
#define TSTR 72

// ---------------------------------------------------------------------------
// Batched fp32 -> bf16 hi/lo split
// ---------------------------------------------------------------------------
__global__ void __launch_bounds__(256) split3_kernel(
    const float* __restrict__ i0, const float* __restrict__ i1,
    const float* __restrict__ i2)
{
    const int z = blockIdx.y;
    const float* in = (z == 0) ? i0 : (z == 1) ? i1 : i2;
    __nv_bfloat16* hi = g_a1 + (size_t)z * MD;
    __nv_bfloat16* lo = g_a2 + (size_t)z * MD;

    const int i = blockIdx.x * 256 + threadIdx.x;
    const float4 v = reinterpret_cast<const float4*>(in)[i];
    __nv_bfloat16 h0 = __float2bfloat16(v.x);
    __nv_bfloat16 h1 = __float2bfloat16(v.y);
    __nv_bfloat16 h2 = __float2bfloat16(v.z);
    __nv_bfloat16 h3 = __float2bfloat16(v.w);
    __nv_bfloat162 H0 = {h0, h1}, H1 = {h2, h3};
    __nv_bfloat162 L0 = {__float2bfloat16(v.x - __bfloat162float(h0)),
                         __float2bfloat16(v.y - __bfloat162float(h1))};
    __nv_bfloat162 L1 = {__float2bfloat16(v.z - __bfloat162float(h2)),
                         __float2bfloat16(v.w - __bfloat162float(h3))};
    reinterpret_cast<__nv_bfloat162*>(hi)[i * 2]     = H0;
    reinterpret_cast<__nv_bfloat162*>(hi)[i * 2 + 1] = H1;
    reinterpret_cast<__nv_bfloat162*>(lo)[i * 2]     = L0;
    reinterpret_cast<__nv_bfloat162*>(lo)[i * 2 + 1] = L1;
}

// ---------------------------------------------------------------------------
// Batched weight transpose + split (all 4 weights)
// ---------------------------------------------------------------------------
__global__ void __launch_bounds__(256) wt4_kernel(
    const float* __restrict__ W0, const float* __restrict__ W1,
    const float* __restrict__ W2, const float* __restrict__ W3)
{
    __shared__ float vs[64][65];
    const int z = blockIdx.z;
    const float* W = (z == 0) ? W0 : (z == 1) ? W1 : (z == 2) ? W2 : W3;
    __nv_bfloat16* wt1 = g_wt1 + (size_t)z * DD;
    __nv_bfloat16* wt2 = g_wt2 + (size_t)z * DD;
    const int k0 = blockIdx.y * 64;
    const int n0 = blockIdx.x * 64;
    const int t  = threadIdx.x;

    for (int i = t; i < 64 * 16; i += 256) {
        const int r = i >> 4, c = i & 15;
        const float4 v = *reinterpret_cast<const float4*>(
            W + (size_t)(k0 + r) * D_SZ + n0 + c * 4);
        vs[r][c * 4 + 0] = v.x; vs[r][c * 4 + 1] = v.y;
        vs[r][c * 4 + 2] = v.z; vs[r][c * 4 + 3] = v.w;
    }
    __syncthreads();

    for (int i = t; i < 64 * 64; i += 256) {
        const int n = i >> 6, k = i & 63;
        const float x = vs[k][n];
        const __nv_bfloat16 h = __float2bfloat16(x);
        const __nv_bfloat16 l = __float2bfloat16(x - __bfloat162float(h));
        const size_t o = (size_t)(n0 + n) * D_SZ + k0 + k;
        wt1[o] = h;
        wt2[o] = l;
    }
}

// ---------------------------------------------------------------------------
// GEMM core: single-buffer cp.async, 2 CTAs/SM.
// wt3 != 0: 3-term (ah*wh + ah*wl + al*wh); wt3 == 0: 2-term (ah*wh + al*wh)
// ---------------------------------------------------------------------------
#define A1B 0
#define A2B (128 * TSTR * 2)
#define W1B (2 * 128 * TSTR * 2)
#define W2B (3 * 128 * TSTR * 2)
#define GEMM_SMEM (4 * 128 * TSTR * 2)        // 73728

__device__ __forceinline__ void gemm_core(
    const __nv_bfloat16* a1, const __nv_bfloat16* a2,
    const __nv_bfloat16* wt1, const __nv_bfloat16* wt2,
    const float* bias, float* outf, __nv_bfloat16* outh,
    __nv_bfloat16* outl, int mode, int wt3, int m0, int n0, char* smc)
{
    const int t = threadIdx.x;
    const int lane = t & 31, wid = t >> 5;
    const int wq = wid & 3, wk = wid >> 2;
    const uint32_t sb = smem_u32(smc);

    float acc[2][8][4] = {};

    for (int ck = 0; ck < 16; ck++) {
        const int j0 = ck * 64;
#pragma unroll
        for (int ii = 0; ii < 4; ii++) {
            const int i = t + ii * 256;
            const int r = i >> 3, c = i & 7;
            const uint32_t off = (uint32_t)(r * TSTR + c * 8) * 2;
            const size_t ga = (size_t)(m0 + r) * D_SZ + j0 + c * 8;
            const size_t gw = (size_t)(n0 + r) * D_SZ + j0 + c * 8;
            cp16(sb + A1B + off, a1 + ga);
            cp16(sb + A2B + off, a2 + ga);
            cp16(sb + W1B + off, wt1 + gw);
            if (wt3) cp16(sb + W2B + off, wt2 + gw);
        }
        CP_COMMIT();
        CP_WAIT0();
        __syncthreads();

#pragma unroll
        for (int ks = 0; ks < 4; ks++) {
            const int kc = ks * 16;
            uint32_t ah[2][4], al[2][4];
#pragma unroll
            for (int mi = 0; mi < 2; mi++) {
                const int row = wq * 32 + mi * 16 + (lane & 15);
                const int col = kc + ((lane >> 4) << 3);
                ldsm_x4(ah[mi], sb + A1B + (uint32_t)(row * TSTR + col) * 2);
                ldsm_x4(al[mi], sb + A2B + (uint32_t)(row * TSTR + col) * 2);
            }
#pragma unroll
            for (int np = 0; np < 4; np++) {
                uint32_t bh4[4], bl4[4];
                const int row = wk * 64 + np * 16 + (lane & 7) + ((lane >> 4) & 1) * 8;
                const int col = kc + ((lane >> 3) & 1) * 8;
                ldsm_x4(bh4, sb + W1B + (uint32_t)(row * TSTR + col) * 2);
                if (wt3) ldsm_x4(bl4, sb + W2B + (uint32_t)(row * TSTR + col) * 2);
#pragma unroll
                for (int mi = 0; mi < 2; mi++) {
                    mma_bf16(acc[mi][np * 2],     ah[mi], bh4);
                    mma_bf16(acc[mi][np * 2],     al[mi], bh4);
                    mma_bf16(acc[mi][np * 2 + 1], ah[mi], bh4 + 2);
                    mma_bf16(acc[mi][np * 2 + 1], al[mi], bh4 + 2);
                    if (wt3) {
                        mma_bf16(acc[mi][np * 2],     ah[mi], bl4);
                        mma_bf16(acc[mi][np * 2 + 1], ah[mi], bl4 + 2);
                    }
                }
            }
        }
        __syncthreads();
    }

    const int g  = lane >> 2;
    const int tg = lane & 3;
#pragma unroll
    for (int mi = 0; mi < 2; mi++) {
#pragma unroll
        for (int ni = 0; ni < 8; ni++) {
            const int col = n0 + wk * 64 + ni * 8 + tg * 2;
            const float2 bb2 = *reinterpret_cast<const float2*>(bias + col);
            const int m = m0 + wq * 32 + mi * 16 + g;
            float2 r0 = make_float2(acc[mi][ni][0] + bb2.x, acc[mi][ni][1] + bb2.y);
            float2 r1 = make_float2(acc[mi][ni][2] + bb2.x, acc[mi][ni][3] + bb2.y);
            if (mode == 0) {
                *reinterpret_cast<float2*>(outf + (size_t)m * D_SZ + col) = r0;
                *reinterpret_cast<float2*>(outf + (size_t)(m + 8) * D_SZ + col) = r1;
            } else {
                const int h  = col >> 6;
                const int dk = col & 63;
                const int b0 = m >> 11, s0 = m & 2047;
                const int b1 = (m + 8) >> 11, s1 = (m + 8) & 2047;
                const size_t o0 = (((size_t)(b0 * H_SZ + h) * S_SZ + s0) * DK_SZ) + dk;
                const size_t o1 = (((size_t)(b1 * H_SZ + h) * S_SZ + s1) * DK_SZ) + dk;
                if (mode == 2) {
                    *reinterpret_cast<float2*>(outf + o0) = r0;
                    *reinterpret_cast<float2*>(outf + o1) = r1;
                } else {
                    const __nv_bfloat16 h00 = __float2bfloat16(r0.x);
                    const __nv_bfloat16 h01 = __float2bfloat16(r0.y);
                    const __nv_bfloat16 h10 = __float2bfloat16(r1.x);
                    const __nv_bfloat16 h11 = __float2bfloat16(r1.y);
                    *reinterpret_cast<uint32_t*>(outh + o0) = bf2pack(h00, h01);
                    *reinterpret_cast<uint32_t*>(outh + o1) = bf2pack(h10, h11);
                    *reinterpret_cast<uint32_t*>(outl + o0) = bf2pack(
                        __float2bfloat16(r0.x - __bfloat162float(h00)),
                        __float2bfloat16(r0.y - __bfloat162float(h01)));
                    *reinterpret_cast<uint32_t*>(outl + o1) = bf2pack(
                        __float2bfloat16(r1.x - __bfloat162float(h10)),
                        __float2bfloat16(r1.y - __bfloat162float(h11)));
                }
            }
        }
    }
}

// Batched QKV projections: z=0 q (3-term), z=1 k (3-term), z=2 v (2-term)
__global__ void __launch_bounds__(256, 2) gemm_proj(
    const float* __restrict__ bq, const float* __restrict__ bk,
    const float* __restrict__ bv)
{
    extern __shared__ __align__(16) char smc[];
    const int z = blockIdx.z;
    const __nv_bfloat16* a1 = g_a1 + (size_t)z * MD;
    const __nv_bfloat16* a2 = g_a2 + (size_t)z * MD;
    const __nv_bfloat16* w1 = g_wt1 + (size_t)z * DD;
    const __nv_bfloat16* w2 = g_wt2 + (size_t)z * DD;
    const float* bias = (z == 0) ? bq : (z == 1) ? bk : bv;
    float* outf = (z == 2) ? g_v : nullptr;
    __nv_bfloat16* outh = (z == 0) ? g_q1 : g_k1;
    __nv_bfloat16* outl = (z == 0) ? g_q2 : g_k2;
    const int mode = (z == 2) ? 2 : 1;
    const int wt3 = (z == 2) ? 0 : 1;
    gemm_core(a1, a2, w1, w2, bias, outf, outh, outl, mode, wt3,
              blockIdx.y * 128, blockIdx.x * 128, smc);
}

// Output projection: 2-term, activations slot 0 (from ctx), Wo slot 3
__global__ void __launch_bounds__(256, 2) gemm_out(
    const float* __restrict__ bo, float* __restrict__ outf)
{
    extern __shared__ __align__(16) char smc[];
    gemm_core(g_a1, g_a2, g_wt1 + 3 * DD, g_wt2 + 3 * DD, bo, outf,
              nullptr, nullptr, 0, 0, blockIdx.y * 128, blockIdx.x * 128, smc);
}

// ---------------------------------------------------------------------------
// V transpose (hi only)
// ---------------------------------------------------------------------------
__global__ void __launch_bounds__(128) vt_kernel()
{
    __shared__ float vs[128][65];
    const int jt = blockIdx.x;
    const int bh = blockIdx.y;
    const int t  = threadIdx.x;
    const int j0 = jt * 128;

    const float4* src = reinterpret_cast<const float4*>(
        g_v + ((size_t)bh * S_SZ + j0) * DK_SZ);
    for (int i = t; i < 128 * 16; i += 128) {
        const int r = i >> 4, c = i & 15;
        const float4 v = src[i];
        vs[r][c * 4 + 0] = v.x; vs[r][c * 4 + 1] = v.y;
        vs[r][c * 4 + 2] = v.z; vs[r][c * 4 + 3] = v.w;
    }
    __syncthreads();

    for (int i = t; i < 64 * 128; i += 128) {
        const int j = i & 127;
        const int d = i >> 7;
        g_vt1[((size_t)bh * 64 + d) * S_SZ + j0 + j] = __float2bfloat16(vs[j][d]);
    }
}

// ---------------------------------------------------------------------------
// Score kernel: 3-term QK, masked scaled scores -> sbuf
// ---------------------------------------------------------------------------
#define SQ_H 0
#define SQ_L (128 * TSTR)
#define SK_H (2 * 128 * TSTR)
#define SK_L (3 * 128 * TSTR)
#define SCORE_SMEM (4 * 128 * TSTR * 2)       // 73728 B

__global__ void __launch_bounds__(256, 2) score_kernel(
    const int* __restrict__ mask, float* __restrict__ sbuf)
{
    extern __shared__ __align__(16) __nv_bfloat16 sm[];
    const int t = threadIdx.x;
    const int lane = t & 31, wid = t >> 5;
    const int wq = wid & 3, wk = wid >> 2;
    const int q0 = blockIdx.x * 128, k0 = blockIdx.y * 128;
    const int bh = blockIdx.z, b = bh >> 4;

    {
        const uint4* q1 = reinterpret_cast<const uint4*>(
            g_q1 + ((size_t)bh * S_SZ + q0) * DK_SZ);
        const uint4* q2 = reinterpret_cast<const uint4*>(
            g_q2 + ((size_t)bh * S_SZ + q0) * DK_SZ);
        const uint4* k1 = reinterpret_cast<const uint4*>(
            g_k1 + ((size_t)bh * S_SZ + k0) * DK_SZ);
        const uint4* k2 = reinterpret_cast<const uint4*>(
            g_k2 + ((size_t)bh * S_SZ + k0) * DK_SZ);
        for (int i = t; i < 1024; i += 256) {
            const int r = i >> 3, c = i & 7;
            const int off = r * TSTR + c * 8;
            *reinterpret_cast<uint4*>(
                reinterpret_cast<char*>(sm) + (size_t)(SQ_H + off) * 2) = q1[i];
            *reinterpret_cast<uint4*>(
                reinterpret_cast<char*>(sm) + (size_t)(SQ_L + off) * 2) = q2[i];
            *reinterpret_cast<uint4*>(
                reinterpret_cast<char*>(sm) + (size_t)(SK_H + off) * 2) = k1[i];
            *reinterpret_cast<uint4*>(
                reinterpret_cast<char*>(sm) + (size_t)(SK_L + off) * 2) = k2[i];
        }
    }
    __syncthreads();

    const uint32_t sb = smem_u32(sm);
    float acc[2][8][4] = {};

#pragma unroll
    for (int ks = 0; ks < 4; ks++) {
        const int kc = ks * 16;
        uint32_t ah[2][4], al[2][4];
#pragma unroll
        for (int mi = 0; mi < 2; mi++) {
            const int row = wq * 32 + mi * 16 + (lane & 15);
            const int col = kc + ((lane >> 4) << 3);
            ldsm_x4(ah[mi], sb + (uint32_t)(SQ_H + row * TSTR + col) * 2);
            ldsm_x4(al[mi], sb + (uint32_t)(SQ_L + row * TSTR + col) * 2);
        }
#pragma unroll
        for (int np = 0; np < 4; np++) {
            uint32_t bh4[4], bl4[4];
            const int row = wk * 64 + np * 16 + (lane & 7) + ((lane >> 4) & 1) * 8;
            const int col = kc + ((lane >> 3) & 1) * 8;
            ldsm_x4(bh4, sb + (uint32_t)(SK_H + row * TSTR + col) * 2);
            ldsm_x4(bl4, sb + (uint32_t)(SK_L + row * TSTR + col) * 2);
#pragma unroll
            for (int mi = 0; mi < 2; mi++) {
                mma_bf16(acc[mi][np * 2],     ah[mi], bh4);
                mma_bf16(acc[mi][np * 2],     ah[mi], bl4);
                mma_bf16(acc[mi][np * 2],     al[mi], bh4);
                mma_bf16(acc[mi][np * 2 + 1], ah[mi], bh4 + 2);
                mma_bf16(acc[mi][np * 2 + 1], ah[mi], bl4 + 2);
                mma_bf16(acc[mi][np * 2 + 1], al[mi], bh4 + 2);
            }
        }
    }

    const int g  = lane >> 2;
    const int tg = lane & 3;
#pragma unroll
    for (int mi = 0; mi < 2; mi++) {
#pragma unroll
        for (int ni = 0; ni < 8; ni++) {
            const int q = q0 + wq * 32 + mi * 16 + g;
            const int k = k0 + wk * 64 + ni * 8 + tg * 2;
            const int2 m0 = *reinterpret_cast<const int2*>(
                mask + ((size_t)b * S_SZ + q) * S_SZ + k);
            const int2 m1 = *reinterpret_cast<const int2*>(
                mask + ((size_t)b * S_SZ + q + 8) * S_SZ + k);
            float2 s0, s1;
            s0.x = m0.x ? -1e9f : acc[mi][ni][0] * 0.125f;
            s0.y = m0.y ? -1e9f : acc[mi][ni][1] * 0.125f;
            s1.x = m1.x ? -1e9f : acc[mi][ni][2] * 0.125f;
            s1.y = m1.y ? -1e9f : acc[mi][ni][3] * 0.125f;
            *reinterpret_cast<float2*>(
                sbuf + ((size_t)bh * S_SZ + q) * S_SZ + k) = s0;
            *reinterpret_cast<float2*>(
                sbuf + ((size_t)bh * S_SZ + q + 8) * S_SZ + k) = s1;
        }
    }
}

// ---------------------------------------------------------------------------
// Softmax (in place over rows of 2048)
// ---------------------------------------------------------------------------
__global__ void __launch_bounds__(256) softmax_kernel(float* __restrict__ buf)
{
    __shared__ float red[8];
    const size_t row = blockIdx.x;
    const int t = threadIdx.x;
    float4* p4 = reinterpret_cast<float4*>(buf + row * S_SZ);

    float4 v0 = p4[t], v1 = p4[t + 256];
    float mx = fmaxf(fmaxf(fmaxf(v0.x, v0.y), fmaxf(v0.z, v0.w)),
                     fmaxf(fmaxf(v1.x, v1.y), fmaxf(v1.z, v1.w)));
#pragma unroll
    for (int o = 16; o; o >>= 1) mx = fmaxf(mx, __shfl_xor_sync(0xffffffffu, mx, o));
    if ((t & 31) == 0) red[t >> 5] = mx;
    __syncthreads();
    mx = fmaxf(fmaxf(fmaxf(red[0], red[1]), fmaxf(red[2], red[3])),
               fmaxf(fmaxf(red[4], red[5]), fmaxf(red[6], red[7])));
    __syncthreads();

    v0.x = __expf(v0.x - mx); v0.y = __expf(v0.y - mx);
    v0.z = __expf(v0.z - mx); v0.w = __expf(v0.w - mx);
    v1.x = __expf(v1.x - mx); v1.y = __expf(v1.y - mx);
    v1.z = __expf(v1.z - mx); v1.w = __expf(v1.w - mx);
    float sum = v0.x + v0.y + v0.z + v0.w + v1.x + v1.y + v1.z + v1.w;
#pragma unroll
    for (int o = 16; o; o >>= 1) sum += __shfl_xor_sync(0xffffffffu, sum, o);
    if ((t & 31) == 0) red[t >> 5] = sum;
    __syncthreads();
    const float inv = 1.f / (red[0] + red[1] + red[2] + red[3] +
                             red[4] + red[5] + red[6] + red[7]);

    v0.x *= inv; v0.y *= inv; v0.z *= inv; v0.w *= inv;
    v1.x *= inv; v1.y *= inv; v1.z *= inv; v1.w *= inv;
    p4[t] = v0;
    p4[t + 256] = v1;
}

// ---------------------------------------------------------------------------
// Context kernel: 1-term PV (P hi x V hi); epilogue writes bf16 hi/lo into
// the out-projection activation slot (g_a1/g_a2 slot 0).
// ---------------------------------------------------------------------------
#define CP_H 0
#define CV_H (128 * TSTR)
#define CTX_SMEM ((128 * TSTR + 64 * TSTR) * 2)   // 27648 B

__global__ void __launch_bounds__(256, 2) ctx_kernel(const float* __restrict__ probs)
{
    extern __shared__ __align__(16) __nv_bfloat16 sm[];
    const int t = threadIdx.x;
    const int lane = t & 31, wid = t >> 5;
    const int q0 = blockIdx.x * 128;
    const int bh = blockIdx.y, b = bh >> 4, h = bh & 15;
    const uint32_t sb = smem_u32(sm);

    const float* prow = probs + ((size_t)bh * S_SZ + q0) * S_SZ;
    const __nv_bfloat16* vt1 = g_vt1 + (size_t)bh * 64 * S_SZ;

    float acc[8][4] = {};

    for (int ch = 0; ch < 32; ch++) {
        const int j0 = ch * 64;
        __syncthreads();
        for (int i = t; i < 2048; i += 256) {
            const int r = i >> 4, c = i & 15;
            const float4 v = *reinterpret_cast<const float4*>(
                prow + (size_t)r * S_SZ + j0 + c * 4);
            const uint2 hp = make_uint2(
                bf2pack(__float2bfloat16(v.x), __float2bfloat16(v.y)),
                bf2pack(__float2bfloat16(v.z), __float2bfloat16(v.w)));
            *reinterpret_cast<uint2*>(
                reinterpret_cast<char*>(sm) + (size_t)(CP_H + r * TSTR + c * 4) * 2) = hp;
        }
        for (int i = t; i < 512; i += 256) {
            const int r = i >> 3, c = i & 7;
            const int off = r * TSTR + c * 8;
            *reinterpret_cast<uint4*>(
                reinterpret_cast<char*>(sm) + (size_t)(CV_H + off) * 2) =
                *reinterpret_cast<const uint4*>(vt1 + (size_t)r * S_SZ + j0 + c * 8);
        }
        __syncthreads();

#pragma unroll
        for (int ks = 0; ks < 4; ks++) {
            const int kc = ks * 16;
            uint32_t ah[4];
            {
                const int row = wid * 16 + (lane & 15);
                const int col = kc + ((lane >> 4) << 3);
                ldsm_x4(ah, sb + (uint32_t)(CP_H + row * TSTR + col) * 2);
            }
#pragma unroll
            for (int np = 0; np < 4; np++) {
                uint32_t bh4[4];
                const int row = np * 16 + (lane & 7) + ((lane >> 4) & 1) * 8;
                const int col = kc + ((lane >> 3) & 1) * 8;
                ldsm_x4(bh4, sb + (uint32_t)(CV_H + row * TSTR + col) * 2);
                mma_bf16(acc[np * 2],     ah, bh4);
                mma_bf16(acc[np * 2 + 1], ah, bh4 + 2);
            }
        }
    }

    // epilogue: split ctx to bf16 hi/lo directly in GEMM-A layout
    const int g  = lane >> 2;
    const int tg = lane & 3;
#pragma unroll
    for (int ni = 0; ni < 8; ni++) {
        const int q = q0 + wid * 16 + g;
        const int d = ni * 8 + tg * 2;
        const size_t m0o = ((size_t)(b * S_SZ + q)) * D_SZ + h * DK_SZ + d;
        const size_t m1o = ((size_t)(b * S_SZ + q + 8)) * D_SZ + h * DK_SZ + d;
        const float2 r0 = make_float2(acc[ni][0], acc[ni][1]);
        const float2 r1 = make_float2(acc[ni][2], acc[ni][3]);
        const __nv_bfloat16 h00 = __float2bfloat16(r0.x);
        const __nv_bfloat16 h01 = __float2bfloat16(r0.y);
        const __nv_bfloat16 h10 = __float2bfloat16(r1.x);
        const __nv_bfloat16 h11 = __float2bfloat16(r1.y);
        *reinterpret_cast<uint32_t*>(g_a1 + m0o) = bf2pack(h00, h01);
        *reinterpret_cast<uint32_t*>(g_a1 + m1o) = bf2pack(h10, h11);
        *reinterpret_cast<uint32_t*>(g_a2 + m0o) = bf2pack(
            __float2bfloat16(r0.x - __bfloat162float(h00)),
            __float2bfloat16(r0.y - __bfloat162float(h01)));
        *reinterpret_cast<uint32_t*>(g_a2 + m1o) = bf2pack(
            __float2bfloat16(r1.x - __bfloat162float(h10)),
            __float2bfloat16(r1.y - __bfloat162float(h11)));
    }
}

// ---------------------------------------------------------------------------
// Residual + LayerNorm
// ---------------------------------------------------------------------------
__global__ void __launch_bounds__(256) ln_kernel(
    const float* __restrict__ resid, const float* __restrict__ gamma,
    const float* __restrict__ beta, float* __restrict__ out)
{
    __shared__ float rs[8], rq[8];
    const int row = blockIdx.x;
    const int t = threadIdx.x;

    const float4 a = reinterpret_cast<const float4*>(g_o + (size_t)row * D_SZ)[t];
    const float4 r = reinterpret_cast<const float4*>(resid + (size_t)row * D_SZ)[t];
    const float4 v = make_float4(a.x + r.x, a.y + r.y, a.z + r.z, a.w + r.w);

    float s  = v.x + v.y + v.z + v.w;
    float sq = v.x * v.x + v.y * v.y + v.z * v.z + v.w * v.w;
#pragma unroll
    for (int o = 16; o; o >>= 1) {
        s  += __shfl_xor_sync(0xffffffffu, s, o);
        sq += __shfl_xor_sync(0xffffffffu, sq, o);
    }
    if ((t & 31) == 0) { rs[t >> 5] = s; rq[t >> 5] = sq; }
    __syncthreads();
    float S = 0.f, SQ = 0.f;
#pragma unroll
    for (int i = 0; i < 8; i++) { S += rs[i]; SQ += rq[i]; }
    const float mu  = S * (1.f / D_SZ);
    const float var = SQ * (1.f / D_SZ) - mu * mu;
    const float rstd = rsqrtf(var + 1e-5f);

    const float4 g  = reinterpret_cast<const float4*>(gamma)[t];
    const float4 be = reinterpret_cast<const float4*>(beta)[t];
    reinterpret_cast<float4*>(out + (size_t)row * D_SZ)[t] =
        make_float4((v.x - mu) * rstd * g.x + be.x,
                    (v.y - mu) * rstd * g.y + be.y,
                    (v.z - mu) * rstd * g.z + be.z,
                    (v.w - mu) * rstd * g.w + be.w);
}

// ---------------------------------------------------------------------------
// kernel_launch
// ---------------------------------------------------------------------------
extern "C" void kernel_launch(void* const* d_in, const int* in_sizes, int n_in,
                              void* d_out, int out_size)
{
    const float* Q  = (const float*)d_in[0];
    const float* K  = (const float*)d_in[1];
    const float* V  = (const float*)d_in[2];
    const int*   mask = (const int*)d_in[3];
    const float* Wq = (const float*)d_in[4];
    const float* bq = (const float*)d_in[5];
    const float* Wk = (const float*)d_in[6];
    const float* bk = (const float*)d_in[7];
    const float* Wv = (const float*)d_in[8];
    const float* bv = (const float*)d_in[9];
    const float* Wo = (const float*)d_in[10];
    const float* bo = (const float*)d_in[11];
    const float* gamma = (const float*)d_in[12];
    const float* beta  = (const float*)d_in[13];

    float *op, *scp;
    cudaGetSymbolAddress((void**)&op,  g_o);
    cudaGetSymbolAddress((void**)&scp, g_sc);

    float* outp = (float*)d_out;
    float* sbuf = scp;
    if ((long long)out_size >= (long long)OUT_ELEMS + (long long)ATTN_ELEMS)
        sbuf = outp + OUT_ELEMS;   // probs land directly in the attn output

    cudaFuncSetAttribute(score_kernel,
        cudaFuncAttributeMaxDynamicSharedMemorySize, SCORE_SMEM);
    cudaFuncSetAttribute(ctx_kernel,
        cudaFuncAttributeMaxDynamicSharedMemorySize, CTX_SMEM);
    cudaFuncSetAttribute(gemm_proj,
        cudaFuncAttributeMaxDynamicSharedMemorySize, GEMM_SMEM);
    cudaFuncSetAttribute(gemm_out,
        cudaFuncAttributeMaxDynamicSharedMemorySize, GEMM_SMEM);

    // input splits + all four weight transposes
    split3_kernel<<<dim3(M_SZ * D_SZ / 1024, 3), 256>>>(Q, K, V);
    wt4_kernel<<<dim3(16, 16, 4), 256>>>(Wq, Wk, Wv, Wo);

    // QKV projections (batched; V is 2-term)
    gemm_proj<<<dim3(8, 32, 3), 256, GEMM_SMEM>>>(bq, bk, bv);
    vt_kernel<<<dim3(16, BH_SZ), 128>>>();

    // attention
    score_kernel<<<dim3(16, 16, BH_SZ), 256, SCORE_SMEM>>>(mask, sbuf);
    softmax_kernel<<<BH_SZ * S_SZ, 256>>>(sbuf);
    ctx_kernel<<<dim3(16, BH_SZ), 256, CTX_SMEM>>>(sbuf);   // writes a1/a2 slot 0

    // output projection (2-term) + LN
    gemm_out<<<dim3(8, 32), 256, GEMM_SMEM>>>(bo, op);
    ln_kernel<<<M_SZ, 256>>>(Q, gamma, beta, outp);
}

// round 15
// speedup vs baseline: 1.3988x; 1.0091x over previous
#include <cuda_runtime.h>
#include <cuda_bf16.h>
#include <cstdint>

// ---------------------------------------------------------------------------
// Problem constants
// ---------------------------------------------------------------------------
#define B_SZ 2
#define S_SZ 2048
#define D_SZ 1024
#define H_SZ 16
#define DK_SZ 64
#define BH_SZ (B_SZ * H_SZ)                   // 32
#define M_SZ (B_SZ * S_SZ)                    // 4096
#define OUT_ELEMS (B_SZ * S_SZ * D_SZ)        // 4,194,304
#define ATTN_ELEMS (134217728)                // B*H*S*S
#define MD ((size_t)M_SZ * D_SZ)
#define DD ((size_t)D_SZ * D_SZ)

// ---------------------------------------------------------------------------
// Scratch
// ---------------------------------------------------------------------------
__device__ float g_o[M_SZ * D_SZ];
__device__ __nv_bfloat16 g_a1[3 * M_SZ * D_SZ];   // activation splits (3 slots)
__device__ __nv_bfloat16 g_a2[3 * M_SZ * D_SZ];
__device__ __nv_bfloat16 g_wt1[4 * D_SZ * D_SZ];  // weight^T splits (4 slots)
__device__ __nv_bfloat16 g_wt2[4 * D_SZ * D_SZ];
__device__ __nv_bfloat16 g_q1[M_SZ * D_SZ];   // q/k proj bf16 hi/lo [bh,s,dk]
__device__ __nv_bfloat16 g_q2[M_SZ * D_SZ];
__device__ __nv_bfloat16 g_k1[M_SZ * D_SZ];
__device__ __nv_bfloat16 g_k2[M_SZ * D_SZ];
__device__ __nv_bfloat16 g_vt1[M_SZ * D_SZ];  // V transposed hi: [bh][d][s]
__device__ float g_sc[ATTN_ELEMS];            // score/prob scratch (if !write_attn)

// ---------------------------------------------------------------------------
// Warp MMA helpers (sm_80+ features only)
// ---------------------------------------------------------------------------
__device__ __forceinline__ uint32_t smem_u32(const void* p) {
    uint32_t a;
    asm("{ .reg .u64 t; cvta.to.shared.u64 t, %1; cvt.u32.u64 %0, t; }"
        : "=r"(a) : "l"(p));
    return a;
}

__device__ __forceinline__ void mma_bf16(float* c, const uint32_t* a,
                                         const uint32_t* b) {
    asm volatile(
        "mma.sync.aligned.m16n8k16.row.col.f32.bf16.bf16.f32 "
        "{%0,%1,%2,%3}, {%4,%5,%6,%7}, {%8,%9}, {%0,%1,%2,%3};"
        : "+f"(c[0]), "+f"(c[1]), "+f"(c[2]), "+f"(c[3])
        : "r"(a[0]), "r"(a[1]), "r"(a[2]), "r"(a[3]),
          "r"(b[0]), "r"(b[1]));
}

__device__ __forceinline__ void ldsm_x4(uint32_t* r, uint32_t addr) {
    asm volatile("ldmatrix.sync.aligned.m8n8.x4.shared.b16 {%0,%1,%2,%3}, [%4];"
                 : "=r"(r[0]), "=r"(r[1]), "=r"(r[2]), "=r"(r[3]) : "r"(addr));
}

__device__ __forceinline__ void cp16(uint32_t dst, const void* src) {
    asm volatile("cp.async.cg.shared.global [%0], [%1], 16;"
                 :: "r"(dst), "l"(src) : "memory");
}
#define CP_COMMIT() asm volatile("cp.async.commit_group;" ::: "memory")
#define CP_WAIT0()  asm volatile("cp.async.wait_group 0;" ::: "memory")

__device__ __forceinline__ uint32_t bf2pack(__nv_bfloat16 a, __nv_bfloat16 b) {
    __nv_bfloat162 v = {a, b};
    return *reinterpret_cast<uint32_t*>(&v);
}

// Tile stride: 72 bf16 per row (144 B, conflict-staggered, 16B aligned)
#define TSTR 72

// ---------------------------------------------------------------------------
// Batched fp32 -> bf16 hi/lo split
// ---------------------------------------------------------------------------
__global__ void __launch_bounds__(256) split3_kernel(
    const float* __restrict__ i0, const float* __restrict__ i1,
    const float* __restrict__ i2)
{
    const int z = blockIdx.y;
    const float* in = (z == 0) ? i0 : (z == 1) ? i1 : i2;
    __nv_bfloat16* hi = g_a1 + (size_t)z * MD;
    __nv_bfloat16* lo = g_a2 + (size_t)z * MD;

    const int i = blockIdx.x * 256 + threadIdx.x;
    const float4 v = reinterpret_cast<const float4*>(in)[i];
    __nv_bfloat16 h0 = __float2bfloat16(v.x);
    __nv_bfloat16 h1 = __float2bfloat16(v.y);
    __nv_bfloat16 h2 = __float2bfloat16(v.z);
    __nv_bfloat16 h3 = __float2bfloat16(v.w);
    __nv_bfloat162 H0 = {h0, h1}, H1 = {h2, h3};
    __nv_bfloat162 L0 = {__float2bfloat16(v.x - __bfloat162float(h0)),
                         __float2bfloat16(v.y - __bfloat162float(h1))};
    __nv_bfloat162 L1 = {__float2bfloat16(v.z - __bfloat162float(h2)),
                         __float2bfloat16(v.w - __bfloat162float(h3))};
    reinterpret_cast<__nv_bfloat162*>(hi)[i * 2]     = H0;
    reinterpret_cast<__nv_bfloat162*>(hi)[i * 2 + 1] = H1;
    reinterpret_cast<__nv_bfloat162*>(lo)[i * 2]     = L0;
    reinterpret_cast<__nv_bfloat162*>(lo)[i * 2 + 1] = L1;
}

// ---------------------------------------------------------------------------
// Batched weight transpose + split (all 4 weights)
// ---------------------------------------------------------------------------
__global__ void __launch_bounds__(256) wt4_kernel(
    const float* __restrict__ W0, const float* __restrict__ W1,
    const float* __restrict__ W2, const float* __restrict__ W3)
{
    __shared__ float vs[64][65];
    const int z = blockIdx.z;
    const float* W = (z == 0) ? W0 : (z == 1) ? W1 : (z == 2) ? W2 : W3;
    __nv_bfloat16* wt1 = g_wt1 + (size_t)z * DD;
    __nv_bfloat16* wt2 = g_wt2 + (size_t)z * DD;
    const int k0 = blockIdx.y * 64;
    const int n0 = blockIdx.x * 64;
    const int t  = threadIdx.x;

    for (int i = t; i < 64 * 16; i += 256) {
        const int r = i >> 4, c = i & 15;
        const float4 v = *reinterpret_cast<const float4*>(
            W + (size_t)(k0 + r) * D_SZ + n0 + c * 4);
        vs[r][c * 4 + 0] = v.x; vs[r][c * 4 + 1] = v.y;
        vs[r][c * 4 + 2] = v.z; vs[r][c * 4 + 3] = v.w;
    }
    __syncthreads();

    for (int i = t; i < 64 * 64; i += 256) {
        const int n = i >> 6, k = i & 63;
        const float x = vs[k][n];
        const __nv_bfloat16 h = __float2bfloat16(x);
        const __nv_bfloat16 l = __float2bfloat16(x - __bfloat162float(h));
        const size_t o = (size_t)(n0 + n) * D_SZ + k0 + k;
        wt1[o] = h;
        wt2[o] = l;
    }
}

// ---------------------------------------------------------------------------
// GEMM core: single-buffer cp.async, 2 CTAs/SM.
// terms: 3 = ah*wh + ah*wl + al*wh;  2 = ah*wh + al*wh;  1 = ah*wh.
// mode: 0 fp32 row-major; 1 bf16 hi/lo at [bh,s,64]; 3 bf16-hi transposed
//       into g_vt1 [bh][64][S].
// ---------------------------------------------------------------------------
#define A1B 0
#define A2B (128 * TSTR * 2)
#define W1B (2 * 128 * TSTR * 2)
#define W2B (3 * 128 * TSTR * 2)
#define GEMM_SMEM (4 * 128 * TSTR * 2)        // 73728

__device__ __forceinline__ void gemm_core(
    const __nv_bfloat16* a1, const __nv_bfloat16* a2,
    const __nv_bfloat16* wt1, const __nv_bfloat16* wt2,
    const float* bias, float* outf, __nv_bfloat16* outh,
    __nv_bfloat16* outl, int mode, int terms, int m0, int n0, char* smc)
{
    const int t = threadIdx.x;
    const int lane = t & 31, wid = t >> 5;
    const int wq = wid & 3, wk = wid >> 2;
    const uint32_t sb = smem_u32(smc);

    float acc[2][8][4] = {};

    for (int ck = 0; ck < 16; ck++) {
        const int j0 = ck * 64;
#pragma unroll
        for (int ii = 0; ii < 4; ii++) {
            const int i = t + ii * 256;
            const int r = i >> 3, c = i & 7;
            const uint32_t off = (uint32_t)(r * TSTR + c * 8) * 2;
            const size_t ga = (size_t)(m0 + r) * D_SZ + j0 + c * 8;
            const size_t gw = (size_t)(n0 + r) * D_SZ + j0 + c * 8;
            cp16(sb + A1B + off, a1 + ga);
            if (terms >= 2) cp16(sb + A2B + off, a2 + ga);
            cp16(sb + W1B + off, wt1 + gw);
            if (terms == 3) cp16(sb + W2B + off, wt2 + gw);
        }
        CP_COMMIT();
        CP_WAIT0();
        __syncthreads();

#pragma unroll
        for (int ks = 0; ks < 4; ks++) {
            const int kc = ks * 16;
            uint32_t ah[2][4], al[2][4];
#pragma unroll
            for (int mi = 0; mi < 2; mi++) {
                const int row = wq * 32 + mi * 16 + (lane & 15);
                const int col = kc + ((lane >> 4) << 3);
                ldsm_x4(ah[mi], sb + A1B + (uint32_t)(row * TSTR + col) * 2);
                if (terms >= 2)
                    ldsm_x4(al[mi], sb + A2B + (uint32_t)(row * TSTR + col) * 2);
            }
#pragma unroll
            for (int np = 0; np < 4; np++) {
                uint32_t bh4[4], bl4[4];
                const int row = wk * 64 + np * 16 + (lane & 7) + ((lane >> 4) & 1) * 8;
                const int col = kc + ((lane >> 3) & 1) * 8;
                ldsm_x4(bh4, sb + W1B + (uint32_t)(row * TSTR + col) * 2);
                if (terms == 3)
                    ldsm_x4(bl4, sb + W2B + (uint32_t)(row * TSTR + col) * 2);
#pragma unroll
                for (int mi = 0; mi < 2; mi++) {
                    mma_bf16(acc[mi][np * 2],     ah[mi], bh4);
                    mma_bf16(acc[mi][np * 2 + 1], ah[mi], bh4 + 2);
                    if (terms >= 2) {
                        mma_bf16(acc[mi][np * 2],     al[mi], bh4);
                        mma_bf16(acc[mi][np * 2 + 1], al[mi], bh4 + 2);
                    }
                    if (terms == 3) {
                        mma_bf16(acc[mi][np * 2],     ah[mi], bl4);
                        mma_bf16(acc[mi][np * 2 + 1], ah[mi], bl4 + 2);
                    }
                }
            }
        }
        __syncthreads();
    }

    const int g  = lane >> 2;
    const int tg = lane & 3;
#pragma unroll
    for (int mi = 0; mi < 2; mi++) {
#pragma unroll
        for (int ni = 0; ni < 8; ni++) {
            const int col = n0 + wk * 64 + ni * 8 + tg * 2;
            const float2 bb2 = *reinterpret_cast<const float2*>(bias + col);
            const int m = m0 + wq * 32 + mi * 16 + g;
            float2 r0 = make_float2(acc[mi][ni][0] + bb2.x, acc[mi][ni][1] + bb2.y);
            float2 r1 = make_float2(acc[mi][ni][2] + bb2.x, acc[mi][ni][3] + bb2.y);
            if (mode == 0) {
                *reinterpret_cast<float2*>(outf + (size_t)m * D_SZ + col) = r0;
                *reinterpret_cast<float2*>(outf + (size_t)(m + 8) * D_SZ + col) = r1;
            } else {
                const int h  = col >> 6;
                const int dk = col & 63;
                const int b0 = m >> 11, s0 = m & 2047;
                const int b1 = (m + 8) >> 11, s1 = (m + 8) & 2047;
                if (mode == 3) {
                    // V^T bf16-hi: g_vt1[(b*16+h)*64 + d][s]
                    __nv_bfloat16* vb =
                        g_vt1 + ((size_t)(b0 * H_SZ + h) * 64 + dk) * S_SZ;
                    __nv_bfloat16* vb1 =
                        g_vt1 + ((size_t)(b1 * H_SZ + h) * 64 + dk) * S_SZ;
                    vb[s0]         = __float2bfloat16(r0.x);
                    vb[S_SZ + s0]  = __float2bfloat16(r0.y);
                    vb1[s1]        = __float2bfloat16(r1.x);
                    vb1[S_SZ + s1] = __float2bfloat16(r1.y);
                } else {
                    const size_t o0 = (((size_t)(b0 * H_SZ + h) * S_SZ + s0) * DK_SZ) + dk;
                    const size_t o1 = (((size_t)(b1 * H_SZ + h) * S_SZ + s1) * DK_SZ) + dk;
                    const __nv_bfloat16 h00 = __float2bfloat16(r0.x);
                    const __nv_bfloat16 h01 = __float2bfloat16(r0.y);
                    const __nv_bfloat16 h10 = __float2bfloat16(r1.x);
                    const __nv_bfloat16 h11 = __float2bfloat16(r1.y);
                    *reinterpret_cast<uint32_t*>(outh + o0) = bf2pack(h00, h01);
                    *reinterpret_cast<uint32_t*>(outh + o1) = bf2pack(h10, h11);
                    *reinterpret_cast<uint32_t*>(outl + o0) = bf2pack(
                        __float2bfloat16(r0.x - __bfloat162float(h00)),
                        __float2bfloat16(r0.y - __bfloat162float(h01)));
                    *reinterpret_cast<uint32_t*>(outl + o1) = bf2pack(
                        __float2bfloat16(r1.x - __bfloat162float(h10)),
                        __float2bfloat16(r1.y - __bfloat162float(h11)));
                }
            }
        }
    }
}

// Batched QKV projections: z=0 q (3-term), z=1 k (3-term),
// z=2 v (1-term, writes V^T bf16-hi directly)
__global__ void __launch_bounds__(256, 2) gemm_proj(
    const float* __restrict__ bq, const float* __restrict__ bk,
    const float* __restrict__ bv)
{
    extern __shared__ __align__(16) char smc[];
    const int z = blockIdx.z;
    const __nv_bfloat16* a1 = g_a1 + (size_t)z * MD;
    const __nv_bfloat16* a2 = g_a2 + (size_t)z * MD;
    const __nv_bfloat16* w1 = g_wt1 + (size_t)z * DD;
    const __nv_bfloat16* w2 = g_wt2 + (size_t)z * DD;
    const float* bias = (z == 0) ? bq : (z == 1) ? bk : bv;
    __nv_bfloat16* outh = (z == 0) ? g_q1 : g_k1;
    __nv_bfloat16* outl = (z == 0) ? g_q2 : g_k2;
    const int mode  = (z == 2) ? 3 : 1;
    const int terms = (z == 2) ? 1 : 3;
    gemm_core(a1, a2, w1, w2, bias, nullptr, outh, outl, mode, terms,
              blockIdx.y * 128, blockIdx.x * 128, smc);
}

// Output projection: 2-term, activations slot 0 (from ctx), Wo slot 3
__global__ void __launch_bounds__(256, 2) gemm_out(
    const float* __restrict__ bo, float* __restrict__ outf)
{
    extern __shared__ __align__(16) char smc[];
    gemm_core(g_a1, g_a2, g_wt1 + 3 * DD, g_wt2 + 3 * DD, bo, outf,
              nullptr, nullptr, 0, 2, blockIdx.y * 128, blockIdx.x * 128, smc);
}

// ---------------------------------------------------------------------------
// Score kernel: 3-term QK, masked scaled scores -> sbuf
// ---------------------------------------------------------------------------
#define SQ_H 0
#define SQ_L (128 * TSTR)
#define SK_H (2 * 128 * TSTR)
#define SK_L (3 * 128 * TSTR)
#define SCORE_SMEM (4 * 128 * TSTR * 2)       // 73728 B

__global__ void __launch_bounds__(256, 2) score_kernel(
    const int* __restrict__ mask, float* __restrict__ sbuf)
{
    extern __shared__ __align__(16) __nv_bfloat16 sm[];
    const int t = threadIdx.x;
    const int lane = t & 31, wid = t >> 5;
    const int wq = wid & 3, wk = wid >> 2;
    const int q0 = blockIdx.x * 128, k0 = blockIdx.y * 128;
    const int bh = blockIdx.z, b = bh >> 4;

    {
        const uint4* q1 = reinterpret_cast<const uint4*>(
            g_q1 + ((size_t)bh * S_SZ + q0) * DK_SZ);
        const uint4* q2 = reinterpret_cast<const uint4*>(
            g_q2 + ((size_t)bh * S_SZ + q0) * DK_SZ);
        const uint4* k1 = reinterpret_cast<const uint4*>(
            g_k1 + ((size_t)bh * S_SZ + k0) * DK_SZ);
        const uint4* k2 = reinterpret_cast<const uint4*>(
            g_k2 + ((size_t)bh * S_SZ + k0) * DK_SZ);
        for (int i = t; i < 1024; i += 256) {
            const int r = i >> 3, c = i & 7;
            const int off = r * TSTR + c * 8;
            *reinterpret_cast<uint4*>(
                reinterpret_cast<char*>(sm) + (size_t)(SQ_H + off) * 2) = q1[i];
            *reinterpret_cast<uint4*>(
                reinterpret_cast<char*>(sm) + (size_t)(SQ_L + off) * 2) = q2[i];
            *reinterpret_cast<uint4*>(
                reinterpret_cast<char*>(sm) + (size_t)(SK_H + off) * 2) = k1[i];
            *reinterpret_cast<uint4*>(
                reinterpret_cast<char*>(sm) + (size_t)(SK_L + off) * 2) = k2[i];
        }
    }
    __syncthreads();

    const uint32_t sb = smem_u32(sm);
    float acc[2][8][4] = {};

#pragma unroll
    for (int ks = 0; ks < 4; ks++) {
        const int kc = ks * 16;
        uint32_t ah[2][4], al[2][4];
#pragma unroll
        for (int mi = 0; mi < 2; mi++) {
            const int row = wq * 32 + mi * 16 + (lane & 15);
            const int col = kc + ((lane >> 4) << 3);
            ldsm_x4(ah[mi], sb + (uint32_t)(SQ_H + row * TSTR + col) * 2);
            ldsm_x4(al[mi], sb + (uint32_t)(SQ_L + row * TSTR + col) * 2);
        }
#pragma unroll
        for (int np = 0; np < 4; np++) {
            uint32_t bh4[4], bl4[4];
            const int row = wk * 64 + np * 16 + (lane & 7) + ((lane >> 4) & 1) * 8;
            const int col = kc + ((lane >> 3) & 1) * 8;
            ldsm_x4(bh4, sb + (uint32_t)(SK_H + row * TSTR + col) * 2);
            ldsm_x4(bl4, sb + (uint32_t)(SK_L + row * TSTR + col) * 2);
#pragma unroll
            for (int mi = 0; mi < 2; mi++) {
                mma_bf16(acc[mi][np * 2],     ah[mi], bh4);
                mma_bf16(acc[mi][np * 2],     ah[mi], bl4);
                mma_bf16(acc[mi][np * 2],     al[mi], bh4);
                mma_bf16(acc[mi][np * 2 + 1], ah[mi], bh4 + 2);
                mma_bf16(acc[mi][np * 2 + 1], ah[mi], bl4 + 2);
                mma_bf16(acc[mi][np * 2 + 1], al[mi], bh4 + 2);
            }
        }
    }

    const int g  = lane >> 2;
    const int tg = lane & 3;
#pragma unroll
    for (int mi = 0; mi < 2; mi++) {
#pragma unroll
        for (int ni = 0; ni < 8; ni++) {
            const int q = q0 + wq * 32 + mi * 16 + g;
            const int k = k0 + wk * 64 + ni * 8 + tg * 2;
            const int2 m0 = *reinterpret_cast<const int2*>(
                mask + ((size_t)b * S_SZ + q) * S_SZ + k);
            const int2 m1 = *reinterpret_cast<const int2*>(
                mask + ((size_t)b * S_SZ + q + 8) * S_SZ + k);
            float2 s0, s1;
            s0.x = m0.x ? -1e9f : acc[mi][ni][0] * 0.125f;
            s0.y = m0.y ? -1e9f : acc[mi][ni][1] * 0.125f;
            s1.x = m1.x ? -1e9f : acc[mi][ni][2] * 0.125f;
            s1.y = m1.y ? -1e9f : acc[mi][ni][3] * 0.125f;
            *reinterpret_cast<float2*>(
                sbuf + ((size_t)bh * S_SZ + q) * S_SZ + k) = s0;
            *reinterpret_cast<float2*>(
                sbuf + ((size_t)bh * S_SZ + q + 8) * S_SZ + k) = s1;
        }
    }
}

// ---------------------------------------------------------------------------
// Softmax (in place over rows of 2048)
// ---------------------------------------------------------------------------
__global__ void __launch_bounds__(256) softmax_kernel(float* __restrict__ buf)
{
    __shared__ float red[8];
    const size_t row = blockIdx.x;
    const int t = threadIdx.x;
    float4* p4 = reinterpret_cast<float4*>(buf + row * S_SZ);

    float4 v0 = p4[t], v1 = p4[t + 256];
    float mx = fmaxf(fmaxf(fmaxf(v0.x, v0.y), fmaxf(v0.z, v0.w)),
                     fmaxf(fmaxf(v1.x, v1.y), fmaxf(v1.z, v1.w)));
#pragma unroll
    for (int o = 16; o; o >>= 1) mx = fmaxf(mx, __shfl_xor_sync(0xffffffffu, mx, o));
    if ((t & 31) == 0) red[t >> 5] = mx;
    __syncthreads();
    mx = fmaxf(fmaxf(fmaxf(red[0], red[1]), fmaxf(red[2], red[3])),
               fmaxf(fmaxf(red[4], red[5]), fmaxf(red[6], red[7])));
    __syncthreads();

    v0.x = __expf(v0.x - mx); v0.y = __expf(v0.y - mx);
    v0.z = __expf(v0.z - mx); v0.w = __expf(v0.w - mx);
    v1.x = __expf(v1.x - mx); v1.y = __expf(v1.y - mx);
    v1.z = __expf(v1.z - mx); v1.w = __expf(v1.w - mx);
    float sum = v0.x + v0.y + v0.z + v0.w + v1.x + v1.y + v1.z + v1.w;
#pragma unroll
    for (int o = 16; o; o >>= 1) sum += __shfl_xor_sync(0xffffffffu, sum, o);
    if ((t & 31) == 0) red[t >> 5] = sum;
    __syncthreads();
    const float inv = 1.f / (red[0] + red[1] + red[2] + red[3] +
                             red[4] + red[5] + red[6] + red[7]);

    v0.x *= inv; v0.y *= inv; v0.z *= inv; v0.w *= inv;
    v1.x *= inv; v1.y *= inv; v1.z *= inv; v1.w *= inv;
    p4[t] = v0;
    p4[t + 256] = v1;
}

// ---------------------------------------------------------------------------
// Context kernel: 1-term PV (P hi x V hi); epilogue writes bf16 hi/lo into
// the out-projection activation slot. 3 CTAs/SM.
// ---------------------------------------------------------------------------
#define CP_H 0
#define CV_H (128 * TSTR)
#define CTX_SMEM ((128 * TSTR + 64 * TSTR) * 2)   // 27648 B

__global__ void __launch_bounds__(256, 3) ctx_kernel(const float* __restrict__ probs)
{
    extern __shared__ __align__(16) __nv_bfloat16 sm[];
    const int t = threadIdx.x;
    const int lane = t & 31, wid = t >> 5;
    const int q0 = blockIdx.x * 128;
    const int bh = blockIdx.y, b = bh >> 4, h = bh & 15;
    const uint32_t sb = smem_u32(sm);

    const float* prow = probs + ((size_t)bh * S_SZ + q0) * S_SZ;
    const __nv_bfloat16* vt1 = g_vt1 + (size_t)bh * 64 * S_SZ;

    float acc[8][4] = {};

    for (int ch = 0; ch < 32; ch++) {
        const int j0 = ch * 64;
        __syncthreads();
        for (int i = t; i < 2048; i += 256) {
            const int r = i >> 4, c = i & 15;
            const float4 v = *reinterpret_cast<const float4*>(
                prow + (size_t)r * S_SZ + j0 + c * 4);
            const uint2 hp = make_uint2(
                bf2pack(__float2bfloat16(v.x), __float2bfloat16(v.y)),
                bf2pack(__float2bfloat16(v.z), __float2bfloat16(v.w)));
            *reinterpret_cast<uint2*>(
                reinterpret_cast<char*>(sm) + (size_t)(CP_H + r * TSTR + c * 4) * 2) = hp;
        }
        for (int i = t; i < 512; i += 256) {
            const int r = i >> 3, c = i & 7;
            const int off = r * TSTR + c * 8;
            *reinterpret_cast<uint4*>(
                reinterpret_cast<char*>(sm) + (size_t)(CV_H + off) * 2) =
                *reinterpret_cast<const uint4*>(vt1 + (size_t)r * S_SZ + j0 + c * 8);
        }
        __syncthreads();

#pragma unroll
        for (int ks = 0; ks < 4; ks++) {
            const int kc = ks * 16;
            uint32_t ah[4];
            {
                const int row = wid * 16 + (lane & 15);
                const int col = kc + ((lane >> 4) << 3);
                ldsm_x4(ah, sb + (uint32_t)(CP_H + row * TSTR + col) * 2);
            }
#pragma unroll
            for (int np = 0; np < 4; np++) {
                uint32_t bh4[4];
                const int row = np * 16 + (lane & 7) + ((lane >> 4) & 1) * 8;
                const int col = kc + ((lane >> 3) & 1) * 8;
                ldsm_x4(bh4, sb + (uint32_t)(CV_H + row * TSTR + col) * 2);
                mma_bf16(acc[np * 2],     ah, bh4);
                mma_bf16(acc[np * 2 + 1], ah, bh4 + 2);
            }
        }
    }

    // epilogue: split ctx to bf16 hi/lo directly in GEMM-A layout
    const int g  = lane >> 2;
    const int tg = lane & 3;
#pragma unroll
    for (int ni = 0; ni < 8; ni++) {
        const int q = q0 + wid * 16 + g;
        const int d = ni * 8 + tg * 2;
        const size_t m0o = ((size_t)(b * S_SZ + q)) * D_SZ + h * DK_SZ + d;
        const size_t m1o = ((size_t)(b * S_SZ + q + 8)) * D_SZ + h * DK_SZ + d;
        const float2 r0 = make_float2(acc[ni][0], acc[ni][1]);
        const float2 r1 = make_float2(acc[ni][2], acc[ni][3]);
        const __nv_bfloat16 h00 = __float2bfloat16(r0.x);
        const __nv_bfloat16 h01 = __float2bfloat16(r0.y);
        const __nv_bfloat16 h10 = __float2bfloat16(r1.x);
        const __nv_bfloat16 h11 = __float2bfloat16(r1.y);
        *reinterpret_cast<uint32_t*>(g_a1 + m0o) = bf2pack(h00, h01);
        *reinterpret_cast<uint32_t*>(g_a1 + m1o) = bf2pack(h10, h11);
        *reinterpret_cast<uint32_t*>(g_a2 + m0o) = bf2pack(
            __float2bfloat16(r0.x - __bfloat162float(h00)),
            __float2bfloat16(r0.y - __bfloat162float(h01)));
        *reinterpret_cast<uint32_t*>(g_a2 + m1o) = bf2pack(
            __float2bfloat16(r1.x - __bfloat162float(h10)),
            __float2bfloat16(r1.y - __bfloat162float(h11)));
    }
}

// ---------------------------------------------------------------------------
// Residual + LayerNorm
// ---------------------------------------------------------------------------
__global__ void __launch_bounds__(256) ln_kernel(
    const float* __restrict__ resid, const float* __restrict__ gamma,
    const float* __restrict__ beta, float* __restrict__ out)
{
    __shared__ float rs[8], rq[8];
    const int row = blockIdx.x;
    const int t = threadIdx.x;

    const float4 a = reinterpret_cast<const float4*>(g_o + (size_t)row * D_SZ)[t];
    const float4 r = reinterpret_cast<const float4*>(resid + (size_t)row * D_SZ)[t];
    const float4 v = make_float4(a.x + r.x, a.y + r.y, a.z + r.z, a.w + r.w);

    float s  = v.x + v.y + v.z + v.w;
    float sq = v.x * v.x + v.y * v.y + v.z * v.z + v.w * v.w;
#pragma unroll
    for (int o = 16; o; o >>= 1) {
        s  += __shfl_xor_sync(0xffffffffu, s, o);
        sq += __shfl_xor_sync(0xffffffffu, sq, o);
    }
    if ((t & 31) == 0) { rs[t >> 5] = s; rq[t >> 5] = sq; }
    __syncthreads();
    float S = 0.f, SQ = 0.f;
#pragma unroll
    for (int i = 0; i < 8; i++) { S += rs[i]; SQ += rq[i]; }
    const float mu  = S * (1.f / D_SZ);
    const float var = SQ * (1.f / D_SZ) - mu * mu;
    const float rstd = rsqrtf(var + 1e-5f);

    const float4 g  = reinterpret_cast<const float4*>(gamma)[t];
    const float4 be = reinterpret_cast<const float4*>(beta)[t];
    reinterpret_cast<float4*>(out + (size_t)row * D_SZ)[t] =
        make_float4((v.x - mu) * rstd * g.x + be.x,
                    (v.y - mu) * rstd * g.y + be.y,
                    (v.z - mu) * rstd * g.z + be.z,
                    (v.w - mu) * rstd * g.w + be.w);
}

// ---------------------------------------------------------------------------
// kernel_launch
// ---------------------------------------------------------------------------
extern "C" void kernel_launch(void* const* d_in, const int* in_sizes, int n_in,
                              void* d_out, int out_size)
{
    const float* Q  = (const float*)d_in[0];
    const float* K  = (const float*)d_in[1];
    const float* V  = (const float*)d_in[2];
    const int*   mask = (const int*)d_in[3];
    const float* Wq = (const float*)d_in[4];
    const float* bq = (const float*)d_in[5];
    const float* Wk = (const float*)d_in[6];
    const float* bk = (const float*)d_in[7];
    const float* Wv = (const float*)d_in[8];
    const float* bv = (const float*)d_in[9];
    const float* Wo = (const float*)d_in[10];
    const float* bo = (const float*)d_in[11];
    const float* gamma = (const float*)d_in[12];
    const float* beta  = (const float*)d_in[13];

    float *op, *scp;
    cudaGetSymbolAddress((void**)&op,  g_o);
    cudaGetSymbolAddress((void**)&scp, g_sc);

    float* outp = (float*)d_out;
    float* sbuf = scp;
    if ((long long)out_size >= (long long)OUT_ELEMS + (long long)ATTN_ELEMS)
        sbuf = outp + OUT_ELEMS;   // probs land directly in the attn output

    cudaFuncSetAttribute(score_kernel,
        cudaFuncAttributeMaxDynamicSharedMemorySize, SCORE_SMEM);
    cudaFuncSetAttribute(ctx_kernel,
        cudaFuncAttributeMaxDynamicSharedMemorySize, CTX_SMEM);
    cudaFuncSetAttribute(gemm_proj,
        cudaFuncAttributeMaxDynamicSharedMemorySize, GEMM_SMEM);
    cudaFuncSetAttribute(gemm_out,
        cudaFuncAttributeMaxDynamicSharedMemorySize, GEMM_SMEM);

    // input splits + all four weight transposes
    split3_kernel<<<dim3(M_SZ * D_SZ / 1024, 3), 256>>>(Q, K, V);
    wt4_kernel<<<dim3(16, 16, 4), 256>>>(Wq, Wk, Wv, Wo);

    // QKV projections (batched; V is 1-term, writes V^T bf16 directly)
    gemm_proj<<<dim3(8, 32, 3), 256, GEMM_SMEM>>>(bq, bk, bv);

    // attention
    score_kernel<<<dim3(16, 16, BH_SZ), 256, SCORE_SMEM>>>(mask, sbuf);
    softmax_kernel<<<BH_SZ * S_SZ, 256>>>(sbuf);
    ctx_kernel<<<dim3(16, BH_SZ), 256, CTX_SMEM>>>(sbuf);   // writes a1/a2 slot 0

    // output projection (2-term) + LN
    gemm_out<<<dim3(8, 32), 256, GEMM_SMEM>>>(bo, op);
    ln_kernel<<<M_SZ, 256>>>(Q, gamma, beta, outp);
}